// round 3
// baseline (speedup 1.0000x reference)
#include <cuda_runtime.h>
#include <cuda_bf16.h>
#include <math.h>

// Problem constants (fixed by setup_inputs)
#define B_SZ    8
#define S_LEN   1024
#define NHEADS  16
#define HDIM    64
#define HIDDEN  1024
#define WIN     64
#define NTOK    (B_SZ * S_LEN)          // 8192
#define QKV_N   (3 * HIDDEN)            // 3072

// ---------------------------------------------------------------------------
// Scratch (device globals — no allocation allowed in kernel_launch)
// ---------------------------------------------------------------------------
__device__ float g_qkv[(size_t)NTOK * QKV_N];    // 96 MB: qkv = hidden @ Wqkv^T
__device__ float g_attn[(size_t)NTOK * HIDDEN];  // 32 MB: attention output

// ---------------------------------------------------------------------------
// SGEMM: C[M,N] = A[M,K] * B[N,K]^T   (both row-major, K contiguous)
// 128x128 block tile, BK=16, 8x8 thread tile, 256 threads.
// All of M,N divisible by 128 and K by 16 for this problem — no bounds checks.
// ---------------------------------------------------------------------------
#define BM 128
#define BN 128
#define BK 16
#define TM 8
#define TN 8

__global__ __launch_bounds__(256, 2) void sgemm_nt_kernel(
    const float* __restrict__ A, const float* __restrict__ Bm,
    float* __restrict__ C, int M, int N, int K)
{
    __shared__ float As[BK][BM];
    __shared__ float Bs[BK][BN];

    const int tid = threadIdx.x;
    const int bm = blockIdx.y * BM;
    const int bn = blockIdx.x * BN;
    const int tx = tid & 15;           // 16 thread-cols
    const int ty = tid >> 4;           // 16 thread-rows

    // gmem load mapping: 128 rows x 16 k-floats per tile, 8 floats/thread
    const int lrow = tid >> 1;         // 0..127
    const int lcol = (tid & 1) * 8;    // 0 or 8

    const float* Aptr = A + (size_t)(bm + lrow) * K + lcol;
    const float* Bptr = Bm + (size_t)(bn + lrow) * K + lcol;

    float acc[TM][TN] = {};

    float4 a0 = *(const float4*)(Aptr);
    float4 a1 = *(const float4*)(Aptr + 4);
    float4 b0 = *(const float4*)(Bptr);
    float4 b1 = *(const float4*)(Bptr + 4);

    for (int kt = 0; kt < K; kt += BK) {
        // stage current tile (transposed: As[k][m])
        As[lcol + 0][lrow] = a0.x; As[lcol + 1][lrow] = a0.y;
        As[lcol + 2][lrow] = a0.z; As[lcol + 3][lrow] = a0.w;
        As[lcol + 4][lrow] = a1.x; As[lcol + 5][lrow] = a1.y;
        As[lcol + 6][lrow] = a1.z; As[lcol + 7][lrow] = a1.w;
        Bs[lcol + 0][lrow] = b0.x; Bs[lcol + 1][lrow] = b0.y;
        Bs[lcol + 2][lrow] = b0.z; Bs[lcol + 3][lrow] = b0.w;
        Bs[lcol + 4][lrow] = b1.x; Bs[lcol + 5][lrow] = b1.y;
        Bs[lcol + 6][lrow] = b1.z; Bs[lcol + 7][lrow] = b1.w;
        __syncthreads();

        // prefetch next tile into registers
        if (kt + BK < K) {
            a0 = *(const float4*)(Aptr + kt + BK);
            a1 = *(const float4*)(Aptr + kt + BK + 4);
            b0 = *(const float4*)(Bptr + kt + BK);
            b1 = *(const float4*)(Bptr + kt + BK + 4);
        }

        #pragma unroll
        for (int kk = 0; kk < BK; kk++) {
            float ar[TM], br[TN];
            *(float4*)(ar)     = *(const float4*)&As[kk][ty * TM];
            *(float4*)(ar + 4) = *(const float4*)&As[kk][ty * TM + 4];
            *(float4*)(br)     = *(const float4*)&Bs[kk][tx * TN];
            *(float4*)(br + 4) = *(const float4*)&Bs[kk][tx * TN + 4];
            #pragma unroll
            for (int i = 0; i < TM; i++)
                #pragma unroll
                for (int j = 0; j < TN; j++)
                    acc[i][j] = fmaf(ar[i], br[j], acc[i][j]);
        }
        __syncthreads();
    }

    #pragma unroll
    for (int i = 0; i < TM; i++) {
        float* Crow = C + (size_t)(bm + ty * TM + i) * N + bn + tx * TN;
        *(float4*)(Crow)     = make_float4(acc[i][0], acc[i][1], acc[i][2], acc[i][3]);
        *(float4*)(Crow + 4) = make_float4(acc[i][4], acc[i][5], acc[i][6], acc[i][7]);
    }
}

// ---------------------------------------------------------------------------
// RoPE applied in-place to q and k slices of g_qkv.
// One thread per (token, head, pair d in [0,32)).
// ---------------------------------------------------------------------------
__global__ void rope_kernel(float* __restrict__ qkv)
{
    int idx = blockIdx.x * blockDim.x + threadIdx.x;
    const int total = NTOK * NHEADS * (HDIM / 2);
    if (idx >= total) return;
    int d = idx & 31;
    int h = (idx >> 5) & 15;
    int r = idx >> 9;              // token row 0..8191
    int t = r & (S_LEN - 1);       // position within sequence

    float inv = powf(10000.0f, -(float)d * (1.0f / 32.0f));
    float phase = (float)t * inv;
    float c, s;
    sincosf(phase, &s, &c);        // note: sincosf(x, &sin, &cos)

    float* qp = qkv + (size_t)r * QKV_N + h * HDIM + d;
    float q1 = qp[0], q2 = qp[32];
    qp[0]  = q1 * c - q2 * s;
    qp[32] = q2 * c + q1 * s;

    float* kp = qp + HIDDEN;
    float k1 = kp[0], k2 = kp[32];
    kp[0]  = k1 * c - k2 * s;
    kp[32] = k2 * c + k1 * s;
}

// ---------------------------------------------------------------------------
// Sliding-window attention.
// Block = (b, h, 64-query tile). Keys needed: [q0-64, q0+128) → 192 rows.
// K tile smem stride 68 (float4 reads across lanes are phase-conflict-free:
// 68 ≡ 4 mod 32). V row-major stride 64 (whole-row reads, conflict-free).
// Warp-per-query: lane owns keys lane+32*ks; softmax via warp shfl reduce;
// P·V via shfl-broadcast of p, lane owns output dims {2*lane, 2*lane+1}.
// ---------------------------------------------------------------------------
#define QT 64
#define KT 192
#define KS_STRIDE 68
#define SMEM_ATTN ((KT * KS_STRIDE + KT * HDIM + QT * HDIM) * 4)

__global__ __launch_bounds__(256) void attn_kernel(
    const float* __restrict__ qkv, float* __restrict__ attn_out)
{
    extern __shared__ float sm[];
    float* Ks = sm;                         // [KT][KS_STRIDE]
    float* Vs = sm + KT * KS_STRIDE;        // [KT][HDIM]
    float* Qs = Vs + KT * HDIM;             // [QT][HDIM]

    const int bx = blockIdx.x;
    const int qt = bx & 15;
    const int h  = (bx >> 4) & 15;
    const int b  = bx >> 8;
    const int q0 = qt * QT;
    const int kbase = q0 - WIN;

    const int tid = threadIdx.x;
    const int lane = tid & 31;
    const int w = tid >> 5;

    const size_t tok_base = (size_t)b * S_LEN;
    const int koff = h * HDIM;

    // stage K and V tiles (zero-fill out-of-range rows)
    for (int idx = tid; idx < KT * (HDIM / 4); idx += 256) {
        int row = idx >> 4;
        int c4  = (idx & 15) << 2;
        int kg  = kbase + row;
        float4 kv = make_float4(0.f, 0.f, 0.f, 0.f);
        float4 vv = kv;
        if (kg >= 0 && kg < S_LEN) {
            const float* base = qkv + (tok_base + kg) * QKV_N;
            kv = *(const float4*)(base + HIDDEN + koff + c4);
            vv = *(const float4*)(base + 2 * HIDDEN + koff + c4);
        }
        *(float4*)&Ks[row * KS_STRIDE + c4] = kv;
        *(float4*)&Vs[row * HDIM + c4]      = vv;
    }
    // stage Q tile
    for (int idx = tid; idx < QT * (HDIM / 4); idx += 256) {
        int row = idx >> 4;
        int c4  = (idx & 15) << 2;
        *(float4*)&Qs[row * HDIM + c4] =
            *(const float4*)(qkv + (tok_base + q0 + row) * QKV_N + koff + c4);
    }
    __syncthreads();

    for (int qi = 0; qi < 8; qi++) {
        const int ql = w * 8 + qi;
        const int qg = q0 + ql;

        // scores (6 keys per lane)
        float sc[6];
        #pragma unroll
        for (int ks = 0; ks < 6; ks++) {
            const int kl = ks * 32 + lane;
            const int kg = kbase + kl;
            float dot = 0.f;
            #pragma unroll
            for (int d = 0; d < HDIM; d += 4) {
                float4 qv = *(const float4*)&Qs[ql * HDIM + d];
                float4 kv = *(const float4*)&Ks[kl * KS_STRIDE + d];
                dot = fmaf(qv.x, kv.x, fmaf(qv.y, kv.y,
                      fmaf(qv.z, kv.z, fmaf(qv.w, kv.w, dot))));
            }
            bool valid = (kg >= 0) && (kg < S_LEN) &&
                         (kg >= qg - WIN) && (kg <= qg + WIN);
            sc[ks] = valid ? dot * 0.125f : -1e30f;
        }

        // softmax across 192 (warp-distributed)
        float m = sc[0];
        #pragma unroll
        for (int ks = 1; ks < 6; ks++) m = fmaxf(m, sc[ks]);
        #pragma unroll
        for (int off = 16; off > 0; off >>= 1)
            m = fmaxf(m, __shfl_xor_sync(0xffffffffu, m, off));
        float p[6];
        float sum = 0.f;
        #pragma unroll
        for (int ks = 0; ks < 6; ks++) { p[ks] = __expf(sc[ks] - m); sum += p[ks]; }
        #pragma unroll
        for (int off = 16; off > 0; off >>= 1)
            sum += __shfl_xor_sync(0xffffffffu, sum, off);
        const float rs = 1.0f / sum;

        // P @ V : lane accumulates dims {2*lane, 2*lane+1}
        float o0 = 0.f, o1 = 0.f;
        #pragma unroll
        for (int ks = 0; ks < 6; ks++) {
            const float pks = p[ks] * rs;
            #pragma unroll 8
            for (int l = 0; l < 32; l++) {
                float pk = __shfl_sync(0xffffffffu, pks, l);
                float2 vv = *(const float2*)&Vs[(ks * 32 + l) * HDIM + 2 * lane];
                o0 = fmaf(pk, vv.x, o0);
                o1 = fmaf(pk, vv.y, o1);
            }
        }
        *(float2*)&attn_out[(tok_base + qg) * HIDDEN + koff + 2 * lane] =
            make_float2(o0, o1);
    }
}

// ---------------------------------------------------------------------------
// Launch
// ---------------------------------------------------------------------------
extern "C" void kernel_launch(void* const* d_in, const int* in_sizes, int n_in,
                              void* d_out, int out_size)
{
    // identify inputs by element count (robust to metadata ordering)
    const float* hidden = nullptr;
    const float* wqkv = nullptr;
    const float* wo = nullptr;
    for (int i = 0; i < n_in; i++) {
        if (in_sizes[i] == NTOK * HIDDEN)            hidden = (const float*)d_in[i];
        else if (in_sizes[i] == QKV_N * HIDDEN)      wqkv   = (const float*)d_in[i];
        else if (in_sizes[i] == HIDDEN * HIDDEN)     wo     = (const float*)d_in[i];
    }

    float* qkv;
    float* attn;
    cudaGetSymbolAddress((void**)&qkv, g_qkv);
    cudaGetSymbolAddress((void**)&attn, g_attn);

    cudaFuncSetAttribute(attn_kernel,
                         cudaFuncAttributeMaxDynamicSharedMemorySize, SMEM_ATTN);

    // 1) QKV projection: [8192,3072] = hidden @ Wqkv^T
    sgemm_nt_kernel<<<dim3(QKV_N / BN, NTOK / BM), 256>>>(
        hidden, wqkv, qkv, NTOK, QKV_N, HIDDEN);

    // 2) RoPE in-place on q,k
    {
        int total = NTOK * NHEADS * (HDIM / 2);
        rope_kernel<<<(total + 255) / 256, 256>>>(qkv);
    }

    // 3) sliding-window attention
    attn_kernel<<<B_SZ * NHEADS * (S_LEN / QT), 256, SMEM_ATTN>>>(qkv, attn);

    // 4) output projection: out = attn @ Wo^T
    sgemm_nt_kernel<<<dim3(HIDDEN / BN, NTOK / BM), 256>>>(
        attn, wo, (float*)d_out, NTOK, HIDDEN, HIDDEN);
}

// round 5
// speedup vs baseline: 1.6793x; 1.6793x over previous
#include <cuda_runtime.h>
#include <cuda_bf16.h>
#include <math.h>
#include <stdint.h>

// Problem constants (fixed by setup_inputs)
#define B_SZ    8
#define S_LEN   1024
#define NHEADS  16
#define HDIM    64
#define HIDDEN  1024
#define WIN     64
#define NTOK    (B_SZ * S_LEN)          // 8192
#define QKV_N   (3 * HIDDEN)            // 3072

// ---------------------------------------------------------------------------
// Scratch (device globals — no allocation allowed in kernel_launch)
// ---------------------------------------------------------------------------
__device__ float g_qkv[(size_t)NTOK * QKV_N];    // 96 MB
__device__ float g_attn[(size_t)NTOK * HIDDEN];  // 32 MB

// bf16 hi/lo split buffers
__device__ __nv_bfloat16 g_hh[(size_t)NTOK * HIDDEN];
__device__ __nv_bfloat16 g_hl[(size_t)NTOK * HIDDEN];
__device__ __nv_bfloat16 g_wqh[(size_t)QKV_N * HIDDEN];
__device__ __nv_bfloat16 g_wql[(size_t)QKV_N * HIDDEN];
__device__ __nv_bfloat16 g_woh[(size_t)HIDDEN * HIDDEN];
__device__ __nv_bfloat16 g_wol[(size_t)HIDDEN * HIDDEN];
__device__ __nv_bfloat16 g_ah[(size_t)NTOK * HIDDEN];
__device__ __nv_bfloat16 g_al[(size_t)NTOK * HIDDEN];

// ---------------------------------------------------------------------------
// fp32 -> bf16 hi/lo split
// ---------------------------------------------------------------------------
__global__ void split_bf16_kernel(const float* __restrict__ x,
                                  __nv_bfloat16* __restrict__ hi,
                                  __nv_bfloat16* __restrict__ lo, int n)
{
    int i = (blockIdx.x * blockDim.x + threadIdx.x) * 4;
    if (i >= n) return;
    float4 v = *(const float4*)(x + i);
    __nv_bfloat16 h0 = __float2bfloat16(v.x);
    __nv_bfloat16 h1 = __float2bfloat16(v.y);
    __nv_bfloat16 h2 = __float2bfloat16(v.z);
    __nv_bfloat16 h3 = __float2bfloat16(v.w);
    __nv_bfloat16 l0 = __float2bfloat16(v.x - __bfloat162float(h0));
    __nv_bfloat16 l1 = __float2bfloat16(v.y - __bfloat162float(h1));
    __nv_bfloat16 l2 = __float2bfloat16(v.z - __bfloat162float(h2));
    __nv_bfloat16 l3 = __float2bfloat16(v.w - __bfloat162float(h3));
    *(__nv_bfloat162*)(hi + i)     = __nv_bfloat162(h0, h1);
    *(__nv_bfloat162*)(hi + i + 2) = __nv_bfloat162(h2, h3);
    *(__nv_bfloat162*)(lo + i)     = __nv_bfloat162(l0, l1);
    *(__nv_bfloat162*)(lo + i + 2) = __nv_bfloat162(l2, l3);
}

// ---------------------------------------------------------------------------
// HMMA helpers (standard PTX, valid on base sm_103 target)
// ---------------------------------------------------------------------------
__device__ __forceinline__ uint32_t smem_u32(const void* p) {
    uint32_t a;
    asm("{ .reg .u64 t; cvta.to.shared.u64 t, %1; cvt.u32.u64 %0, t; }"
        : "=r"(a) : "l"(p));
    return a;
}

#define LDMX4(r0, r1, r2, r3, a) \
    asm volatile("ldmatrix.sync.aligned.m8n8.x4.shared.b16 {%0,%1,%2,%3}, [%4];" \
                 : "=r"(r0), "=r"(r1), "=r"(r2), "=r"(r3) : "r"(a))

#define LDMX2(r0, r1, a) \
    asm volatile("ldmatrix.sync.aligned.m8n8.x2.shared.b16 {%0,%1}, [%2];" \
                 : "=r"(r0), "=r"(r1) : "r"(a))

#define MMA16816(d, a, b) \
    asm volatile("mma.sync.aligned.m16n8k16.row.col.f32.bf16.bf16.f32 " \
                 "{%0,%1,%2,%3}, {%4,%5,%6,%7}, {%8,%9}, {%0,%1,%2,%3};" \
                 : "+f"((d)[0]), "+f"((d)[1]), "+f"((d)[2]), "+f"((d)[3]) \
                 : "r"((a)[0]), "r"((a)[1]), "r"((a)[2]), "r"((a)[3]), \
                   "r"((b)[0]), "r"((b)[1]))

// ---------------------------------------------------------------------------
// bf16 split GEMM via mma.sync: C[M,N] = (Ah+Al)[M,K] @ (Bh+Bl)[N,K]^T
// 3-term compensated: AhBh + AhBl + AlBh (fp32 accumulate).
// CTA tile 128x128, K-chunk 32, 8 warps (2x4), 64x32 per warp.
// smem tiles: 128 rows x 32 bf16, padded stride 40 elems (80B) -> no conflicts.
// ---------------------------------------------------------------------------
#define KC        32
#define TSTRIDE   40
#define TILE_B    (128 * TSTRIDE * 2)   // 10240 B
#define BUF_B     (4 * TILE_B)          // Ah, Al, Bh, Bl
#define GSMEM     (2 * BUF_B)           // 81920 B (double buffered)

__global__ __launch_bounds__(256, 1) void gemm_bf16_kernel(
    const __nv_bfloat16* __restrict__ Ah, const __nv_bfloat16* __restrict__ Al,
    const __nv_bfloat16* __restrict__ Bh, const __nv_bfloat16* __restrict__ Bl,
    float* __restrict__ C, int M, int N, int K)
{
    extern __shared__ char smem[];
    const uint32_t sbase = smem_u32(smem);

    const int tid  = threadIdx.x;
    const int wid  = tid >> 5;
    const int lane = tid & 31;
    const int bm = blockIdx.y * 128;
    const int bn = blockIdx.x * 128;
    const int m0 = (wid & 1) * 64;      // warp row offset within tile
    const int n0 = (wid >> 1) * 32;     // warp col offset within tile

    const __nv_bfloat16* srcs[4] = { Ah, Al, Bh, Bl };
    const int r0s[4] = { bm, bm, bn, bn };

    // staging map: per matrix, 512 uint4; thread handles u = tid, tid+256
    const int row0 = tid >> 2;          // 0..63  (u=tid)
    const int row1 = (tid + 256) >> 2;  // 64..127
    const int c16  = tid & 3;           // 16B column index

    // ldmatrix per-lane offsets (element units)
    const int quad = lane >> 3, lrow = lane & 7;
    const int a_off = ((quad & 1) * 8 + lrow) * TSTRIDE + (quad >> 1) * 8;
    const int b_off = (lane & 7) * TSTRIDE + ((lane >> 3) & 1) * 8;

    float acc[4][4][4] = {};
    uint4 pre[8];

    auto ldg = [&](int ch) {
        #pragma unroll
        for (int t = 0; t < 4; t++) {
            const __nv_bfloat16* s = srcs[t] + (size_t)r0s[t] * K + ch * KC + c16 * 8;
            pre[t * 2 + 0] = *(const uint4*)(s + (size_t)row0 * K);
            pre[t * 2 + 1] = *(const uint4*)(s + (size_t)row1 * K);
        }
    };
    auto sts = [&](int buf) {
        #pragma unroll
        for (int t = 0; t < 4; t++) {
            char* tb = smem + buf * BUF_B + t * TILE_B + c16 * 16;
            *(uint4*)(tb + row0 * (TSTRIDE * 2)) = pre[t * 2 + 0];
            *(uint4*)(tb + row1 * (TSTRIDE * 2)) = pre[t * 2 + 1];
        }
    };

    ldg(0); sts(0);
    __syncthreads();

    const int NCH = K / KC;
    for (int c = 0; c < NCH; c++) {
        const int buf = c & 1;
        if (c + 1 < NCH) ldg(c + 1);

        const uint32_t base = sbase + buf * BUF_B;
        #pragma unroll
        for (int kk = 0; kk < 2; kk++) {
            uint32_t ah[4][4], al[4][4], bh[4][2], bl[4][2];
            #pragma unroll
            for (int mi = 0; mi < 4; mi++) {
                uint32_t ea = ((m0 + mi * 16) * TSTRIDE + kk * 16 + a_off) * 2;
                LDMX4(ah[mi][0], ah[mi][1], ah[mi][2], ah[mi][3], base + ea);
                LDMX4(al[mi][0], al[mi][1], al[mi][2], al[mi][3], base + TILE_B + ea);
            }
            #pragma unroll
            for (int ni = 0; ni < 4; ni++) {
                uint32_t eb = ((n0 + ni * 8) * TSTRIDE + kk * 16 + b_off) * 2;
                LDMX2(bh[ni][0], bh[ni][1], base + 2 * TILE_B + eb);
                LDMX2(bl[ni][0], bl[ni][1], base + 3 * TILE_B + eb);
            }
            #pragma unroll
            for (int mi = 0; mi < 4; mi++)
                #pragma unroll
                for (int ni = 0; ni < 4; ni++) {
                    MMA16816(acc[mi][ni], ah[mi], bh[ni]);
                    MMA16816(acc[mi][ni], ah[mi], bl[ni]);
                    MMA16816(acc[mi][ni], al[mi], bh[ni]);
                }
        }
        if (c + 1 < NCH) sts((c + 1) & 1);
        __syncthreads();
    }

    // epilogue: c0,c1 -> row g, cols 2t,2t+1 ; c2,c3 -> row g+8
    const int g = lane >> 2, tg = lane & 3;
    #pragma unroll
    for (int mi = 0; mi < 4; mi++) {
        const int row = bm + m0 + mi * 16 + g;
        #pragma unroll
        for (int ni = 0; ni < 4; ni++) {
            const int col = bn + n0 + ni * 8 + tg * 2;
            *(float2*)&C[(size_t)row * N + col] =
                make_float2(acc[mi][ni][0], acc[mi][ni][1]);
            *(float2*)&C[(size_t)(row + 8) * N + col] =
                make_float2(acc[mi][ni][2], acc[mi][ni][3]);
        }
    }
}

// ---------------------------------------------------------------------------
// RoPE applied in-place to q and k slices of g_qkv.
// ---------------------------------------------------------------------------
__global__ void rope_kernel(float* __restrict__ qkv)
{
    int idx = blockIdx.x * blockDim.x + threadIdx.x;
    const int total = NTOK * NHEADS * (HDIM / 2);
    if (idx >= total) return;
    int d = idx & 31;
    int h = (idx >> 5) & 15;
    int r = idx >> 9;
    int t = r & (S_LEN - 1);

    float inv = powf(10000.0f, -(float)d * (1.0f / 32.0f));
    float phase = (float)t * inv;
    float c, s;
    sincosf(phase, &s, &c);

    float* qp = qkv + (size_t)r * QKV_N + h * HDIM + d;
    float q1 = qp[0], q2 = qp[32];
    qp[0]  = q1 * c - q2 * s;
    qp[32] = q2 * c + q1 * s;

    float* kp = qp + HIDDEN;
    float k1 = kp[0], k2 = kp[32];
    kp[0]  = k1 * c - k2 * s;
    kp[32] = k2 * c + k1 * s;
}

// ---------------------------------------------------------------------------
// Sliding-window attention (unchanged, known-good).
// ---------------------------------------------------------------------------
#define QT 64
#define KT 192
#define KS_STRIDE 68
#define SMEM_ATTN ((KT * KS_STRIDE + KT * HDIM + QT * HDIM) * 4)

__global__ __launch_bounds__(256) void attn_kernel(
    const float* __restrict__ qkv, float* __restrict__ attn_out)
{
    extern __shared__ float sm[];
    float* Ks = sm;
    float* Vs = sm + KT * KS_STRIDE;
    float* Qs = Vs + KT * HDIM;

    const int bx = blockIdx.x;
    const int qt = bx & 15;
    const int h  = (bx >> 4) & 15;
    const int b  = bx >> 8;
    const int q0 = qt * QT;
    const int kbase = q0 - WIN;

    const int tid = threadIdx.x;
    const int lane = tid & 31;
    const int w = tid >> 5;

    const size_t tok_base = (size_t)b * S_LEN;
    const int koff = h * HDIM;

    for (int idx = tid; idx < KT * (HDIM / 4); idx += 256) {
        int row = idx >> 4;
        int c4  = (idx & 15) << 2;
        int kg  = kbase + row;
        float4 kv = make_float4(0.f, 0.f, 0.f, 0.f);
        float4 vv = kv;
        if (kg >= 0 && kg < S_LEN) {
            const float* base = qkv + (tok_base + kg) * QKV_N;
            kv = *(const float4*)(base + HIDDEN + koff + c4);
            vv = *(const float4*)(base + 2 * HIDDEN + koff + c4);
        }
        *(float4*)&Ks[row * KS_STRIDE + c4] = kv;
        *(float4*)&Vs[row * HDIM + c4]      = vv;
    }
    for (int idx = tid; idx < QT * (HDIM / 4); idx += 256) {
        int row = idx >> 4;
        int c4  = (idx & 15) << 2;
        *(float4*)&Qs[row * HDIM + c4] =
            *(const float4*)(qkv + (tok_base + q0 + row) * QKV_N + koff + c4);
    }
    __syncthreads();

    for (int qi = 0; qi < 8; qi++) {
        const int ql = w * 8 + qi;
        const int qg = q0 + ql;

        float sc[6];
        #pragma unroll
        for (int ks = 0; ks < 6; ks++) {
            const int kl = ks * 32 + lane;
            const int kg = kbase + kl;
            float dot = 0.f;
            #pragma unroll
            for (int d = 0; d < HDIM; d += 4) {
                float4 qv = *(const float4*)&Qs[ql * HDIM + d];
                float4 kv = *(const float4*)&Ks[kl * KS_STRIDE + d];
                dot = fmaf(qv.x, kv.x, fmaf(qv.y, kv.y,
                      fmaf(qv.z, kv.z, fmaf(qv.w, kv.w, dot))));
            }
            bool valid = (kg >= 0) && (kg < S_LEN) &&
                         (kg >= qg - WIN) && (kg <= qg + WIN);
            sc[ks] = valid ? dot * 0.125f : -1e30f;
        }

        float m = sc[0];
        #pragma unroll
        for (int ks = 1; ks < 6; ks++) m = fmaxf(m, sc[ks]);
        #pragma unroll
        for (int off = 16; off > 0; off >>= 1)
            m = fmaxf(m, __shfl_xor_sync(0xffffffffu, m, off));
        float p[6];
        float sum = 0.f;
        #pragma unroll
        for (int ks = 0; ks < 6; ks++) { p[ks] = __expf(sc[ks] - m); sum += p[ks]; }
        #pragma unroll
        for (int off = 16; off > 0; off >>= 1)
            sum += __shfl_xor_sync(0xffffffffu, sum, off);
        const float rs = 1.0f / sum;

        float o0 = 0.f, o1 = 0.f;
        #pragma unroll
        for (int ks = 0; ks < 6; ks++) {
            const float pks = p[ks] * rs;
            #pragma unroll 8
            for (int l = 0; l < 32; l++) {
                float pk = __shfl_sync(0xffffffffu, pks, l);
                float2 vv = *(const float2*)&Vs[(ks * 32 + l) * HDIM + 2 * lane];
                o0 = fmaf(pk, vv.x, o0);
                o1 = fmaf(pk, vv.y, o1);
            }
        }
        *(float2*)&attn_out[(tok_base + qg) * HIDDEN + koff + 2 * lane] =
            make_float2(o0, o1);
    }
}

// ---------------------------------------------------------------------------
// Launch
// ---------------------------------------------------------------------------
extern "C" void kernel_launch(void* const* d_in, const int* in_sizes, int n_in,
                              void* d_out, int out_size)
{
    const float* hidden = nullptr;
    const float* wqkv = nullptr;
    const float* wo = nullptr;
    for (int i = 0; i < n_in; i++) {
        if (in_sizes[i] == NTOK * HIDDEN)            hidden = (const float*)d_in[i];
        else if (in_sizes[i] == QKV_N * HIDDEN)      wqkv   = (const float*)d_in[i];
        else if (in_sizes[i] == HIDDEN * HIDDEN)     wo     = (const float*)d_in[i];
    }

    float *qkv, *attn;
    __nv_bfloat16 *hh, *hl, *wqh, *wql, *woh, *wol, *ah, *al;
    cudaGetSymbolAddress((void**)&qkv,  g_qkv);
    cudaGetSymbolAddress((void**)&attn, g_attn);
    cudaGetSymbolAddress((void**)&hh,  g_hh);
    cudaGetSymbolAddress((void**)&hl,  g_hl);
    cudaGetSymbolAddress((void**)&wqh, g_wqh);
    cudaGetSymbolAddress((void**)&wql, g_wql);
    cudaGetSymbolAddress((void**)&woh, g_woh);
    cudaGetSymbolAddress((void**)&wol, g_wol);
    cudaGetSymbolAddress((void**)&ah,  g_ah);
    cudaGetSymbolAddress((void**)&al,  g_al);

    cudaFuncSetAttribute(attn_kernel,
                         cudaFuncAttributeMaxDynamicSharedMemorySize, SMEM_ATTN);
    cudaFuncSetAttribute(gemm_bf16_kernel,
                         cudaFuncAttributeMaxDynamicSharedMemorySize, GSMEM);

    // 0) split inputs into bf16 hi/lo
    {
        int n;
        n = NTOK * HIDDEN;
        split_bf16_kernel<<<(n / 4 + 255) / 256, 256>>>(hidden, hh, hl, n);
        n = QKV_N * HIDDEN;
        split_bf16_kernel<<<(n / 4 + 255) / 256, 256>>>(wqkv, wqh, wql, n);
        n = HIDDEN * HIDDEN;
        split_bf16_kernel<<<(n / 4 + 255) / 256, 256>>>(wo, woh, wol, n);
    }

    // 1) QKV projection (HMMA): [8192,3072] = hidden @ Wqkv^T
    gemm_bf16_kernel<<<dim3(QKV_N / 128, NTOK / 128), 256, GSMEM>>>(
        hh, hl, wqh, wql, qkv, NTOK, QKV_N, HIDDEN);

    // 2) RoPE in-place on q,k
    {
        int total = NTOK * NHEADS * (HDIM / 2);
        rope_kernel<<<(total + 255) / 256, 256>>>(qkv);
    }

    // 3) sliding-window attention (fp32)
    attn_kernel<<<B_SZ * NHEADS * (S_LEN / QT), 256, SMEM_ATTN>>>(qkv, attn);

    // 4) split attention output, then output projection (HMMA)
    {
        int n = NTOK * HIDDEN;
        split_bf16_kernel<<<(n / 4 + 255) / 256, 256>>>(attn, ah, al, n);
    }
    gemm_bf16_kernel<<<dim3(HIDDEN / 128, NTOK / 128), 256, GSMEM>>>(
        ah, al, woh, wol, (float*)d_out, NTOK, HIDDEN, HIDDEN);
}

// round 7
// speedup vs baseline: 3.4097x; 2.0304x over previous
#include <cuda_runtime.h>
#include <cuda_bf16.h>
#include <math.h>
#include <stdint.h>

// Problem constants (fixed by setup_inputs)
#define B_SZ    8
#define S_LEN   1024
#define NHEADS  16
#define HDIM    64
#define HIDDEN  1024
#define WIN     64
#define NTOK    (B_SZ * S_LEN)          // 8192
#define QKV_N   (3 * HIDDEN)            // 3072

// ---------------------------------------------------------------------------
// Scratch (device globals — no allocation allowed in kernel_launch)
// ---------------------------------------------------------------------------
__device__ float g_qkv[(size_t)NTOK * QKV_N];    // 96 MB
__device__ float g_attn[(size_t)NTOK * HIDDEN];  // 32 MB

// bf16 hi/lo split buffers
__device__ __nv_bfloat16 g_hh[(size_t)NTOK * HIDDEN];
__device__ __nv_bfloat16 g_hl[(size_t)NTOK * HIDDEN];
__device__ __nv_bfloat16 g_wqh[(size_t)QKV_N * HIDDEN];
__device__ __nv_bfloat16 g_wql[(size_t)QKV_N * HIDDEN];
__device__ __nv_bfloat16 g_woh[(size_t)HIDDEN * HIDDEN];
__device__ __nv_bfloat16 g_wol[(size_t)HIDDEN * HIDDEN];
__device__ __nv_bfloat16 g_ah[(size_t)NTOK * HIDDEN];
__device__ __nv_bfloat16 g_al[(size_t)NTOK * HIDDEN];

// ---------------------------------------------------------------------------
// fp32 -> bf16 hi/lo split
// ---------------------------------------------------------------------------
__global__ void split_bf16_kernel(const float* __restrict__ x,
                                  __nv_bfloat16* __restrict__ hi,
                                  __nv_bfloat16* __restrict__ lo, int n)
{
    int i = (blockIdx.x * blockDim.x + threadIdx.x) * 4;
    if (i >= n) return;
    float4 v = *(const float4*)(x + i);
    __nv_bfloat16 h0 = __float2bfloat16(v.x);
    __nv_bfloat16 h1 = __float2bfloat16(v.y);
    __nv_bfloat16 h2 = __float2bfloat16(v.z);
    __nv_bfloat16 h3 = __float2bfloat16(v.w);
    __nv_bfloat16 l0 = __float2bfloat16(v.x - __bfloat162float(h0));
    __nv_bfloat16 l1 = __float2bfloat16(v.y - __bfloat162float(h1));
    __nv_bfloat16 l2 = __float2bfloat16(v.z - __bfloat162float(h2));
    __nv_bfloat16 l3 = __float2bfloat16(v.w - __bfloat162float(h3));
    *(__nv_bfloat162*)(hi + i)     = __nv_bfloat162(h0, h1);
    *(__nv_bfloat162*)(hi + i + 2) = __nv_bfloat162(h2, h3);
    *(__nv_bfloat162*)(lo + i)     = __nv_bfloat162(l0, l1);
    *(__nv_bfloat162*)(lo + i + 2) = __nv_bfloat162(l2, l3);
}

// ---------------------------------------------------------------------------
// HMMA helpers (standard PTX, valid on base sm_103 target)
// ---------------------------------------------------------------------------
__device__ __forceinline__ uint32_t smem_u32(const void* p) {
    uint32_t a;
    asm("{ .reg .u64 t; cvta.to.shared.u64 t, %1; cvt.u32.u64 %0, t; }"
        : "=r"(a) : "l"(p));
    return a;
}

#define LDMX4(r0, r1, r2, r3, a) \
    asm volatile("ldmatrix.sync.aligned.m8n8.x4.shared.b16 {%0,%1,%2,%3}, [%4];" \
                 : "=r"(r0), "=r"(r1), "=r"(r2), "=r"(r3) : "r"(a))

#define LDMX2(r0, r1, a) \
    asm volatile("ldmatrix.sync.aligned.m8n8.x2.shared.b16 {%0,%1}, [%2];" \
                 : "=r"(r0), "=r"(r1) : "r"(a))

#define LDMX2T(r0, r1, a) \
    asm volatile("ldmatrix.sync.aligned.m8n8.x2.trans.shared.b16 {%0,%1}, [%2];" \
                 : "=r"(r0), "=r"(r1) : "r"(a))

#define MMA16816(d, a, b) \
    asm volatile("mma.sync.aligned.m16n8k16.row.col.f32.bf16.bf16.f32 " \
                 "{%0,%1,%2,%3}, {%4,%5,%6,%7}, {%8,%9}, {%0,%1,%2,%3};" \
                 : "+f"((d)[0]), "+f"((d)[1]), "+f"((d)[2]), "+f"((d)[3]) \
                 : "r"((a)[0]), "r"((a)[1]), "r"((a)[2]), "r"((a)[3]), \
                   "r"((b)[0]), "r"((b)[1]))

__device__ __forceinline__ uint32_t pack_hi2(float x, float y) {
    __nv_bfloat162 p(__float2bfloat16(x), __float2bfloat16(y));
    return *(uint32_t*)&p;
}
__device__ __forceinline__ uint32_t pack_lo2(float x, float y) {
    float hx = __bfloat162float(__float2bfloat16(x));
    float hy = __bfloat162float(__float2bfloat16(y));
    __nv_bfloat162 p(__float2bfloat16(x - hx), __float2bfloat16(y - hy));
    return *(uint32_t*)&p;
}

// ---------------------------------------------------------------------------
// bf16 split GEMM via mma.sync (unchanged from R5, validated)
// ---------------------------------------------------------------------------
#define KC        32
#define TSTRIDE   40
#define TILE_B    (128 * TSTRIDE * 2)   // 10240 B
#define BUF_B     (4 * TILE_B)
#define GSMEM     (2 * BUF_B)           // 81920 B

__global__ __launch_bounds__(256, 1) void gemm_bf16_kernel(
    const __nv_bfloat16* __restrict__ Ah, const __nv_bfloat16* __restrict__ Al,
    const __nv_bfloat16* __restrict__ Bh, const __nv_bfloat16* __restrict__ Bl,
    float* __restrict__ C, int M, int N, int K)
{
    extern __shared__ char smem[];
    const uint32_t sbase = smem_u32(smem);

    const int tid  = threadIdx.x;
    const int wid  = tid >> 5;
    const int lane = tid & 31;
    const int bm = blockIdx.y * 128;
    const int bn = blockIdx.x * 128;
    const int m0 = (wid & 1) * 64;
    const int n0 = (wid >> 1) * 32;

    const __nv_bfloat16* srcs[4] = { Ah, Al, Bh, Bl };
    const int r0s[4] = { bm, bm, bn, bn };

    const int row0 = tid >> 2;
    const int row1 = (tid + 256) >> 2;
    const int c16  = tid & 3;

    const int quad = lane >> 3, lrow = lane & 7;
    const int a_off = ((quad & 1) * 8 + lrow) * TSTRIDE + (quad >> 1) * 8;
    const int b_off = (lane & 7) * TSTRIDE + ((lane >> 3) & 1) * 8;

    float acc[4][4][4] = {};
    uint4 pre[8];

    auto ldg = [&](int ch) {
        #pragma unroll
        for (int t = 0; t < 4; t++) {
            const __nv_bfloat16* s = srcs[t] + (size_t)r0s[t] * K + ch * KC + c16 * 8;
            pre[t * 2 + 0] = *(const uint4*)(s + (size_t)row0 * K);
            pre[t * 2 + 1] = *(const uint4*)(s + (size_t)row1 * K);
        }
    };
    auto sts = [&](int buf) {
        #pragma unroll
        for (int t = 0; t < 4; t++) {
            char* tb = smem + buf * BUF_B + t * TILE_B + c16 * 16;
            *(uint4*)(tb + row0 * (TSTRIDE * 2)) = pre[t * 2 + 0];
            *(uint4*)(tb + row1 * (TSTRIDE * 2)) = pre[t * 2 + 1];
        }
    };

    ldg(0); sts(0);
    __syncthreads();

    const int NCH = K / KC;
    for (int c = 0; c < NCH; c++) {
        const int buf = c & 1;
        if (c + 1 < NCH) ldg(c + 1);

        const uint32_t base = sbase + buf * BUF_B;
        #pragma unroll
        for (int kk = 0; kk < 2; kk++) {
            uint32_t ah[4][4], al[4][4], bh[4][2], bl[4][2];
            #pragma unroll
            for (int mi = 0; mi < 4; mi++) {
                uint32_t ea = ((m0 + mi * 16) * TSTRIDE + kk * 16 + a_off) * 2;
                LDMX4(ah[mi][0], ah[mi][1], ah[mi][2], ah[mi][3], base + ea);
                LDMX4(al[mi][0], al[mi][1], al[mi][2], al[mi][3], base + TILE_B + ea);
            }
            #pragma unroll
            for (int ni = 0; ni < 4; ni++) {
                uint32_t eb = ((n0 + ni * 8) * TSTRIDE + kk * 16 + b_off) * 2;
                LDMX2(bh[ni][0], bh[ni][1], base + 2 * TILE_B + eb);
                LDMX2(bl[ni][0], bl[ni][1], base + 3 * TILE_B + eb);
            }
            #pragma unroll
            for (int mi = 0; mi < 4; mi++)
                #pragma unroll
                for (int ni = 0; ni < 4; ni++) {
                    MMA16816(acc[mi][ni], ah[mi], bh[ni]);
                    MMA16816(acc[mi][ni], ah[mi], bl[ni]);
                    MMA16816(acc[mi][ni], al[mi], bh[ni]);
                }
        }
        if (c + 1 < NCH) sts((c + 1) & 1);
        __syncthreads();
    }

    const int g = lane >> 2, tg = lane & 3;
    #pragma unroll
    for (int mi = 0; mi < 4; mi++) {
        const int row = bm + m0 + mi * 16 + g;
        #pragma unroll
        for (int ni = 0; ni < 4; ni++) {
            const int col = bn + n0 + ni * 8 + tg * 2;
            *(float2*)&C[(size_t)row * N + col] =
                make_float2(acc[mi][ni][0], acc[mi][ni][1]);
            *(float2*)&C[(size_t)(row + 8) * N + col] =
                make_float2(acc[mi][ni][2], acc[mi][ni][3]);
        }
    }
}

// ---------------------------------------------------------------------------
// RoPE applied in-place to q and k slices of g_qkv.
// ---------------------------------------------------------------------------
__global__ void rope_kernel(float* __restrict__ qkv)
{
    int idx = blockIdx.x * blockDim.x + threadIdx.x;
    const int total = NTOK * NHEADS * (HDIM / 2);
    if (idx >= total) return;
    int d = idx & 31;
    int h = (idx >> 5) & 15;
    int r = idx >> 9;
    int t = r & (S_LEN - 1);

    float inv = powf(10000.0f, -(float)d * (1.0f / 32.0f));
    float phase = (float)t * inv;
    float c, s;
    sincosf(phase, &s, &c);

    float* qp = qkv + (size_t)r * QKV_N + h * HDIM + d;
    float q1 = qp[0], q2 = qp[32];
    qp[0]  = q1 * c - q2 * s;
    qp[32] = q2 * c + q1 * s;

    float* kp = qp + HIDDEN;
    float k1 = kp[0], k2 = kp[32];
    kp[0]  = k1 * c - k2 * s;
    kp[32] = k2 * c + k1 * s;
}

// ---------------------------------------------------------------------------
// Sliding-window attention via HMMA (hi/lo bf16, 3-term).
// Block = (b, h, 128-query tile). 8 warps; warp w owns queries 16w..16w+15
// and key band [16w, 16w+160) relative to kbase = q0-64.
// smem: Q/K/V bf16 hi+lo, stride 72 elems (144B == 4 banks mod 32:
// conflict-free ldmatrix). K/V rows 272 (zero-padded for warp 7's band).
// ---------------------------------------------------------------------------
#define ASTR   72
#define O_QH   0
#define O_QL   (128 * ASTR)
#define O_KH   (2 * 128 * ASTR)
#define O_KL   (O_KH + 272 * ASTR)
#define O_VH   (O_KL + 272 * ASTR)
#define O_VL   (O_VH + 272 * ASTR)
#define ATT_SMEM_BYTES ((O_VL + 272 * ASTR) * 2)   // 193536

__global__ __launch_bounds__(256, 1) void attn_mma_kernel(
    const float* __restrict__ qkv, float* __restrict__ attn_out)
{
    extern __shared__ __nv_bfloat16 smb[];
    const uint32_t sb = smem_u32(smb);

    const int bx = blockIdx.x;          // qt + 8*(h + 16*b)
    const int qt = bx & 7;
    const int h  = (bx >> 3) & 15;
    const int b  = bx >> 7;
    const int q0 = qt * 128;
    const int kbase = q0 - 64;
    const size_t tok_base = (size_t)b * S_LEN;
    const int koff = h * HDIM;

    const int tid = threadIdx.x;

    // ---- stage Q (scaled by 1/8) ----
    for (int idx = tid; idx < 128 * 16; idx += 256) {
        int row = idx >> 4, c4 = (idx & 15) << 2;
        float4 v = *(const float4*)(qkv + (tok_base + q0 + row) * QKV_N + koff + c4);
        v.x *= 0.125f; v.y *= 0.125f; v.z *= 0.125f; v.w *= 0.125f;
        __nv_bfloat16 h0 = __float2bfloat16(v.x), h1 = __float2bfloat16(v.y);
        __nv_bfloat16 h2 = __float2bfloat16(v.z), h3 = __float2bfloat16(v.w);
        int e = row * ASTR + c4;
        *(__nv_bfloat162*)&smb[O_QH + e]     = __nv_bfloat162(h0, h1);
        *(__nv_bfloat162*)&smb[O_QH + e + 2] = __nv_bfloat162(h2, h3);
        *(__nv_bfloat162*)&smb[O_QL + e] = __nv_bfloat162(
            __float2bfloat16(v.x - __bfloat162float(h0)),
            __float2bfloat16(v.y - __bfloat162float(h1)));
        *(__nv_bfloat162*)&smb[O_QL + e + 2] = __nv_bfloat162(
            __float2bfloat16(v.z - __bfloat162float(h2)),
            __float2bfloat16(v.w - __bfloat162float(h3)));
    }
    // ---- stage K and V (272 rows, zero-fill OOB) ----
    for (int idx = tid; idx < 272 * 16; idx += 256) {
        int row = idx >> 4, c4 = (idx & 15) << 2;
        int kg = kbase + row;
        float4 kv = make_float4(0.f, 0.f, 0.f, 0.f), vv = kv;
        if (kg >= 0 && kg < S_LEN) {
            const float* base = qkv + (tok_base + kg) * QKV_N + koff + c4;
            kv = *(const float4*)(base + HIDDEN);
            vv = *(const float4*)(base + 2 * HIDDEN);
        }
        int e = row * ASTR + c4;
        __nv_bfloat16 kh0 = __float2bfloat16(kv.x), kh1 = __float2bfloat16(kv.y);
        __nv_bfloat16 kh2 = __float2bfloat16(kv.z), kh3 = __float2bfloat16(kv.w);
        *(__nv_bfloat162*)&smb[O_KH + e]     = __nv_bfloat162(kh0, kh1);
        *(__nv_bfloat162*)&smb[O_KH + e + 2] = __nv_bfloat162(kh2, kh3);
        *(__nv_bfloat162*)&smb[O_KL + e] = __nv_bfloat162(
            __float2bfloat16(kv.x - __bfloat162float(kh0)),
            __float2bfloat16(kv.y - __bfloat162float(kh1)));
        *(__nv_bfloat162*)&smb[O_KL + e + 2] = __nv_bfloat162(
            __float2bfloat16(kv.z - __bfloat162float(kh2)),
            __float2bfloat16(kv.w - __bfloat162float(kh3)));
        __nv_bfloat16 vh0 = __float2bfloat16(vv.x), vh1 = __float2bfloat16(vv.y);
        __nv_bfloat16 vh2 = __float2bfloat16(vv.z), vh3 = __float2bfloat16(vv.w);
        *(__nv_bfloat162*)&smb[O_VH + e]     = __nv_bfloat162(vh0, vh1);
        *(__nv_bfloat162*)&smb[O_VH + e + 2] = __nv_bfloat162(vh2, vh3);
        *(__nv_bfloat162*)&smb[O_VL + e] = __nv_bfloat162(
            __float2bfloat16(vv.x - __bfloat162float(vh0)),
            __float2bfloat16(vv.y - __bfloat162float(vh1)));
        *(__nv_bfloat162*)&smb[O_VL + e + 2] = __nv_bfloat162(
            __float2bfloat16(vv.z - __bfloat162float(vh2)),
            __float2bfloat16(vv.w - __bfloat162float(vh3)));
    }
    __syncthreads();

    // ---- per-warp compute ----
    const int w = tid >> 5, lane = tid & 31;
    const int quad = lane >> 3, lrow = lane & 7;
    const int a_off = ((quad & 1) * 8 + lrow) * ASTR + (quad >> 1) * 8;
    const int b_off = lrow * ASTR + (quad & 1) * 8;
    const int qrow0 = 16 * w;

    // S = Q K^T (3-term), 20 n-tiles of 8 keys
    float S[20][4];
    #pragma unroll
    for (int jj = 0; jj < 20; jj++)
        S[jj][0] = S[jj][1] = S[jj][2] = S[jj][3] = 0.f;

    #pragma unroll
    for (int kk = 0; kk < 4; kk++) {
        uint32_t qh[4], ql[4];
        uint32_t ea = sb + 2u * (O_QH + qrow0 * ASTR + kk * 16 + a_off);
        uint32_t el = sb + 2u * (O_QL + qrow0 * ASTR + kk * 16 + a_off);
        LDMX4(qh[0], qh[1], qh[2], qh[3], ea);
        LDMX4(ql[0], ql[1], ql[2], ql[3], el);
        #pragma unroll
        for (int jj = 0; jj < 20; jj++) {
            int kr = qrow0 + jj * 8;
            uint32_t kh[2], kl[2];
            LDMX2(kh[0], kh[1], sb + 2u * (O_KH + kr * ASTR + kk * 16 + b_off));
            LDMX2(kl[0], kl[1], sb + 2u * (O_KL + kr * ASTR + kk * 16 + b_off));
            MMA16816(S[jj], qh, kh);
            MMA16816(S[jj], qh, kl);
            MMA16816(S[jj], ql, kh);
        }
    }

    // ---- mask + softmax (rows g and g+8 within warp tile) ----
    const int g = lane >> 2, tg = lane & 3;
    const int qg = q0 + qrow0 + g;
    #pragma unroll
    for (int jj = 0; jj < 20; jj++) {
        int col = kbase + qrow0 + jj * 8 + 2 * tg;
        #pragma unroll
        for (int e = 0; e < 2; e++) {
            int c = col + e;
            bool okc = (c >= 0) && (c < S_LEN);
            int d0 = c - qg;
            if (!(okc && d0 >= -WIN && d0 <= WIN)) S[jj][e] = -1e30f;
            int d1 = d0 - 8;
            if (!(okc && d1 >= -WIN && d1 <= WIN)) S[jj][2 + e] = -1e30f;
        }
    }
    float m0 = -1e30f, m1 = -1e30f;
    #pragma unroll
    for (int jj = 0; jj < 20; jj++) {
        m0 = fmaxf(m0, fmaxf(S[jj][0], S[jj][1]));
        m1 = fmaxf(m1, fmaxf(S[jj][2], S[jj][3]));
    }
    m0 = fmaxf(m0, __shfl_xor_sync(0xffffffffu, m0, 1));
    m0 = fmaxf(m0, __shfl_xor_sync(0xffffffffu, m0, 2));
    m1 = fmaxf(m1, __shfl_xor_sync(0xffffffffu, m1, 1));
    m1 = fmaxf(m1, __shfl_xor_sync(0xffffffffu, m1, 2));
    float s0 = 0.f, s1 = 0.f;
    #pragma unroll
    for (int jj = 0; jj < 20; jj++) {
        S[jj][0] = __expf(S[jj][0] - m0); s0 += S[jj][0];
        S[jj][1] = __expf(S[jj][1] - m0); s0 += S[jj][1];
        S[jj][2] = __expf(S[jj][2] - m1); s1 += S[jj][2];
        S[jj][3] = __expf(S[jj][3] - m1); s1 += S[jj][3];
    }
    s0 += __shfl_xor_sync(0xffffffffu, s0, 1);
    s0 += __shfl_xor_sync(0xffffffffu, s0, 2);
    s1 += __shfl_xor_sync(0xffffffffu, s1, 1);
    s1 += __shfl_xor_sync(0xffffffffu, s1, 2);
    const float r0 = 1.0f / s0, r1 = 1.0f / s1;
    #pragma unroll
    for (int jj = 0; jj < 20; jj++) {
        S[jj][0] *= r0; S[jj][1] *= r0; S[jj][2] *= r1; S[jj][3] *= r1;
    }

    // ---- O = P V (3-term); P fragments built in registers ----
    float O[8][4];
    #pragma unroll
    for (int ni = 0; ni < 8; ni++)
        O[ni][0] = O[ni][1] = O[ni][2] = O[ni][3] = 0.f;

    const int vrow = lane & 15;
    #pragma unroll
    for (int kt = 0; kt < 10; kt++) {
        const float* sA = S[2 * kt];
        const float* sB = S[2 * kt + 1];
        uint32_t ph[4], pl[4];
        ph[0] = pack_hi2(sA[0], sA[1]); pl[0] = pack_lo2(sA[0], sA[1]);
        ph[1] = pack_hi2(sA[2], sA[3]); pl[1] = pack_lo2(sA[2], sA[3]);
        ph[2] = pack_hi2(sB[0], sB[1]); pl[2] = pack_lo2(sB[0], sB[1]);
        ph[3] = pack_hi2(sB[2], sB[3]); pl[3] = pack_lo2(sB[2], sB[3]);
        const int vr = qrow0 + kt * 16 + vrow;
        #pragma unroll
        for (int ni = 0; ni < 8; ni++) {
            uint32_t vh[2], vl[2];
            LDMX2T(vh[0], vh[1], sb + 2u * (O_VH + vr * ASTR + ni * 8));
            LDMX2T(vl[0], vl[1], sb + 2u * (O_VL + vr * ASTR + ni * 8));
            MMA16816(O[ni], ph, vh);
            MMA16816(O[ni], ph, vl);
            MMA16816(O[ni], pl, vh);
        }
    }

    // ---- store O ----
    #pragma unroll
    for (int ni = 0; ni < 8; ni++) {
        const int col = koff + ni * 8 + 2 * tg;
        *(float2*)&attn_out[(tok_base + qg) * HIDDEN + col] =
            make_float2(O[ni][0], O[ni][1]);
        *(float2*)&attn_out[(tok_base + qg + 8) * HIDDEN + col] =
            make_float2(O[ni][2], O[ni][3]);
    }
}

// ---------------------------------------------------------------------------
// Launch
// ---------------------------------------------------------------------------
extern "C" void kernel_launch(void* const* d_in, const int* in_sizes, int n_in,
                              void* d_out, int out_size)
{
    const float* hidden = nullptr;
    const float* wqkv = nullptr;
    const float* wo = nullptr;
    for (int i = 0; i < n_in; i++) {
        if (in_sizes[i] == NTOK * HIDDEN)            hidden = (const float*)d_in[i];
        else if (in_sizes[i] == QKV_N * HIDDEN)      wqkv   = (const float*)d_in[i];
        else if (in_sizes[i] == HIDDEN * HIDDEN)     wo     = (const float*)d_in[i];
    }

    float *qkv, *attn;
    __nv_bfloat16 *hh, *hl, *wqh, *wql, *woh, *wol, *ah, *al;
    cudaGetSymbolAddress((void**)&qkv,  g_qkv);
    cudaGetSymbolAddress((void**)&attn, g_attn);
    cudaGetSymbolAddress((void**)&hh,  g_hh);
    cudaGetSymbolAddress((void**)&hl,  g_hl);
    cudaGetSymbolAddress((void**)&wqh, g_wqh);
    cudaGetSymbolAddress((void**)&wql, g_wql);
    cudaGetSymbolAddress((void**)&woh, g_woh);
    cudaGetSymbolAddress((void**)&wol, g_wol);
    cudaGetSymbolAddress((void**)&ah,  g_ah);
    cudaGetSymbolAddress((void**)&al,  g_al);

    cudaFuncSetAttribute(gemm_bf16_kernel,
                         cudaFuncAttributeMaxDynamicSharedMemorySize, GSMEM);
    cudaFuncSetAttribute(attn_mma_kernel,
                         cudaFuncAttributeMaxDynamicSharedMemorySize, ATT_SMEM_BYTES);

    // 0) split inputs into bf16 hi/lo
    {
        int n;
        n = NTOK * HIDDEN;
        split_bf16_kernel<<<(n / 4 + 255) / 256, 256>>>(hidden, hh, hl, n);
        n = QKV_N * HIDDEN;
        split_bf16_kernel<<<(n / 4 + 255) / 256, 256>>>(wqkv, wqh, wql, n);
        n = HIDDEN * HIDDEN;
        split_bf16_kernel<<<(n / 4 + 255) / 256, 256>>>(wo, woh, wol, n);
    }

    // 1) QKV projection (HMMA): [8192,3072] = hidden @ Wqkv^T
    gemm_bf16_kernel<<<dim3(QKV_N / 128, NTOK / 128), 256, GSMEM>>>(
        hh, hl, wqh, wql, qkv, NTOK, QKV_N, HIDDEN);

    // 2) RoPE in-place on q,k
    {
        int total = NTOK * NHEADS * (HDIM / 2);
        rope_kernel<<<(total + 255) / 256, 256>>>(qkv);
    }

    // 3) sliding-window attention (HMMA hi/lo)
    attn_mma_kernel<<<B_SZ * NHEADS * (S_LEN / 128), 256, ATT_SMEM_BYTES>>>(qkv, attn);

    // 4) split attention output, then output projection (HMMA)
    {
        int n = NTOK * HIDDEN;
        split_bf16_kernel<<<(n / 4 + 255) / 256, 256>>>(attn, ah, al, n);
    }
    gemm_bf16_kernel<<<dim3(HIDDEN / 128, NTOK / 128), 256, GSMEM>>>(
        ah, al, woh, wol, (float*)d_out, NTOK, HIDDEN, HIDDEN);
}

// round 8
// speedup vs baseline: 3.4257x; 1.0047x over previous
#include <cuda_runtime.h>
#include <cuda_bf16.h>
#include <math.h>
#include <stdint.h>

// Problem constants (fixed by setup_inputs)
#define B_SZ    8
#define S_LEN   1024
#define NHEADS  16
#define HDIM    64
#define HIDDEN  1024
#define WIN     64
#define NTOK    (B_SZ * S_LEN)          // 8192
#define QKV_N   (3 * HIDDEN)            // 3072

// ---------------------------------------------------------------------------
// Scratch (device globals — no allocation allowed in kernel_launch)
// ---------------------------------------------------------------------------
__device__ float g_qkv[(size_t)NTOK * QKV_N];    // 96 MB
__device__ float g_attn[(size_t)NTOK * HIDDEN];  // 32 MB

// bf16 hi/lo split buffers
__device__ __nv_bfloat16 g_hh[(size_t)NTOK * HIDDEN];
__device__ __nv_bfloat16 g_hl[(size_t)NTOK * HIDDEN];
__device__ __nv_bfloat16 g_wqh[(size_t)QKV_N * HIDDEN];
__device__ __nv_bfloat16 g_wql[(size_t)QKV_N * HIDDEN];
__device__ __nv_bfloat16 g_woh[(size_t)HIDDEN * HIDDEN];
__device__ __nv_bfloat16 g_wol[(size_t)HIDDEN * HIDDEN];
__device__ __nv_bfloat16 g_ah[(size_t)NTOK * HIDDEN];
__device__ __nv_bfloat16 g_al[(size_t)NTOK * HIDDEN];

// ---------------------------------------------------------------------------
// fp32 -> bf16 hi/lo split
// ---------------------------------------------------------------------------
__global__ void split_bf16_kernel(const float* __restrict__ x,
                                  __nv_bfloat16* __restrict__ hi,
                                  __nv_bfloat16* __restrict__ lo, int n)
{
    int i = (blockIdx.x * blockDim.x + threadIdx.x) * 4;
    if (i >= n) return;
    float4 v = *(const float4*)(x + i);
    __nv_bfloat16 h0 = __float2bfloat16(v.x);
    __nv_bfloat16 h1 = __float2bfloat16(v.y);
    __nv_bfloat16 h2 = __float2bfloat16(v.z);
    __nv_bfloat16 h3 = __float2bfloat16(v.w);
    __nv_bfloat16 l0 = __float2bfloat16(v.x - __bfloat162float(h0));
    __nv_bfloat16 l1 = __float2bfloat16(v.y - __bfloat162float(h1));
    __nv_bfloat16 l2 = __float2bfloat16(v.z - __bfloat162float(h2));
    __nv_bfloat16 l3 = __float2bfloat16(v.w - __bfloat162float(h3));
    *(__nv_bfloat162*)(hi + i)     = __nv_bfloat162(h0, h1);
    *(__nv_bfloat162*)(hi + i + 2) = __nv_bfloat162(h2, h3);
    *(__nv_bfloat162*)(lo + i)     = __nv_bfloat162(l0, l1);
    *(__nv_bfloat162*)(lo + i + 2) = __nv_bfloat162(l2, l3);
}

// ---------------------------------------------------------------------------
// HMMA helpers (standard PTX, valid on base sm_103 target)
// ---------------------------------------------------------------------------
__device__ __forceinline__ uint32_t smem_u32(const void* p) {
    uint32_t a;
    asm("{ .reg .u64 t; cvta.to.shared.u64 t, %1; cvt.u32.u64 %0, t; }"
        : "=r"(a) : "l"(p));
    return a;
}

#define LDMX4(r0, r1, r2, r3, a) \
    asm volatile("ldmatrix.sync.aligned.m8n8.x4.shared.b16 {%0,%1,%2,%3}, [%4];" \
                 : "=r"(r0), "=r"(r1), "=r"(r2), "=r"(r3) : "r"(a))

#define LDMX2(r0, r1, a) \
    asm volatile("ldmatrix.sync.aligned.m8n8.x2.shared.b16 {%0,%1}, [%2];" \
                 : "=r"(r0), "=r"(r1) : "r"(a))

#define LDMX2T(r0, r1, a) \
    asm volatile("ldmatrix.sync.aligned.m8n8.x2.trans.shared.b16 {%0,%1}, [%2];" \
                 : "=r"(r0), "=r"(r1) : "r"(a))

#define MMA16816(d, a, b) \
    asm volatile("mma.sync.aligned.m16n8k16.row.col.f32.bf16.bf16.f32 " \
                 "{%0,%1,%2,%3}, {%4,%5,%6,%7}, {%8,%9}, {%0,%1,%2,%3};" \
                 : "+f"((d)[0]), "+f"((d)[1]), "+f"((d)[2]), "+f"((d)[3]) \
                 : "r"((a)[0]), "r"((a)[1]), "r"((a)[2]), "r"((a)[3]), \
                   "r"((b)[0]), "r"((b)[1]))

__device__ __forceinline__ uint32_t pack_hi2(float x, float y) {
    __nv_bfloat162 p(__float2bfloat16(x), __float2bfloat16(y));
    return *(uint32_t*)&p;
}
__device__ __forceinline__ uint32_t pack_lo2(float x, float y) {
    float hx = __bfloat162float(__float2bfloat16(x));
    float hy = __bfloat162float(__float2bfloat16(y));
    __nv_bfloat162 p(__float2bfloat16(x - hx), __float2bfloat16(y - hy));
    return *(uint32_t*)&p;
}

// ---------------------------------------------------------------------------
// bf16 split GEMM via mma.sync.
// CHANGE vs R7: MMA issue order is TERM-MAJOR — all 16 acc tiles get AhBh,
// then AhBl, then AlBh. Accumulator reuse distance 1 -> 16 MMAs, removing
// dependent-HMMA stalls at 1-CTA occupancy.
// ---------------------------------------------------------------------------
#define KC        32
#define TSTRIDE   40
#define TILE_B    (128 * TSTRIDE * 2)   // 10240 B
#define BUF_B     (4 * TILE_B)
#define GSMEM     (2 * BUF_B)           // 81920 B

__global__ __launch_bounds__(256, 1) void gemm_bf16_kernel(
    const __nv_bfloat16* __restrict__ Ah, const __nv_bfloat16* __restrict__ Al,
    const __nv_bfloat16* __restrict__ Bh, const __nv_bfloat16* __restrict__ Bl,
    float* __restrict__ C, int M, int N, int K)
{
    extern __shared__ char smem[];
    const uint32_t sbase = smem_u32(smem);

    const int tid  = threadIdx.x;
    const int wid  = tid >> 5;
    const int lane = tid & 31;
    const int bm = blockIdx.y * 128;
    const int bn = blockIdx.x * 128;
    const int m0 = (wid & 1) * 64;
    const int n0 = (wid >> 1) * 32;

    const __nv_bfloat16* srcs[4] = { Ah, Al, Bh, Bl };
    const int r0s[4] = { bm, bm, bn, bn };

    const int row0 = tid >> 2;
    const int row1 = (tid + 256) >> 2;
    const int c16  = tid & 3;

    const int quad = lane >> 3, lrow = lane & 7;
    const int a_off = ((quad & 1) * 8 + lrow) * TSTRIDE + (quad >> 1) * 8;
    const int b_off = (lane & 7) * TSTRIDE + ((lane >> 3) & 1) * 8;

    float acc[4][4][4] = {};
    uint4 pre[8];

    auto ldg = [&](int ch) {
        #pragma unroll
        for (int t = 0; t < 4; t++) {
            const __nv_bfloat16* s = srcs[t] + (size_t)r0s[t] * K + ch * KC + c16 * 8;
            pre[t * 2 + 0] = *(const uint4*)(s + (size_t)row0 * K);
            pre[t * 2 + 1] = *(const uint4*)(s + (size_t)row1 * K);
        }
    };
    auto sts = [&](int buf) {
        #pragma unroll
        for (int t = 0; t < 4; t++) {
            char* tb = smem + buf * BUF_B + t * TILE_B + c16 * 16;
            *(uint4*)(tb + row0 * (TSTRIDE * 2)) = pre[t * 2 + 0];
            *(uint4*)(tb + row1 * (TSTRIDE * 2)) = pre[t * 2 + 1];
        }
    };

    ldg(0); sts(0);
    __syncthreads();

    const int NCH = K / KC;
    for (int c = 0; c < NCH; c++) {
        const int buf = c & 1;
        if (c + 1 < NCH) ldg(c + 1);

        const uint32_t base = sbase + buf * BUF_B;
        #pragma unroll
        for (int kk = 0; kk < 2; kk++) {
            uint32_t ah[4][4], al[4][4], bh[4][2], bl[4][2];
            #pragma unroll
            for (int mi = 0; mi < 4; mi++) {
                uint32_t ea = ((m0 + mi * 16) * TSTRIDE + kk * 16 + a_off) * 2;
                LDMX4(ah[mi][0], ah[mi][1], ah[mi][2], ah[mi][3], base + ea);
                LDMX4(al[mi][0], al[mi][1], al[mi][2], al[mi][3], base + TILE_B + ea);
            }
            #pragma unroll
            for (int ni = 0; ni < 4; ni++) {
                uint32_t eb = ((n0 + ni * 8) * TSTRIDE + kk * 16 + b_off) * 2;
                LDMX2(bh[ni][0], bh[ni][1], base + 2 * TILE_B + eb);
                LDMX2(bl[ni][0], bl[ni][1], base + 3 * TILE_B + eb);
            }
            // term-major: acc reuse distance = 16 MMAs
            #pragma unroll
            for (int mi = 0; mi < 4; mi++)
                #pragma unroll
                for (int ni = 0; ni < 4; ni++)
                    MMA16816(acc[mi][ni], ah[mi], bh[ni]);
            #pragma unroll
            for (int mi = 0; mi < 4; mi++)
                #pragma unroll
                for (int ni = 0; ni < 4; ni++)
                    MMA16816(acc[mi][ni], ah[mi], bl[ni]);
            #pragma unroll
            for (int mi = 0; mi < 4; mi++)
                #pragma unroll
                for (int ni = 0; ni < 4; ni++)
                    MMA16816(acc[mi][ni], al[mi], bh[ni]);
        }
        if (c + 1 < NCH) sts((c + 1) & 1);
        __syncthreads();
    }

    const int g = lane >> 2, tg = lane & 3;
    #pragma unroll
    for (int mi = 0; mi < 4; mi++) {
        const int row = bm + m0 + mi * 16 + g;
        #pragma unroll
        for (int ni = 0; ni < 4; ni++) {
            const int col = bn + n0 + ni * 8 + tg * 2;
            *(float2*)&C[(size_t)row * N + col] =
                make_float2(acc[mi][ni][0], acc[mi][ni][1]);
            *(float2*)&C[(size_t)(row + 8) * N + col] =
                make_float2(acc[mi][ni][2], acc[mi][ni][3]);
        }
    }
}

// ---------------------------------------------------------------------------
// RoPE applied in-place to q and k slices of g_qkv.
// ---------------------------------------------------------------------------
__global__ void rope_kernel(float* __restrict__ qkv)
{
    int idx = blockIdx.x * blockDim.x + threadIdx.x;
    const int total = NTOK * NHEADS * (HDIM / 2);
    if (idx >= total) return;
    int d = idx & 31;
    int h = (idx >> 5) & 15;
    int r = idx >> 9;
    int t = r & (S_LEN - 1);

    float inv = powf(10000.0f, -(float)d * (1.0f / 32.0f));
    float phase = (float)t * inv;
    float c, s;
    sincosf(phase, &s, &c);

    float* qp = qkv + (size_t)r * QKV_N + h * HDIM + d;
    float q1 = qp[0], q2 = qp[32];
    qp[0]  = q1 * c - q2 * s;
    qp[32] = q2 * c + q1 * s;

    float* kp = qp + HIDDEN;
    float k1 = kp[0], k2 = kp[32];
    kp[0]  = k1 * c - k2 * s;
    kp[32] = k2 * c + k1 * s;
}

// ---------------------------------------------------------------------------
// Sliding-window attention via HMMA (hi/lo bf16, 3-term).
// CHANGE vs R7: S-loop reordered in chunks of 5 j-tiles (term-major within
// chunk); P.V reordered in chunks of 4 n-tiles.
// ---------------------------------------------------------------------------
#define ASTR   72
#define O_QH   0
#define O_QL   (128 * ASTR)
#define O_KH   (2 * 128 * ASTR)
#define O_KL   (O_KH + 272 * ASTR)
#define O_VH   (O_KL + 272 * ASTR)
#define O_VL   (O_VH + 272 * ASTR)
#define ATT_SMEM_BYTES ((O_VL + 272 * ASTR) * 2)   // 193536

__global__ __launch_bounds__(256, 1) void attn_mma_kernel(
    const float* __restrict__ qkv, float* __restrict__ attn_out)
{
    extern __shared__ __nv_bfloat16 smb[];
    const uint32_t sb = smem_u32(smb);

    const int bx = blockIdx.x;          // qt + 8*(h + 16*b)
    const int qt = bx & 7;
    const int h  = (bx >> 3) & 15;
    const int b  = bx >> 7;
    const int q0 = qt * 128;
    const int kbase = q0 - 64;
    const size_t tok_base = (size_t)b * S_LEN;
    const int koff = h * HDIM;

    const int tid = threadIdx.x;

    // ---- stage Q (scaled by 1/8) ----
    for (int idx = tid; idx < 128 * 16; idx += 256) {
        int row = idx >> 4, c4 = (idx & 15) << 2;
        float4 v = *(const float4*)(qkv + (tok_base + q0 + row) * QKV_N + koff + c4);
        v.x *= 0.125f; v.y *= 0.125f; v.z *= 0.125f; v.w *= 0.125f;
        __nv_bfloat16 h0 = __float2bfloat16(v.x), h1 = __float2bfloat16(v.y);
        __nv_bfloat16 h2 = __float2bfloat16(v.z), h3 = __float2bfloat16(v.w);
        int e = row * ASTR + c4;
        *(__nv_bfloat162*)&smb[O_QH + e]     = __nv_bfloat162(h0, h1);
        *(__nv_bfloat162*)&smb[O_QH + e + 2] = __nv_bfloat162(h2, h3);
        *(__nv_bfloat162*)&smb[O_QL + e] = __nv_bfloat162(
            __float2bfloat16(v.x - __bfloat162float(h0)),
            __float2bfloat16(v.y - __bfloat162float(h1)));
        *(__nv_bfloat162*)&smb[O_QL + e + 2] = __nv_bfloat162(
            __float2bfloat16(v.z - __bfloat162float(h2)),
            __float2bfloat16(v.w - __bfloat162float(h3)));
    }
    // ---- stage K and V (272 rows, zero-fill OOB) ----
    for (int idx = tid; idx < 272 * 16; idx += 256) {
        int row = idx >> 4, c4 = (idx & 15) << 2;
        int kg = kbase + row;
        float4 kv = make_float4(0.f, 0.f, 0.f, 0.f), vv = kv;
        if (kg >= 0 && kg < S_LEN) {
            const float* base = qkv + (tok_base + kg) * QKV_N + koff + c4;
            kv = *(const float4*)(base + HIDDEN);
            vv = *(const float4*)(base + 2 * HIDDEN);
        }
        int e = row * ASTR + c4;
        __nv_bfloat16 kh0 = __float2bfloat16(kv.x), kh1 = __float2bfloat16(kv.y);
        __nv_bfloat16 kh2 = __float2bfloat16(kv.z), kh3 = __float2bfloat16(kv.w);
        *(__nv_bfloat162*)&smb[O_KH + e]     = __nv_bfloat162(kh0, kh1);
        *(__nv_bfloat162*)&smb[O_KH + e + 2] = __nv_bfloat162(kh2, kh3);
        *(__nv_bfloat162*)&smb[O_KL + e] = __nv_bfloat162(
            __float2bfloat16(kv.x - __bfloat162float(kh0)),
            __float2bfloat16(kv.y - __bfloat162float(kh1)));
        *(__nv_bfloat162*)&smb[O_KL + e + 2] = __nv_bfloat162(
            __float2bfloat16(kv.z - __bfloat162float(kh2)),
            __float2bfloat16(kv.w - __bfloat162float(kh3)));
        __nv_bfloat16 vh0 = __float2bfloat16(vv.x), vh1 = __float2bfloat16(vv.y);
        __nv_bfloat16 vh2 = __float2bfloat16(vv.z), vh3 = __float2bfloat16(vv.w);
        *(__nv_bfloat162*)&smb[O_VH + e]     = __nv_bfloat162(vh0, vh1);
        *(__nv_bfloat162*)&smb[O_VH + e + 2] = __nv_bfloat162(vh2, vh3);
        *(__nv_bfloat162*)&smb[O_VL + e] = __nv_bfloat162(
            __float2bfloat16(vv.x - __bfloat162float(vh0)),
            __float2bfloat16(vv.y - __bfloat162float(vh1)));
        *(__nv_bfloat162*)&smb[O_VL + e + 2] = __nv_bfloat162(
            __float2bfloat16(vv.z - __bfloat162float(vh2)),
            __float2bfloat16(vv.w - __bfloat162float(vh3)));
    }
    __syncthreads();

    // ---- per-warp compute ----
    const int w = tid >> 5, lane = tid & 31;
    const int quad = lane >> 3, lrow = lane & 7;
    const int a_off = ((quad & 1) * 8 + lrow) * ASTR + (quad >> 1) * 8;
    const int b_off = lrow * ASTR + (quad & 1) * 8;
    const int qrow0 = 16 * w;

    // S = Q K^T (3-term), 20 n-tiles of 8 keys
    float S[20][4];
    #pragma unroll
    for (int jj = 0; jj < 20; jj++)
        S[jj][0] = S[jj][1] = S[jj][2] = S[jj][3] = 0.f;

    #pragma unroll
    for (int kk = 0; kk < 4; kk++) {
        uint32_t qh[4], ql[4];
        uint32_t ea = sb + 2u * (O_QH + qrow0 * ASTR + kk * 16 + a_off);
        uint32_t el = sb + 2u * (O_QL + qrow0 * ASTR + kk * 16 + a_off);
        LDMX4(qh[0], qh[1], qh[2], qh[3], ea);
        LDMX4(ql[0], ql[1], ql[2], ql[3], el);
        #pragma unroll
        for (int jc = 0; jc < 4; jc++) {        // 4 chunks of 5 j-tiles
            uint32_t kh[5][2], kl[5][2];
            #pragma unroll
            for (int j5 = 0; j5 < 5; j5++) {
                int kr = qrow0 + (jc * 5 + j5) * 8;
                LDMX2(kh[j5][0], kh[j5][1], sb + 2u * (O_KH + kr * ASTR + kk * 16 + b_off));
                LDMX2(kl[j5][0], kl[j5][1], sb + 2u * (O_KL + kr * ASTR + kk * 16 + b_off));
            }
            #pragma unroll
            for (int j5 = 0; j5 < 5; j5++)
                MMA16816(S[jc * 5 + j5], qh, kh[j5]);
            #pragma unroll
            for (int j5 = 0; j5 < 5; j5++)
                MMA16816(S[jc * 5 + j5], qh, kl[j5]);
            #pragma unroll
            for (int j5 = 0; j5 < 5; j5++)
                MMA16816(S[jc * 5 + j5], ql, kh[j5]);
        }
    }

    // ---- mask + softmax (rows g and g+8 within warp tile) ----
    const int g = lane >> 2, tg = lane & 3;
    const int qg = q0 + qrow0 + g;
    #pragma unroll
    for (int jj = 0; jj < 20; jj++) {
        int col = kbase + qrow0 + jj * 8 + 2 * tg;
        #pragma unroll
        for (int e = 0; e < 2; e++) {
            int c = col + e;
            bool okc = (c >= 0) && (c < S_LEN);
            int d0 = c - qg;
            if (!(okc && d0 >= -WIN && d0 <= WIN)) S[jj][e] = -1e30f;
            int d1 = d0 - 8;
            if (!(okc && d1 >= -WIN && d1 <= WIN)) S[jj][2 + e] = -1e30f;
        }
    }
    float m0 = -1e30f, m1 = -1e30f;
    #pragma unroll
    for (int jj = 0; jj < 20; jj++) {
        m0 = fmaxf(m0, fmaxf(S[jj][0], S[jj][1]));
        m1 = fmaxf(m1, fmaxf(S[jj][2], S[jj][3]));
    }
    m0 = fmaxf(m0, __shfl_xor_sync(0xffffffffu, m0, 1));
    m0 = fmaxf(m0, __shfl_xor_sync(0xffffffffu, m0, 2));
    m1 = fmaxf(m1, __shfl_xor_sync(0xffffffffu, m1, 1));
    m1 = fmaxf(m1, __shfl_xor_sync(0xffffffffu, m1, 2));
    float s0 = 0.f, s1 = 0.f;
    #pragma unroll
    for (int jj = 0; jj < 20; jj++) {
        S[jj][0] = __expf(S[jj][0] - m0); s0 += S[jj][0];
        S[jj][1] = __expf(S[jj][1] - m0); s0 += S[jj][1];
        S[jj][2] = __expf(S[jj][2] - m1); s1 += S[jj][2];
        S[jj][3] = __expf(S[jj][3] - m1); s1 += S[jj][3];
    }
    s0 += __shfl_xor_sync(0xffffffffu, s0, 1);
    s0 += __shfl_xor_sync(0xffffffffu, s0, 2);
    s1 += __shfl_xor_sync(0xffffffffu, s1, 1);
    s1 += __shfl_xor_sync(0xffffffffu, s1, 2);
    const float r0 = 1.0f / s0, r1 = 1.0f / s1;
    #pragma unroll
    for (int jj = 0; jj < 20; jj++) {
        S[jj][0] *= r0; S[jj][1] *= r0; S[jj][2] *= r1; S[jj][3] *= r1;
    }

    // ---- O = P V (3-term); P fragments built in registers ----
    float O[8][4];
    #pragma unroll
    for (int ni = 0; ni < 8; ni++)
        O[ni][0] = O[ni][1] = O[ni][2] = O[ni][3] = 0.f;

    const int vrow = lane & 15;
    #pragma unroll
    for (int kt = 0; kt < 10; kt++) {
        const float* sA = S[2 * kt];
        const float* sB = S[2 * kt + 1];
        uint32_t ph[4], pl[4];
        ph[0] = pack_hi2(sA[0], sA[1]); pl[0] = pack_lo2(sA[0], sA[1]);
        ph[1] = pack_hi2(sA[2], sA[3]); pl[1] = pack_lo2(sA[2], sA[3]);
        ph[2] = pack_hi2(sB[0], sB[1]); pl[2] = pack_lo2(sB[0], sB[1]);
        ph[3] = pack_hi2(sB[2], sB[3]); pl[3] = pack_lo2(sB[2], sB[3]);
        const int vr = qrow0 + kt * 16 + vrow;
        #pragma unroll
        for (int nc = 0; nc < 2; nc++) {        // 2 chunks of 4 n-tiles
            uint32_t vh[4][2], vl[4][2];
            #pragma unroll
            for (int n4 = 0; n4 < 4; n4++) {
                int ni = nc * 4 + n4;
                LDMX2T(vh[n4][0], vh[n4][1], sb + 2u * (O_VH + vr * ASTR + ni * 8));
                LDMX2T(vl[n4][0], vl[n4][1], sb + 2u * (O_VL + vr * ASTR + ni * 8));
            }
            #pragma unroll
            for (int n4 = 0; n4 < 4; n4++)
                MMA16816(O[nc * 4 + n4], ph, vh[n4]);
            #pragma unroll
            for (int n4 = 0; n4 < 4; n4++)
                MMA16816(O[nc * 4 + n4], ph, vl[n4]);
            #pragma unroll
            for (int n4 = 0; n4 < 4; n4++)
                MMA16816(O[nc * 4 + n4], pl, vh[n4]);
        }
    }

    // ---- store O ----
    #pragma unroll
    for (int ni = 0; ni < 8; ni++) {
        const int col = koff + ni * 8 + 2 * tg;
        *(float2*)&attn_out[(tok_base + qg) * HIDDEN + col] =
            make_float2(O[ni][0], O[ni][1]);
        *(float2*)&attn_out[(tok_base + qg + 8) * HIDDEN + col] =
            make_float2(O[ni][2], O[ni][3]);
    }
}

// ---------------------------------------------------------------------------
// Launch
// ---------------------------------------------------------------------------
extern "C" void kernel_launch(void* const* d_in, const int* in_sizes, int n_in,
                              void* d_out, int out_size)
{
    const float* hidden = nullptr;
    const float* wqkv = nullptr;
    const float* wo = nullptr;
    for (int i = 0; i < n_in; i++) {
        if (in_sizes[i] == NTOK * HIDDEN)            hidden = (const float*)d_in[i];
        else if (in_sizes[i] == QKV_N * HIDDEN)      wqkv   = (const float*)d_in[i];
        else if (in_sizes[i] == HIDDEN * HIDDEN)     wo     = (const float*)d_in[i];
    }

    float *qkv, *attn;
    __nv_bfloat16 *hh, *hl, *wqh, *wql, *woh, *wol, *ah, *al;
    cudaGetSymbolAddress((void**)&qkv,  g_qkv);
    cudaGetSymbolAddress((void**)&attn, g_attn);
    cudaGetSymbolAddress((void**)&hh,  g_hh);
    cudaGetSymbolAddress((void**)&hl,  g_hl);
    cudaGetSymbolAddress((void**)&wqh, g_wqh);
    cudaGetSymbolAddress((void**)&wql, g_wql);
    cudaGetSymbolAddress((void**)&woh, g_woh);
    cudaGetSymbolAddress((void**)&wol, g_wol);
    cudaGetSymbolAddress((void**)&ah,  g_ah);
    cudaGetSymbolAddress((void**)&al,  g_al);

    cudaFuncSetAttribute(gemm_bf16_kernel,
                         cudaFuncAttributeMaxDynamicSharedMemorySize, GSMEM);
    cudaFuncSetAttribute(attn_mma_kernel,
                         cudaFuncAttributeMaxDynamicSharedMemorySize, ATT_SMEM_BYTES);

    // 0) split inputs into bf16 hi/lo
    {
        int n;
        n = NTOK * HIDDEN;
        split_bf16_kernel<<<(n / 4 + 255) / 256, 256>>>(hidden, hh, hl, n);
        n = QKV_N * HIDDEN;
        split_bf16_kernel<<<(n / 4 + 255) / 256, 256>>>(wqkv, wqh, wql, n);
        n = HIDDEN * HIDDEN;
        split_bf16_kernel<<<(n / 4 + 255) / 256, 256>>>(wo, woh, wol, n);
    }

    // 1) QKV projection (HMMA): [8192,3072] = hidden @ Wqkv^T
    gemm_bf16_kernel<<<dim3(QKV_N / 128, NTOK / 128), 256, GSMEM>>>(
        hh, hl, wqh, wql, qkv, NTOK, QKV_N, HIDDEN);

    // 2) RoPE in-place on q,k
    {
        int total = NTOK * NHEADS * (HDIM / 2);
        rope_kernel<<<(total + 255) / 256, 256>>>(qkv);
    }

    // 3) sliding-window attention (HMMA hi/lo)
    attn_mma_kernel<<<B_SZ * NHEADS * (S_LEN / 128), 256, ATT_SMEM_BYTES>>>(qkv, attn);

    // 4) split attention output, then output projection (HMMA)
    {
        int n = NTOK * HIDDEN;
        split_bf16_kernel<<<(n / 4 + 255) / 256, 256>>>(attn, ah, al, n);
    }
    gemm_bf16_kernel<<<dim3(HIDDEN / 128, NTOK / 128), 256, GSMEM>>>(
        ah, al, woh, wol, (float*)d_out, NTOK, HIDDEN, HIDDEN);
}

// round 9
// speedup vs baseline: 3.4351x; 1.0028x over previous
#include <cuda_runtime.h>
#include <cuda_bf16.h>
#include <math.h>
#include <stdint.h>

// Problem constants (fixed by setup_inputs)
#define B_SZ    8
#define S_LEN   1024
#define NHEADS  16
#define HDIM    64
#define HIDDEN  1024
#define WIN     64
#define NTOK    (B_SZ * S_LEN)          // 8192
#define QKV_N   (3 * HIDDEN)            // 3072

// ---------------------------------------------------------------------------
// Scratch (device globals — no allocation allowed in kernel_launch)
// ---------------------------------------------------------------------------
__device__ float g_qkv[(size_t)NTOK * QKV_N];    // 96 MB
__device__ float g_attn[(size_t)NTOK * HIDDEN];  // 32 MB

// bf16 hi/lo split buffers
__device__ __nv_bfloat16 g_hh[(size_t)NTOK * HIDDEN];
__device__ __nv_bfloat16 g_hl[(size_t)NTOK * HIDDEN];
__device__ __nv_bfloat16 g_wqh[(size_t)QKV_N * HIDDEN];
__device__ __nv_bfloat16 g_wql[(size_t)QKV_N * HIDDEN];
__device__ __nv_bfloat16 g_woh[(size_t)HIDDEN * HIDDEN];
__device__ __nv_bfloat16 g_wol[(size_t)HIDDEN * HIDDEN];
__device__ __nv_bfloat16 g_ah[(size_t)NTOK * HIDDEN];
__device__ __nv_bfloat16 g_al[(size_t)NTOK * HIDDEN];

// ---------------------------------------------------------------------------
// fp32 -> bf16 hi/lo split
// ---------------------------------------------------------------------------
__global__ void split_bf16_kernel(const float* __restrict__ x,
                                  __nv_bfloat16* __restrict__ hi,
                                  __nv_bfloat16* __restrict__ lo, int n)
{
    int i = (blockIdx.x * blockDim.x + threadIdx.x) * 4;
    if (i >= n) return;
    float4 v = *(const float4*)(x + i);
    __nv_bfloat16 h0 = __float2bfloat16(v.x);
    __nv_bfloat16 h1 = __float2bfloat16(v.y);
    __nv_bfloat16 h2 = __float2bfloat16(v.z);
    __nv_bfloat16 h3 = __float2bfloat16(v.w);
    __nv_bfloat16 l0 = __float2bfloat16(v.x - __bfloat162float(h0));
    __nv_bfloat16 l1 = __float2bfloat16(v.y - __bfloat162float(h1));
    __nv_bfloat16 l2 = __float2bfloat16(v.z - __bfloat162float(h2));
    __nv_bfloat16 l3 = __float2bfloat16(v.w - __bfloat162float(h3));
    *(__nv_bfloat162*)(hi + i)     = __nv_bfloat162(h0, h1);
    *(__nv_bfloat162*)(hi + i + 2) = __nv_bfloat162(h2, h3);
    *(__nv_bfloat162*)(lo + i)     = __nv_bfloat162(l0, l1);
    *(__nv_bfloat162*)(lo + i + 2) = __nv_bfloat162(l2, l3);
}

// ---------------------------------------------------------------------------
// PTX helpers
// ---------------------------------------------------------------------------
__device__ __forceinline__ uint32_t smem_u32(const void* p) {
    uint32_t a;
    asm("{ .reg .u64 t; cvta.to.shared.u64 t, %1; cvt.u32.u64 %0, t; }"
        : "=r"(a) : "l"(p));
    return a;
}

#define CP_ASYNC16(dst, src) \
    asm volatile("cp.async.cg.shared.global [%0], [%1], 16;" \
                 :: "r"(dst), "l"(src) : "memory")
#define CP_COMMIT()  asm volatile("cp.async.commit_group;" ::: "memory")
#define CP_WAIT0()   asm volatile("cp.async.wait_group 0;" ::: "memory")

#define LDMX4(r0, r1, r2, r3, a) \
    asm volatile("ldmatrix.sync.aligned.m8n8.x4.shared.b16 {%0,%1,%2,%3}, [%4];" \
                 : "=r"(r0), "=r"(r1), "=r"(r2), "=r"(r3) : "r"(a))

#define LDMX2(r0, r1, a) \
    asm volatile("ldmatrix.sync.aligned.m8n8.x2.shared.b16 {%0,%1}, [%2];" \
                 : "=r"(r0), "=r"(r1) : "r"(a))

#define LDMX2T(r0, r1, a) \
    asm volatile("ldmatrix.sync.aligned.m8n8.x2.trans.shared.b16 {%0,%1}, [%2];" \
                 : "=r"(r0), "=r"(r1) : "r"(a))

#define MMA16816(d, a, b) \
    asm volatile("mma.sync.aligned.m16n8k16.row.col.f32.bf16.bf16.f32 " \
                 "{%0,%1,%2,%3}, {%4,%5,%6,%7}, {%8,%9}, {%0,%1,%2,%3};" \
                 : "+f"((d)[0]), "+f"((d)[1]), "+f"((d)[2]), "+f"((d)[3]) \
                 : "r"((a)[0]), "r"((a)[1]), "r"((a)[2]), "r"((a)[3]), \
                   "r"((b)[0]), "r"((b)[1]))

__device__ __forceinline__ uint32_t pack_hi2(float x, float y) {
    __nv_bfloat162 p(__float2bfloat16(x), __float2bfloat16(y));
    return *(uint32_t*)&p;
}
__device__ __forceinline__ uint32_t pack_lo2(float x, float y) {
    float hx = __bfloat162float(__float2bfloat16(x));
    float hy = __bfloat162float(__float2bfloat16(y));
    __nv_bfloat162 p(__float2bfloat16(x - hx), __float2bfloat16(y - hy));
    return *(uint32_t*)&p;
}

// ---------------------------------------------------------------------------
// bf16 split GEMM via mma.sync.
// CHANGE vs R8: cp.async staging (gmem->smem direct, no register round-trip)
// and __launch_bounds__(256, 2) for 2 CTAs/SM (occ 12.5% -> 25%).
// ---------------------------------------------------------------------------
#define KC        32
#define TSTRIDE   40
#define TILE_B    (128 * TSTRIDE * 2)   // 10240 B
#define BUF_B     (4 * TILE_B)
#define GSMEM     (2 * BUF_B)           // 81920 B

__global__ __launch_bounds__(256, 2) void gemm_bf16_kernel(
    const __nv_bfloat16* __restrict__ Ah, const __nv_bfloat16* __restrict__ Al,
    const __nv_bfloat16* __restrict__ Bh, const __nv_bfloat16* __restrict__ Bl,
    float* __restrict__ C, int M, int N, int K)
{
    extern __shared__ char smem[];
    const uint32_t sbase = smem_u32(smem);

    const int tid  = threadIdx.x;
    const int wid  = tid >> 5;
    const int lane = tid & 31;
    const int bm = blockIdx.y * 128;
    const int bn = blockIdx.x * 128;
    const int m0 = (wid & 1) * 64;
    const int n0 = (wid >> 1) * 32;

    const __nv_bfloat16* srcs[4] = { Ah, Al, Bh, Bl };
    const int r0s[4] = { bm, bm, bn, bn };

    const int row0 = tid >> 2;          // 0..63
    const int row1 = row0 + 64;         // 64..127
    const int c16  = tid & 3;

    const int quad = lane >> 3, lrow = lane & 7;
    const int a_off = ((quad & 1) * 8 + lrow) * TSTRIDE + (quad >> 1) * 8;
    const int b_off = (lane & 7) * TSTRIDE + ((lane >> 3) & 1) * 8;

    float acc[4][4][4] = {};

    auto stage_async = [&](int buf, int ch) {
        #pragma unroll
        for (int t = 0; t < 4; t++) {
            const __nv_bfloat16* s = srcs[t] + (size_t)r0s[t] * K + ch * KC + c16 * 8;
            uint32_t db = sbase + buf * BUF_B + t * TILE_B + c16 * 16;
            CP_ASYNC16(db + row0 * (TSTRIDE * 2), s + (size_t)row0 * K);
            CP_ASYNC16(db + row1 * (TSTRIDE * 2), s + (size_t)row1 * K);
        }
    };

    stage_async(0, 0);
    CP_COMMIT();

    const int NCH = K / KC;
    for (int c = 0; c < NCH; c++) {
        const int buf = c & 1;
        CP_WAIT0();
        __syncthreads();
        if (c + 1 < NCH) { stage_async((c + 1) & 1, c + 1); CP_COMMIT(); }

        const uint32_t base = sbase + buf * BUF_B;
        #pragma unroll
        for (int kk = 0; kk < 2; kk++) {
            uint32_t ah[4][4], al[4][4], bh[4][2], bl[4][2];
            #pragma unroll
            for (int mi = 0; mi < 4; mi++) {
                uint32_t ea = ((m0 + mi * 16) * TSTRIDE + kk * 16 + a_off) * 2;
                LDMX4(ah[mi][0], ah[mi][1], ah[mi][2], ah[mi][3], base + ea);
                LDMX4(al[mi][0], al[mi][1], al[mi][2], al[mi][3], base + TILE_B + ea);
            }
            #pragma unroll
            for (int ni = 0; ni < 4; ni++) {
                uint32_t eb = ((n0 + ni * 8) * TSTRIDE + kk * 16 + b_off) * 2;
                LDMX2(bh[ni][0], bh[ni][1], base + 2 * TILE_B + eb);
                LDMX2(bl[ni][0], bl[ni][1], base + 3 * TILE_B + eb);
            }
            #pragma unroll
            for (int mi = 0; mi < 4; mi++)
                #pragma unroll
                for (int ni = 0; ni < 4; ni++)
                    MMA16816(acc[mi][ni], ah[mi], bh[ni]);
            #pragma unroll
            for (int mi = 0; mi < 4; mi++)
                #pragma unroll
                for (int ni = 0; ni < 4; ni++)
                    MMA16816(acc[mi][ni], ah[mi], bl[ni]);
            #pragma unroll
            for (int mi = 0; mi < 4; mi++)
                #pragma unroll
                for (int ni = 0; ni < 4; ni++)
                    MMA16816(acc[mi][ni], al[mi], bh[ni]);
        }
        __syncthreads();
    }

    const int g = lane >> 2, tg = lane & 3;
    #pragma unroll
    for (int mi = 0; mi < 4; mi++) {
        const int row = bm + m0 + mi * 16 + g;
        #pragma unroll
        for (int ni = 0; ni < 4; ni++) {
            const int col = bn + n0 + ni * 8 + tg * 2;
            *(float2*)&C[(size_t)row * N + col] =
                make_float2(acc[mi][ni][0], acc[mi][ni][1]);
            *(float2*)&C[(size_t)(row + 8) * N + col] =
                make_float2(acc[mi][ni][2], acc[mi][ni][3]);
        }
    }
}

// ---------------------------------------------------------------------------
// Sliding-window attention via HMMA (hi/lo bf16, 3-term).
// CHANGE vs R8: RoPE fused into Q/K staging (rope kernel + one full q,k
// memory pass eliminated).
// ---------------------------------------------------------------------------
#define ASTR   72
#define O_QH   0
#define O_QL   (128 * ASTR)
#define O_KH   (2 * 128 * ASTR)
#define O_KL   (O_KH + 272 * ASTR)
#define O_VH   (O_KL + 272 * ASTR)
#define O_VL   (O_VH + 272 * ASTR)
#define ATT_SMEM_BYTES ((O_VL + 272 * ASTR) * 2)   // 193536

__global__ __launch_bounds__(256, 1) void attn_mma_kernel(
    const float* __restrict__ qkv, float* __restrict__ attn_out)
{
    extern __shared__ __nv_bfloat16 smb[];
    const uint32_t sb = smem_u32(smb);

    const int bx = blockIdx.x;          // qt + 8*(h + 16*b)
    const int qt = bx & 7;
    const int h  = (bx >> 3) & 15;
    const int b  = bx >> 7;
    const int q0 = qt * 128;
    const int kbase = q0 - 64;
    const size_t tok_base = (size_t)b * S_LEN;
    const int koff = h * HDIM;

    const int tid = threadIdx.x;

    // helper: split-store 4 rope'd values at smem element offsets (eh, el)
    auto store4 = [&](int oh, int ol, int e, float x0, float x1, float x2, float x3) {
        __nv_bfloat16 h0 = __float2bfloat16(x0), h1 = __float2bfloat16(x1);
        __nv_bfloat16 h2 = __float2bfloat16(x2), h3 = __float2bfloat16(x3);
        *(__nv_bfloat162*)&smb[oh + e]     = __nv_bfloat162(h0, h1);
        *(__nv_bfloat162*)&smb[oh + e + 2] = __nv_bfloat162(h2, h3);
        *(__nv_bfloat162*)&smb[ol + e] = __nv_bfloat162(
            __float2bfloat16(x0 - __bfloat162float(h0)),
            __float2bfloat16(x1 - __bfloat162float(h1)));
        *(__nv_bfloat162*)&smb[ol + e + 2] = __nv_bfloat162(
            __float2bfloat16(x2 - __bfloat162float(h2)),
            __float2bfloat16(x3 - __bfloat162float(h3)));
    };

    // ---- stage Q with fused RoPE (scaled by 1/8) ----
    // idx covers (row, pair-group): 8 groups of 4 pairs per row
    for (int idx = tid; idx < 128 * 8; idx += 256) {
        int row = idx >> 3, c4 = (idx & 7) << 2;     // c4 in 0..28
        const float* base = qkv + (tok_base + q0 + row) * QKV_N + koff;
        float4 v1 = *(const float4*)(base + c4);
        float4 v2 = *(const float4*)(base + 32 + c4);
        float t = (float)(q0 + row);
        float r1[4], r2[4];
        float a1[4] = { v1.x, v1.y, v1.z, v1.w };
        float a2[4] = { v2.x, v2.y, v2.z, v2.w };
        #pragma unroll
        for (int j = 0; j < 4; j++) {
            float inv = powf(10000.0f, -(float)(c4 + j) * (1.0f / 32.0f));
            float sn, cs;
            sincosf(t * inv, &sn, &cs);
            r1[j] = (a1[j] * cs - a2[j] * sn) * 0.125f;
            r2[j] = (a2[j] * cs + a1[j] * sn) * 0.125f;
        }
        int e = row * ASTR + c4;
        store4(O_QH, O_QL, e,      r1[0], r1[1], r1[2], r1[3]);
        store4(O_QH, O_QL, e + 32, r2[0], r2[1], r2[2], r2[3]);
    }
    // ---- stage K with fused RoPE (272 rows, zero-fill OOB) ----
    for (int idx = tid; idx < 272 * 8; idx += 256) {
        int row = idx >> 3, c4 = (idx & 7) << 2;
        int kg = kbase + row;
        float r1[4] = {0.f, 0.f, 0.f, 0.f}, r2[4] = {0.f, 0.f, 0.f, 0.f};
        if (kg >= 0 && kg < S_LEN) {
            const float* base = qkv + (tok_base + kg) * QKV_N + HIDDEN + koff;
            float4 v1 = *(const float4*)(base + c4);
            float4 v2 = *(const float4*)(base + 32 + c4);
            float t = (float)kg;
            float a1[4] = { v1.x, v1.y, v1.z, v1.w };
            float a2[4] = { v2.x, v2.y, v2.z, v2.w };
            #pragma unroll
            for (int j = 0; j < 4; j++) {
                float inv = powf(10000.0f, -(float)(c4 + j) * (1.0f / 32.0f));
                float sn, cs;
                sincosf(t * inv, &sn, &cs);
                r1[j] = a1[j] * cs - a2[j] * sn;
                r2[j] = a2[j] * cs + a1[j] * sn;
            }
        }
        int e = row * ASTR + c4;
        store4(O_KH, O_KL, e,      r1[0], r1[1], r1[2], r1[3]);
        store4(O_KH, O_KL, e + 32, r2[0], r2[1], r2[2], r2[3]);
    }
    // ---- stage V (272 rows, zero-fill OOB) ----
    for (int idx = tid; idx < 272 * 16; idx += 256) {
        int row = idx >> 4, c4 = (idx & 15) << 2;
        int kg = kbase + row;
        float4 vv = make_float4(0.f, 0.f, 0.f, 0.f);
        if (kg >= 0 && kg < S_LEN)
            vv = *(const float4*)(qkv + (tok_base + kg) * QKV_N + 2 * HIDDEN + koff + c4);
        store4(O_VH, O_VL, row * ASTR + c4, vv.x, vv.y, vv.z, vv.w);
    }
    __syncthreads();

    // ---- per-warp compute ----
    const int w = tid >> 5, lane = tid & 31;
    const int quad = lane >> 3, lrow = lane & 7;
    const int a_off = ((quad & 1) * 8 + lrow) * ASTR + (quad >> 1) * 8;
    const int b_off = lrow * ASTR + (quad & 1) * 8;
    const int qrow0 = 16 * w;

    float S[20][4];
    #pragma unroll
    for (int jj = 0; jj < 20; jj++)
        S[jj][0] = S[jj][1] = S[jj][2] = S[jj][3] = 0.f;

    #pragma unroll
    for (int kk = 0; kk < 4; kk++) {
        uint32_t qh[4], ql[4];
        uint32_t ea = sb + 2u * (O_QH + qrow0 * ASTR + kk * 16 + a_off);
        uint32_t el = sb + 2u * (O_QL + qrow0 * ASTR + kk * 16 + a_off);
        LDMX4(qh[0], qh[1], qh[2], qh[3], ea);
        LDMX4(ql[0], ql[1], ql[2], ql[3], el);
        #pragma unroll
        for (int jc = 0; jc < 4; jc++) {
            uint32_t kh[5][2], kl[5][2];
            #pragma unroll
            for (int j5 = 0; j5 < 5; j5++) {
                int kr = qrow0 + (jc * 5 + j5) * 8;
                LDMX2(kh[j5][0], kh[j5][1], sb + 2u * (O_KH + kr * ASTR + kk * 16 + b_off));
                LDMX2(kl[j5][0], kl[j5][1], sb + 2u * (O_KL + kr * ASTR + kk * 16 + b_off));
            }
            #pragma unroll
            for (int j5 = 0; j5 < 5; j5++)
                MMA16816(S[jc * 5 + j5], qh, kh[j5]);
            #pragma unroll
            for (int j5 = 0; j5 < 5; j5++)
                MMA16816(S[jc * 5 + j5], qh, kl[j5]);
            #pragma unroll
            for (int j5 = 0; j5 < 5; j5++)
                MMA16816(S[jc * 5 + j5], ql, kh[j5]);
        }
    }

    // ---- mask + softmax ----
    const int g = lane >> 2, tg = lane & 3;
    const int qg = q0 + qrow0 + g;
    #pragma unroll
    for (int jj = 0; jj < 20; jj++) {
        int col = kbase + qrow0 + jj * 8 + 2 * tg;
        #pragma unroll
        for (int e = 0; e < 2; e++) {
            int c = col + e;
            bool okc = (c >= 0) && (c < S_LEN);
            int d0 = c - qg;
            if (!(okc && d0 >= -WIN && d0 <= WIN)) S[jj][e] = -1e30f;
            int d1 = d0 - 8;
            if (!(okc && d1 >= -WIN && d1 <= WIN)) S[jj][2 + e] = -1e30f;
        }
    }
    float m0 = -1e30f, m1 = -1e30f;
    #pragma unroll
    for (int jj = 0; jj < 20; jj++) {
        m0 = fmaxf(m0, fmaxf(S[jj][0], S[jj][1]));
        m1 = fmaxf(m1, fmaxf(S[jj][2], S[jj][3]));
    }
    m0 = fmaxf(m0, __shfl_xor_sync(0xffffffffu, m0, 1));
    m0 = fmaxf(m0, __shfl_xor_sync(0xffffffffu, m0, 2));
    m1 = fmaxf(m1, __shfl_xor_sync(0xffffffffu, m1, 1));
    m1 = fmaxf(m1, __shfl_xor_sync(0xffffffffu, m1, 2));
    float s0 = 0.f, s1 = 0.f;
    #pragma unroll
    for (int jj = 0; jj < 20; jj++) {
        S[jj][0] = __expf(S[jj][0] - m0); s0 += S[jj][0];
        S[jj][1] = __expf(S[jj][1] - m0); s0 += S[jj][1];
        S[jj][2] = __expf(S[jj][2] - m1); s1 += S[jj][2];
        S[jj][3] = __expf(S[jj][3] - m1); s1 += S[jj][3];
    }
    s0 += __shfl_xor_sync(0xffffffffu, s0, 1);
    s0 += __shfl_xor_sync(0xffffffffu, s0, 2);
    s1 += __shfl_xor_sync(0xffffffffu, s1, 1);
    s1 += __shfl_xor_sync(0xffffffffu, s1, 2);
    const float r0 = 1.0f / s0, r1 = 1.0f / s1;
    #pragma unroll
    for (int jj = 0; jj < 20; jj++) {
        S[jj][0] *= r0; S[jj][1] *= r0; S[jj][2] *= r1; S[jj][3] *= r1;
    }

    // ---- O = P V (3-term) ----
    float O[8][4];
    #pragma unroll
    for (int ni = 0; ni < 8; ni++)
        O[ni][0] = O[ni][1] = O[ni][2] = O[ni][3] = 0.f;

    const int vrow = lane & 15;
    #pragma unroll
    for (int kt = 0; kt < 10; kt++) {
        const float* sA = S[2 * kt];
        const float* sB = S[2 * kt + 1];
        uint32_t ph[4], pl[4];
        ph[0] = pack_hi2(sA[0], sA[1]); pl[0] = pack_lo2(sA[0], sA[1]);
        ph[1] = pack_hi2(sA[2], sA[3]); pl[1] = pack_lo2(sA[2], sA[3]);
        ph[2] = pack_hi2(sB[0], sB[1]); pl[2] = pack_lo2(sB[0], sB[1]);
        ph[3] = pack_hi2(sB[2], sB[3]); pl[3] = pack_lo2(sB[2], sB[3]);
        const int vr = qrow0 + kt * 16 + vrow;
        #pragma unroll
        for (int nc = 0; nc < 2; nc++) {
            uint32_t vh[4][2], vl[4][2];
            #pragma unroll
            for (int n4 = 0; n4 < 4; n4++) {
                int ni = nc * 4 + n4;
                LDMX2T(vh[n4][0], vh[n4][1], sb + 2u * (O_VH + vr * ASTR + ni * 8));
                LDMX2T(vl[n4][0], vl[n4][1], sb + 2u * (O_VL + vr * ASTR + ni * 8));
            }
            #pragma unroll
            for (int n4 = 0; n4 < 4; n4++)
                MMA16816(O[nc * 4 + n4], ph, vh[n4]);
            #pragma unroll
            for (int n4 = 0; n4 < 4; n4++)
                MMA16816(O[nc * 4 + n4], ph, vl[n4]);
            #pragma unroll
            for (int n4 = 0; n4 < 4; n4++)
                MMA16816(O[nc * 4 + n4], pl, vh[n4]);
        }
    }

    // ---- store O ----
    #pragma unroll
    for (int ni = 0; ni < 8; ni++) {
        const int col = koff + ni * 8 + 2 * tg;
        *(float2*)&attn_out[(tok_base + qg) * HIDDEN + col] =
            make_float2(O[ni][0], O[ni][1]);
        *(float2*)&attn_out[(tok_base + qg + 8) * HIDDEN + col] =
            make_float2(O[ni][2], O[ni][3]);
    }
}

// ---------------------------------------------------------------------------
// Launch
// ---------------------------------------------------------------------------
extern "C" void kernel_launch(void* const* d_in, const int* in_sizes, int n_in,
                              void* d_out, int out_size)
{
    const float* hidden = nullptr;
    const float* wqkv = nullptr;
    const float* wo = nullptr;
    for (int i = 0; i < n_in; i++) {
        if (in_sizes[i] == NTOK * HIDDEN)            hidden = (const float*)d_in[i];
        else if (in_sizes[i] == QKV_N * HIDDEN)      wqkv   = (const float*)d_in[i];
        else if (in_sizes[i] == HIDDEN * HIDDEN)     wo     = (const float*)d_in[i];
    }

    float *qkv, *attn;
    __nv_bfloat16 *hh, *hl, *wqh, *wql, *woh, *wol, *ah, *al;
    cudaGetSymbolAddress((void**)&qkv,  g_qkv);
    cudaGetSymbolAddress((void**)&attn, g_attn);
    cudaGetSymbolAddress((void**)&hh,  g_hh);
    cudaGetSymbolAddress((void**)&hl,  g_hl);
    cudaGetSymbolAddress((void**)&wqh, g_wqh);
    cudaGetSymbolAddress((void**)&wql, g_wql);
    cudaGetSymbolAddress((void**)&woh, g_woh);
    cudaGetSymbolAddress((void**)&wol, g_wol);
    cudaGetSymbolAddress((void**)&ah,  g_ah);
    cudaGetSymbolAddress((void**)&al,  g_al);

    cudaFuncSetAttribute(gemm_bf16_kernel,
                         cudaFuncAttributeMaxDynamicSharedMemorySize, GSMEM);
    cudaFuncSetAttribute(attn_mma_kernel,
                         cudaFuncAttributeMaxDynamicSharedMemorySize, ATT_SMEM_BYTES);

    // 0) split inputs into bf16 hi/lo
    {
        int n;
        n = NTOK * HIDDEN;
        split_bf16_kernel<<<(n / 4 + 255) / 256, 256>>>(hidden, hh, hl, n);
        n = QKV_N * HIDDEN;
        split_bf16_kernel<<<(n / 4 + 255) / 256, 256>>>(wqkv, wqh, wql, n);
        n = HIDDEN * HIDDEN;
        split_bf16_kernel<<<(n / 4 + 255) / 256, 256>>>(wo, woh, wol, n);
    }

    // 1) QKV projection (HMMA): [8192,3072] = hidden @ Wqkv^T
    gemm_bf16_kernel<<<dim3(QKV_N / 128, NTOK / 128), 256, GSMEM>>>(
        hh, hl, wqh, wql, qkv, NTOK, QKV_N, HIDDEN);

    // 2) sliding-window attention (HMMA hi/lo, RoPE fused into staging)
    attn_mma_kernel<<<B_SZ * NHEADS * (S_LEN / 128), 256, ATT_SMEM_BYTES>>>(qkv, attn);

    // 3) split attention output, then output projection (HMMA)
    {
        int n = NTOK * HIDDEN;
        split_bf16_kernel<<<(n / 4 + 255) / 256, 256>>>(attn, ah, al, n);
    }
    gemm_bf16_kernel<<<dim3(HIDDEN / 128, NTOK / 128), 256, GSMEM>>>(
        ah, al, woh, wol, (float*)d_out, NTOK, HIDDEN, HIDDEN);
}

// round 10
// speedup vs baseline: 3.4501x; 1.0043x over previous
#include <cuda_runtime.h>
#include <cuda_bf16.h>
#include <math.h>
#include <stdint.h>

// Problem constants (fixed by setup_inputs)
#define B_SZ    8
#define S_LEN   1024
#define NHEADS  16
#define HDIM    64
#define HIDDEN  1024
#define WIN     64
#define NTOK    (B_SZ * S_LEN)          // 8192
#define QKV_N   (3 * HIDDEN)            // 3072

// ---------------------------------------------------------------------------
// Scratch (device globals — no allocation allowed in kernel_launch)
// ---------------------------------------------------------------------------
__device__ __nv_bfloat16 g_qh[(size_t)NTOK * QKV_N];   // 48 MB: qkv hi
__device__ __nv_bfloat16 g_ql[(size_t)NTOK * QKV_N];   // 48 MB: qkv lo

__device__ __nv_bfloat16 g_hh[(size_t)NTOK * HIDDEN];
__device__ __nv_bfloat16 g_hl[(size_t)NTOK * HIDDEN];
__device__ __nv_bfloat16 g_wqh[(size_t)QKV_N * HIDDEN];
__device__ __nv_bfloat16 g_wql[(size_t)QKV_N * HIDDEN];
__device__ __nv_bfloat16 g_woh[(size_t)HIDDEN * HIDDEN];
__device__ __nv_bfloat16 g_wol[(size_t)HIDDEN * HIDDEN];
__device__ __nv_bfloat16 g_ah[(size_t)NTOK * HIDDEN];
__device__ __nv_bfloat16 g_al[(size_t)NTOK * HIDDEN];

__device__ float2 g_rope[S_LEN * 32];   // (cos, sin) per (t, d)

// ---------------------------------------------------------------------------
// rope table
// ---------------------------------------------------------------------------
__global__ void rope_table_kernel()
{
    int idx = blockIdx.x * blockDim.x + threadIdx.x;
    if (idx >= S_LEN * 32) return;
    int t = idx >> 5, d = idx & 31;
    float inv = powf(10000.0f, -(float)d * (1.0f / 32.0f));
    float sn, cs;
    sincosf((float)t * inv, &sn, &cs);
    g_rope[idx] = make_float2(cs, sn);
}

// ---------------------------------------------------------------------------
// fp32 -> bf16 hi/lo split
// ---------------------------------------------------------------------------
__global__ void split_bf16_kernel(const float* __restrict__ x,
                                  __nv_bfloat16* __restrict__ hi,
                                  __nv_bfloat16* __restrict__ lo, int n)
{
    int i = (blockIdx.x * blockDim.x + threadIdx.x) * 4;
    if (i >= n) return;
    float4 v = *(const float4*)(x + i);
    __nv_bfloat16 h0 = __float2bfloat16(v.x);
    __nv_bfloat16 h1 = __float2bfloat16(v.y);
    __nv_bfloat16 h2 = __float2bfloat16(v.z);
    __nv_bfloat16 h3 = __float2bfloat16(v.w);
    *(__nv_bfloat162*)(hi + i)     = __nv_bfloat162(h0, h1);
    *(__nv_bfloat162*)(hi + i + 2) = __nv_bfloat162(h2, h3);
    *(__nv_bfloat162*)(lo + i) = __nv_bfloat162(
        __float2bfloat16(v.x - __bfloat162float(h0)),
        __float2bfloat16(v.y - __bfloat162float(h1)));
    *(__nv_bfloat162*)(lo + i + 2) = __nv_bfloat162(
        __float2bfloat16(v.z - __bfloat162float(h2)),
        __float2bfloat16(v.w - __bfloat162float(h3)));
}

// ---------------------------------------------------------------------------
// PTX helpers
// ---------------------------------------------------------------------------
__device__ __forceinline__ uint32_t smem_u32(const void* p) {
    uint32_t a;
    asm("{ .reg .u64 t; cvta.to.shared.u64 t, %1; cvt.u32.u64 %0, t; }"
        : "=r"(a) : "l"(p));
    return a;
}

#define CP_ASYNC16(dst, src) \
    asm volatile("cp.async.cg.shared.global [%0], [%1], 16;" \
                 :: "r"(dst), "l"(src) : "memory")
#define CP_COMMIT()  asm volatile("cp.async.commit_group;" ::: "memory")
#define CP_WAIT0()   asm volatile("cp.async.wait_group 0;" ::: "memory")

#define LDMX4(r0, r1, r2, r3, a) \
    asm volatile("ldmatrix.sync.aligned.m8n8.x4.shared.b16 {%0,%1,%2,%3}, [%4];" \
                 : "=r"(r0), "=r"(r1), "=r"(r2), "=r"(r3) : "r"(a))

#define LDMX2(r0, r1, a) \
    asm volatile("ldmatrix.sync.aligned.m8n8.x2.shared.b16 {%0,%1}, [%2];" \
                 : "=r"(r0), "=r"(r1) : "r"(a))

#define LDMX2T(r0, r1, a) \
    asm volatile("ldmatrix.sync.aligned.m8n8.x2.trans.shared.b16 {%0,%1}, [%2];" \
                 : "=r"(r0), "=r"(r1) : "r"(a))

#define MMA16816(d, a, b) \
    asm volatile("mma.sync.aligned.m16n8k16.row.col.f32.bf16.bf16.f32 " \
                 "{%0,%1,%2,%3}, {%4,%5,%6,%7}, {%8,%9}, {%0,%1,%2,%3};" \
                 : "+f"((d)[0]), "+f"((d)[1]), "+f"((d)[2]), "+f"((d)[3]) \
                 : "r"((a)[0]), "r"((a)[1]), "r"((a)[2]), "r"((a)[3]), \
                   "r"((b)[0]), "r"((b)[1]))

__device__ __forceinline__ uint32_t pack_hi2(float x, float y) {
    __nv_bfloat162 p(__float2bfloat16(x), __float2bfloat16(y));
    return *(uint32_t*)&p;
}
__device__ __forceinline__ uint32_t pack_lo2(float x, float y) {
    float hx = __bfloat162float(__float2bfloat16(x));
    float hy = __bfloat162float(__float2bfloat16(y));
    __nv_bfloat162 p(__float2bfloat16(x - hx), __float2bfloat16(y - hy));
    return *(uint32_t*)&p;
}

// ---------------------------------------------------------------------------
// bf16 split GEMM via mma.sync — persistent CTAs (grid=296, tile loop).
// If Chi != nullptr, write bf16 hi/lo split output; else fp32 C.
// ---------------------------------------------------------------------------
#define KC        32
#define TSTRIDE   40
#define TILE_B    (128 * TSTRIDE * 2)   // 10240 B
#define BUF_B     (4 * TILE_B)
#define GSMEM     (2 * BUF_B)           // 81920 B

__global__ __launch_bounds__(256, 2) void gemm_bf16_kernel(
    const __nv_bfloat16* __restrict__ Ah, const __nv_bfloat16* __restrict__ Al,
    const __nv_bfloat16* __restrict__ Bh, const __nv_bfloat16* __restrict__ Bl,
    float* __restrict__ C,
    __nv_bfloat16* __restrict__ Chi, __nv_bfloat16* __restrict__ Clo,
    int M, int N, int K, int ntiles)
{
    extern __shared__ char smem[];
    const uint32_t sbase = smem_u32(smem);

    const int tid  = threadIdx.x;
    const int wid  = tid >> 5;
    const int lane = tid & 31;
    const int m0 = (wid & 1) * 64;
    const int n0 = (wid >> 1) * 32;
    const int nb = N >> 7;

    const int row0 = tid >> 2;          // 0..63
    const int row1 = row0 + 64;         // 64..127
    const int c16  = tid & 3;

    const int quad = lane >> 3, lrow = lane & 7;
    const int a_off = ((quad & 1) * 8 + lrow) * TSTRIDE + (quad >> 1) * 8;
    const int b_off = (lane & 7) * TSTRIDE + ((lane >> 3) & 1) * 8;
    const int g = lane >> 2, tg = lane & 3;
    const int NCH = K / KC;             // even (K=1024)

    for (int tile = blockIdx.x; tile < ntiles; tile += gridDim.x) {
        const int bm = (tile / nb) * 128;
        const int bn = (tile % nb) * 128;
        const __nv_bfloat16* srcs[4] = { Ah, Al, Bh, Bl };
        const int r0s[4] = { bm, bm, bn, bn };

        auto stage_async = [&](int buf, int ch) {
            #pragma unroll
            for (int t = 0; t < 4; t++) {
                const __nv_bfloat16* s = srcs[t] + (size_t)r0s[t] * K + ch * KC + c16 * 8;
                uint32_t db = sbase + buf * BUF_B + t * TILE_B + c16 * 16;
                CP_ASYNC16(db + row0 * (TSTRIDE * 2), s + (size_t)row0 * K);
                CP_ASYNC16(db + row1 * (TSTRIDE * 2), s + (size_t)row1 * K);
            }
        };

        float acc[4][4][4] = {};

        stage_async(0, 0);
        CP_COMMIT();

        for (int c = 0; c < NCH; c++) {
            const int buf = c & 1;
            CP_WAIT0();
            __syncthreads();
            if (c + 1 < NCH) { stage_async((c + 1) & 1, c + 1); CP_COMMIT(); }

            const uint32_t base = sbase + buf * BUF_B;
            #pragma unroll
            for (int kk = 0; kk < 2; kk++) {
                uint32_t ah[4][4], al[4][4], bh[4][2], bl[4][2];
                #pragma unroll
                for (int mi = 0; mi < 4; mi++) {
                    uint32_t ea = ((m0 + mi * 16) * TSTRIDE + kk * 16 + a_off) * 2;
                    LDMX4(ah[mi][0], ah[mi][1], ah[mi][2], ah[mi][3], base + ea);
                    LDMX4(al[mi][0], al[mi][1], al[mi][2], al[mi][3], base + TILE_B + ea);
                }
                #pragma unroll
                for (int ni = 0; ni < 4; ni++) {
                    uint32_t eb = ((n0 + ni * 8) * TSTRIDE + kk * 16 + b_off) * 2;
                    LDMX2(bh[ni][0], bh[ni][1], base + 2 * TILE_B + eb);
                    LDMX2(bl[ni][0], bl[ni][1], base + 3 * TILE_B + eb);
                }
                #pragma unroll
                for (int mi = 0; mi < 4; mi++)
                    #pragma unroll
                    for (int ni = 0; ni < 4; ni++)
                        MMA16816(acc[mi][ni], ah[mi], bh[ni]);
                #pragma unroll
                for (int mi = 0; mi < 4; mi++)
                    #pragma unroll
                    for (int ni = 0; ni < 4; ni++)
                        MMA16816(acc[mi][ni], ah[mi], bl[ni]);
                #pragma unroll
                for (int mi = 0; mi < 4; mi++)
                    #pragma unroll
                    for (int ni = 0; ni < 4; ni++)
                        MMA16816(acc[mi][ni], al[mi], bh[ni]);
            }
            __syncthreads();
        }

        if (Chi) {
            #pragma unroll
            for (int mi = 0; mi < 4; mi++) {
                #pragma unroll
                for (int ni = 0; ni < 4; ni++) {
                    const int col = bn + n0 + ni * 8 + tg * 2;
                    size_t i0 = (size_t)(bm + m0 + mi * 16 + g) * N + col;
                    size_t i1 = i0 + 8 * (size_t)N;
                    *(uint32_t*)&Chi[i0] = pack_hi2(acc[mi][ni][0], acc[mi][ni][1]);
                    *(uint32_t*)&Clo[i0] = pack_lo2(acc[mi][ni][0], acc[mi][ni][1]);
                    *(uint32_t*)&Chi[i1] = pack_hi2(acc[mi][ni][2], acc[mi][ni][3]);
                    *(uint32_t*)&Clo[i1] = pack_lo2(acc[mi][ni][2], acc[mi][ni][3]);
                }
            }
        } else {
            #pragma unroll
            for (int mi = 0; mi < 4; mi++) {
                const int row = bm + m0 + mi * 16 + g;
                #pragma unroll
                for (int ni = 0; ni < 4; ni++) {
                    const int col = bn + n0 + ni * 8 + tg * 2;
                    *(float2*)&C[(size_t)row * N + col] =
                        make_float2(acc[mi][ni][0], acc[mi][ni][1]);
                    *(float2*)&C[(size_t)(row + 8) * N + col] =
                        make_float2(acc[mi][ni][2], acc[mi][ni][3]);
                }
            }
        }
        __syncthreads();
    }
}

// ---------------------------------------------------------------------------
// Sliding-window attention via HMMA (hi/lo bf16, 3-term).
// Inputs are bf16 hi/lo qkv; RoPE via precomputed table; V staged as pure
// copy; epilogue writes bf16 hi/lo attention output directly.
// ---------------------------------------------------------------------------
#define ASTR   72
#define O_QH   0
#define O_QL   (128 * ASTR)
#define O_KH   (2 * 128 * ASTR)
#define O_KL   (O_KH + 272 * ASTR)
#define O_VH   (O_KL + 272 * ASTR)
#define O_VL   (O_VH + 272 * ASTR)
#define ATT_SMEM_BYTES ((O_VL + 272 * ASTR) * 2)   // 193536

__global__ __launch_bounds__(256, 1) void attn_mma_kernel(
    const __nv_bfloat16* __restrict__ qh, const __nv_bfloat16* __restrict__ ql,
    const float2* __restrict__ rope,
    __nv_bfloat16* __restrict__ out_h, __nv_bfloat16* __restrict__ out_l)
{
    extern __shared__ __nv_bfloat16 smb[];
    const uint32_t sb = smem_u32(smb);

    const int bx = blockIdx.x;          // qt + 8*(h + 16*b)
    const int qt = bx & 7;
    const int h  = (bx >> 3) & 15;
    const int b  = bx >> 7;
    const int q0 = qt * 128;
    const int kbase = q0 - 64;
    const size_t tok_base = (size_t)b * S_LEN;
    const int koff = h * HDIM;

    const int tid = threadIdx.x;

    auto store4 = [&](int oh, int ol, int e, float x0, float x1, float x2, float x3) {
        __nv_bfloat16 h0 = __float2bfloat16(x0), h1 = __float2bfloat16(x1);
        __nv_bfloat16 h2 = __float2bfloat16(x2), h3 = __float2bfloat16(x3);
        *(__nv_bfloat162*)&smb[oh + e]     = __nv_bfloat162(h0, h1);
        *(__nv_bfloat162*)&smb[oh + e + 2] = __nv_bfloat162(h2, h3);
        *(__nv_bfloat162*)&smb[ol + e] = __nv_bfloat162(
            __float2bfloat16(x0 - __bfloat162float(h0)),
            __float2bfloat16(x1 - __bfloat162float(h1)));
        *(__nv_bfloat162*)&smb[ol + e + 2] = __nv_bfloat162(
            __float2bfloat16(x2 - __bfloat162float(h2)),
            __float2bfloat16(x3 - __bfloat162float(h3)));
    };

    // loads 4 fp32 values = hi+lo at bf16 pair granularity
    auto load4 = [&](const __nv_bfloat16* ph, const __nv_bfloat16* pl, float* v) {
        __nv_bfloat162 h01 = *(const __nv_bfloat162*)(ph);
        __nv_bfloat162 h23 = *(const __nv_bfloat162*)(ph + 2);
        __nv_bfloat162 l01 = *(const __nv_bfloat162*)(pl);
        __nv_bfloat162 l23 = *(const __nv_bfloat162*)(pl + 2);
        v[0] = __bfloat162float(h01.x) + __bfloat162float(l01.x);
        v[1] = __bfloat162float(h01.y) + __bfloat162float(l01.y);
        v[2] = __bfloat162float(h23.x) + __bfloat162float(l23.x);
        v[3] = __bfloat162float(h23.y) + __bfloat162float(l23.y);
    };

    // ---- stage Q with table RoPE (scaled by 1/8) ----
    for (int idx = tid; idx < 128 * 8; idx += 256) {
        int row = idx >> 3, c4 = (idx & 7) << 2;     // c4 in 0..28
        size_t off = (tok_base + q0 + row) * QKV_N + koff;
        float a1[4], a2[4];
        load4(qh + off + c4,      ql + off + c4,      a1);
        load4(qh + off + 32 + c4, ql + off + 32 + c4, a2);
        const float2* rp = rope + (q0 + row) * 32 + c4;
        float r1[4], r2[4];
        #pragma unroll
        for (int j = 0; j < 4; j++) {
            float2 cs = rp[j];
            r1[j] = (a1[j] * cs.x - a2[j] * cs.y) * 0.125f;
            r2[j] = (a2[j] * cs.x + a1[j] * cs.y) * 0.125f;
        }
        int e = row * ASTR + c4;
        store4(O_QH, O_QL, e,      r1[0], r1[1], r1[2], r1[3]);
        store4(O_QH, O_QL, e + 32, r2[0], r2[1], r2[2], r2[3]);
    }
    // ---- stage K with table RoPE (272 rows, zero-fill OOB) ----
    for (int idx = tid; idx < 272 * 8; idx += 256) {
        int row = idx >> 3, c4 = (idx & 7) << 2;
        int kg = kbase + row;
        float r1[4] = {0.f, 0.f, 0.f, 0.f}, r2[4] = {0.f, 0.f, 0.f, 0.f};
        if (kg >= 0 && kg < S_LEN) {
            size_t off = (tok_base + kg) * QKV_N + HIDDEN + koff;
            float a1[4], a2[4];
            load4(qh + off + c4,      ql + off + c4,      a1);
            load4(qh + off + 32 + c4, ql + off + 32 + c4, a2);
            const float2* rp = rope + kg * 32 + c4;
            #pragma unroll
            for (int j = 0; j < 4; j++) {
                float2 cs = rp[j];
                r1[j] = a1[j] * cs.x - a2[j] * cs.y;
                r2[j] = a2[j] * cs.x + a1[j] * cs.y;
            }
        }
        int e = row * ASTR + c4;
        store4(O_KH, O_KL, e,      r1[0], r1[1], r1[2], r1[3]);
        store4(O_KH, O_KL, e + 32, r2[0], r2[1], r2[2], r2[3]);
    }
    // ---- stage V: pure bf16 copy (272 rows x 8 uint4 per array) ----
    for (int idx = tid; idx < 272 * 8; idx += 256) {
        int row = idx >> 3, c8 = (idx & 7) << 3;
        int kg = kbase + row;
        uint4 vh = make_uint4(0, 0, 0, 0), vl = vh;
        if (kg >= 0 && kg < S_LEN) {
            size_t off = (tok_base + kg) * QKV_N + 2 * HIDDEN + koff + c8;
            vh = *(const uint4*)(qh + off);
            vl = *(const uint4*)(ql + off);
        }
        int e = row * ASTR + c8;
        *(uint4*)&smb[O_VH + e] = vh;
        *(uint4*)&smb[O_VL + e] = vl;
    }
    __syncthreads();

    // ---- per-warp compute ----
    const int w = tid >> 5, lane = tid & 31;
    const int quad = lane >> 3, lrow = lane & 7;
    const int a_off = ((quad & 1) * 8 + lrow) * ASTR + (quad >> 1) * 8;
    const int b_off = lrow * ASTR + (quad & 1) * 8;
    const int qrow0 = 16 * w;

    float S[20][4];
    #pragma unroll
    for (int jj = 0; jj < 20; jj++)
        S[jj][0] = S[jj][1] = S[jj][2] = S[jj][3] = 0.f;

    #pragma unroll
    for (int kk = 0; kk < 4; kk++) {
        uint32_t qhf[4], qlf[4];
        uint32_t ea = sb + 2u * (O_QH + qrow0 * ASTR + kk * 16 + a_off);
        uint32_t el = sb + 2u * (O_QL + qrow0 * ASTR + kk * 16 + a_off);
        LDMX4(qhf[0], qhf[1], qhf[2], qhf[3], ea);
        LDMX4(qlf[0], qlf[1], qlf[2], qlf[3], el);
        #pragma unroll
        for (int jc = 0; jc < 4; jc++) {
            uint32_t kh[5][2], kl[5][2];
            #pragma unroll
            for (int j5 = 0; j5 < 5; j5++) {
                int kr = qrow0 + (jc * 5 + j5) * 8;
                LDMX2(kh[j5][0], kh[j5][1], sb + 2u * (O_KH + kr * ASTR + kk * 16 + b_off));
                LDMX2(kl[j5][0], kl[j5][1], sb + 2u * (O_KL + kr * ASTR + kk * 16 + b_off));
            }
            #pragma unroll
            for (int j5 = 0; j5 < 5; j5++)
                MMA16816(S[jc * 5 + j5], qhf, kh[j5]);
            #pragma unroll
            for (int j5 = 0; j5 < 5; j5++)
                MMA16816(S[jc * 5 + j5], qhf, kl[j5]);
            #pragma unroll
            for (int j5 = 0; j5 < 5; j5++)
                MMA16816(S[jc * 5 + j5], qlf, kh[j5]);
        }
    }

    // ---- mask + softmax ----
    const int g = lane >> 2, tg = lane & 3;
    const int qg = q0 + qrow0 + g;
    #pragma unroll
    for (int jj = 0; jj < 20; jj++) {
        int col = kbase + qrow0 + jj * 8 + 2 * tg;
        #pragma unroll
        for (int e = 0; e < 2; e++) {
            int c = col + e;
            bool okc = (c >= 0) && (c < S_LEN);
            int d0 = c - qg;
            if (!(okc && d0 >= -WIN && d0 <= WIN)) S[jj][e] = -1e30f;
            int d1 = d0 - 8;
            if (!(okc && d1 >= -WIN && d1 <= WIN)) S[jj][2 + e] = -1e30f;
        }
    }
    float m0 = -1e30f, m1 = -1e30f;
    #pragma unroll
    for (int jj = 0; jj < 20; jj++) {
        m0 = fmaxf(m0, fmaxf(S[jj][0], S[jj][1]));
        m1 = fmaxf(m1, fmaxf(S[jj][2], S[jj][3]));
    }
    m0 = fmaxf(m0, __shfl_xor_sync(0xffffffffu, m0, 1));
    m0 = fmaxf(m0, __shfl_xor_sync(0xffffffffu, m0, 2));
    m1 = fmaxf(m1, __shfl_xor_sync(0xffffffffu, m1, 1));
    m1 = fmaxf(m1, __shfl_xor_sync(0xffffffffu, m1, 2));
    float s0 = 0.f, s1 = 0.f;
    #pragma unroll
    for (int jj = 0; jj < 20; jj++) {
        S[jj][0] = __expf(S[jj][0] - m0); s0 += S[jj][0];
        S[jj][1] = __expf(S[jj][1] - m0); s0 += S[jj][1];
        S[jj][2] = __expf(S[jj][2] - m1); s1 += S[jj][2];
        S[jj][3] = __expf(S[jj][3] - m1); s1 += S[jj][3];
    }
    s0 += __shfl_xor_sync(0xffffffffu, s0, 1);
    s0 += __shfl_xor_sync(0xffffffffu, s0, 2);
    s1 += __shfl_xor_sync(0xffffffffu, s1, 1);
    s1 += __shfl_xor_sync(0xffffffffu, s1, 2);
    const float r0 = 1.0f / s0, r1 = 1.0f / s1;
    #pragma unroll
    for (int jj = 0; jj < 20; jj++) {
        S[jj][0] *= r0; S[jj][1] *= r0; S[jj][2] *= r1; S[jj][3] *= r1;
    }

    // ---- O = P V (3-term) ----
    float O[8][4];
    #pragma unroll
    for (int ni = 0; ni < 8; ni++)
        O[ni][0] = O[ni][1] = O[ni][2] = O[ni][3] = 0.f;

    const int vrow = lane & 15;
    #pragma unroll
    for (int kt = 0; kt < 10; kt++) {
        const float* sA = S[2 * kt];
        const float* sB = S[2 * kt + 1];
        uint32_t ph[4], pl[4];
        ph[0] = pack_hi2(sA[0], sA[1]); pl[0] = pack_lo2(sA[0], sA[1]);
        ph[1] = pack_hi2(sA[2], sA[3]); pl[1] = pack_lo2(sA[2], sA[3]);
        ph[2] = pack_hi2(sB[0], sB[1]); pl[2] = pack_lo2(sB[0], sB[1]);
        ph[3] = pack_hi2(sB[2], sB[3]); pl[3] = pack_lo2(sB[2], sB[3]);
        const int vr = qrow0 + kt * 16 + vrow;
        #pragma unroll
        for (int nc = 0; nc < 2; nc++) {
            uint32_t vh[4][2], vl[4][2];
            #pragma unroll
            for (int n4 = 0; n4 < 4; n4++) {
                int ni = nc * 4 + n4;
                LDMX2T(vh[n4][0], vh[n4][1], sb + 2u * (O_VH + vr * ASTR + ni * 8));
                LDMX2T(vl[n4][0], vl[n4][1], sb + 2u * (O_VL + vr * ASTR + ni * 8));
            }
            #pragma unroll
            for (int n4 = 0; n4 < 4; n4++)
                MMA16816(O[nc * 4 + n4], ph, vh[n4]);
            #pragma unroll
            for (int n4 = 0; n4 < 4; n4++)
                MMA16816(O[nc * 4 + n4], ph, vl[n4]);
            #pragma unroll
            for (int n4 = 0; n4 < 4; n4++)
                MMA16816(O[nc * 4 + n4], pl, vh[n4]);
        }
    }

    // ---- store O as bf16 hi/lo (feeds out-projection directly) ----
    #pragma unroll
    for (int ni = 0; ni < 8; ni++) {
        const int col = koff + ni * 8 + 2 * tg;
        size_t i0 = (tok_base + qg) * HIDDEN + col;
        size_t i1 = (tok_base + qg + 8) * HIDDEN + col;
        *(uint32_t*)&out_h[i0] = pack_hi2(O[ni][0], O[ni][1]);
        *(uint32_t*)&out_l[i0] = pack_lo2(O[ni][0], O[ni][1]);
        *(uint32_t*)&out_h[i1] = pack_hi2(O[ni][2], O[ni][3]);
        *(uint32_t*)&out_l[i1] = pack_lo2(O[ni][2], O[ni][3]);
    }
}

// ---------------------------------------------------------------------------
// Launch
// ---------------------------------------------------------------------------
extern "C" void kernel_launch(void* const* d_in, const int* in_sizes, int n_in,
                              void* d_out, int out_size)
{
    const float* hidden = nullptr;
    const float* wqkv = nullptr;
    const float* wo = nullptr;
    for (int i = 0; i < n_in; i++) {
        if (in_sizes[i] == NTOK * HIDDEN)            hidden = (const float*)d_in[i];
        else if (in_sizes[i] == QKV_N * HIDDEN)      wqkv   = (const float*)d_in[i];
        else if (in_sizes[i] == HIDDEN * HIDDEN)     wo     = (const float*)d_in[i];
    }

    __nv_bfloat16 *qh, *ql, *hh, *hl, *wqh, *wql, *woh, *wol, *ah, *al;
    float2* rope;
    cudaGetSymbolAddress((void**)&qh,  g_qh);
    cudaGetSymbolAddress((void**)&ql,  g_ql);
    cudaGetSymbolAddress((void**)&hh,  g_hh);
    cudaGetSymbolAddress((void**)&hl,  g_hl);
    cudaGetSymbolAddress((void**)&wqh, g_wqh);
    cudaGetSymbolAddress((void**)&wql, g_wql);
    cudaGetSymbolAddress((void**)&woh, g_woh);
    cudaGetSymbolAddress((void**)&wol, g_wol);
    cudaGetSymbolAddress((void**)&ah,  g_ah);
    cudaGetSymbolAddress((void**)&al,  g_al);
    cudaGetSymbolAddress((void**)&rope, g_rope);

    cudaFuncSetAttribute(gemm_bf16_kernel,
                         cudaFuncAttributeMaxDynamicSharedMemorySize, GSMEM);
    cudaFuncSetAttribute(attn_mma_kernel,
                         cudaFuncAttributeMaxDynamicSharedMemorySize, ATT_SMEM_BYTES);

    // 0) rope table + splits
    rope_table_kernel<<<(S_LEN * 32 + 255) / 256, 256>>>();
    {
        int n;
        n = NTOK * HIDDEN;
        split_bf16_kernel<<<(n / 4 + 255) / 256, 256>>>(hidden, hh, hl, n);
        n = QKV_N * HIDDEN;
        split_bf16_kernel<<<(n / 4 + 255) / 256, 256>>>(wqkv, wqh, wql, n);
        n = HIDDEN * HIDDEN;
        split_bf16_kernel<<<(n / 4 + 255) / 256, 256>>>(wo, woh, wol, n);
    }

    // 1) QKV projection (persistent HMMA) -> bf16 hi/lo qkv
    gemm_bf16_kernel<<<296, 256, GSMEM>>>(
        hh, hl, wqh, wql, nullptr, qh, ql,
        NTOK, QKV_N, HIDDEN, (NTOK / 128) * (QKV_N / 128));

    // 2) sliding-window attention (HMMA hi/lo, table RoPE) -> bf16 hi/lo
    attn_mma_kernel<<<B_SZ * NHEADS * (S_LEN / 128), 256, ATT_SMEM_BYTES>>>(
        qh, ql, rope, ah, al);

    // 3) output projection (persistent HMMA) -> fp32 d_out
    gemm_bf16_kernel<<<296, 256, GSMEM>>>(
        ah, al, woh, wol, (float*)d_out, nullptr, nullptr,
        NTOK, HIDDEN, HIDDEN, (NTOK / 128) * (HIDDEN / 128));
}

// round 11
// speedup vs baseline: 3.5170x; 1.0194x over previous
#include <cuda_runtime.h>
#include <cuda_bf16.h>
#include <math.h>
#include <stdint.h>

// Problem constants (fixed by setup_inputs)
#define B_SZ    8
#define S_LEN   1024
#define NHEADS  16
#define HDIM    64
#define HIDDEN  1024
#define WIN     64
#define NTOK    (B_SZ * S_LEN)          // 8192
#define QKV_N   (3 * HIDDEN)            // 3072

// ---------------------------------------------------------------------------
// Scratch (device globals — no allocation allowed in kernel_launch)
// ---------------------------------------------------------------------------
__device__ __nv_bfloat16 g_qh[(size_t)NTOK * QKV_N];   // 48 MB: qkv hi
__device__ __nv_bfloat16 g_ql[(size_t)NTOK * QKV_N];   // 48 MB: qkv lo

__device__ __nv_bfloat16 g_hh[(size_t)NTOK * HIDDEN];
__device__ __nv_bfloat16 g_hl[(size_t)NTOK * HIDDEN];
__device__ __nv_bfloat16 g_wqh[(size_t)QKV_N * HIDDEN];
__device__ __nv_bfloat16 g_wql[(size_t)QKV_N * HIDDEN];
__device__ __nv_bfloat16 g_woh[(size_t)HIDDEN * HIDDEN];
__device__ __nv_bfloat16 g_wol[(size_t)HIDDEN * HIDDEN];
__device__ __nv_bfloat16 g_ah[(size_t)NTOK * HIDDEN];
__device__ __nv_bfloat16 g_al[(size_t)NTOK * HIDDEN];

__device__ float2 g_rope[S_LEN * 32];   // (cos, sin) per (t, d)

// ---------------------------------------------------------------------------
// rope table
// ---------------------------------------------------------------------------
__global__ void rope_table_kernel()
{
    int idx = blockIdx.x * blockDim.x + threadIdx.x;
    if (idx >= S_LEN * 32) return;
    int t = idx >> 5, d = idx & 31;
    float inv = powf(10000.0f, -(float)d * (1.0f / 32.0f));
    float sn, cs;
    sincosf((float)t * inv, &sn, &cs);
    g_rope[idx] = make_float2(cs, sn);
}

// ---------------------------------------------------------------------------
// fp32 -> bf16 hi/lo split
// ---------------------------------------------------------------------------
__global__ void split_bf16_kernel(const float* __restrict__ x,
                                  __nv_bfloat16* __restrict__ hi,
                                  __nv_bfloat16* __restrict__ lo, int n)
{
    int i = (blockIdx.x * blockDim.x + threadIdx.x) * 4;
    if (i >= n) return;
    float4 v = *(const float4*)(x + i);
    __nv_bfloat16 h0 = __float2bfloat16(v.x);
    __nv_bfloat16 h1 = __float2bfloat16(v.y);
    __nv_bfloat16 h2 = __float2bfloat16(v.z);
    __nv_bfloat16 h3 = __float2bfloat16(v.w);
    *(__nv_bfloat162*)(hi + i)     = __nv_bfloat162(h0, h1);
    *(__nv_bfloat162*)(hi + i + 2) = __nv_bfloat162(h2, h3);
    *(__nv_bfloat162*)(lo + i) = __nv_bfloat162(
        __float2bfloat16(v.x - __bfloat162float(h0)),
        __float2bfloat16(v.y - __bfloat162float(h1)));
    *(__nv_bfloat162*)(lo + i + 2) = __nv_bfloat162(
        __float2bfloat16(v.z - __bfloat162float(h2)),
        __float2bfloat16(v.w - __bfloat162float(h3)));
}

// ---------------------------------------------------------------------------
// PTX helpers
// ---------------------------------------------------------------------------
__device__ __forceinline__ uint32_t smem_u32(const void* p) {
    uint32_t a;
    asm("{ .reg .u64 t; cvta.to.shared.u64 t, %1; cvt.u32.u64 %0, t; }"
        : "=r"(a) : "l"(p));
    return a;
}

#define CP_ASYNC16(dst, src) \
    asm volatile("cp.async.cg.shared.global [%0], [%1], 16;" \
                 :: "r"(dst), "l"(src) : "memory")
#define CP_COMMIT()  asm volatile("cp.async.commit_group;" ::: "memory")
#define CP_WAIT0()   asm volatile("cp.async.wait_group 0;" ::: "memory")

#define LDMX4(r0, r1, r2, r3, a) \
    asm volatile("ldmatrix.sync.aligned.m8n8.x4.shared.b16 {%0,%1,%2,%3}, [%4];" \
                 : "=r"(r0), "=r"(r1), "=r"(r2), "=r"(r3) : "r"(a))

#define LDMX2(r0, r1, a) \
    asm volatile("ldmatrix.sync.aligned.m8n8.x2.shared.b16 {%0,%1}, [%2];" \
                 : "=r"(r0), "=r"(r1) : "r"(a))

#define LDMX2T(r0, r1, a) \
    asm volatile("ldmatrix.sync.aligned.m8n8.x2.trans.shared.b16 {%0,%1}, [%2];" \
                 : "=r"(r0), "=r"(r1) : "r"(a))

#define MMA16816(d, a, b) \
    asm volatile("mma.sync.aligned.m16n8k16.row.col.f32.bf16.bf16.f32 " \
                 "{%0,%1,%2,%3}, {%4,%5,%6,%7}, {%8,%9}, {%0,%1,%2,%3};" \
                 : "+f"((d)[0]), "+f"((d)[1]), "+f"((d)[2]), "+f"((d)[3]) \
                 : "r"((a)[0]), "r"((a)[1]), "r"((a)[2]), "r"((a)[3]), \
                   "r"((b)[0]), "r"((b)[1]))

__device__ __forceinline__ uint32_t pack_hi2(float x, float y) {
    __nv_bfloat162 p(__float2bfloat16(x), __float2bfloat16(y));
    return *(uint32_t*)&p;
}
__device__ __forceinline__ uint32_t pack_lo2(float x, float y) {
    float hx = __bfloat162float(__float2bfloat16(x));
    float hy = __bfloat162float(__float2bfloat16(y));
    __nv_bfloat162 p(__float2bfloat16(x - hx), __float2bfloat16(y - hy));
    return *(uint32_t*)&p;
}

// ---------------------------------------------------------------------------
// bf16 split GEMM via mma.sync — persistent CTAs, 4 warps of 64x64.
// MMA:LDSM ratio 6:1 (B fragments packed pairwise into ldmatrix.x4).
// If Chi != nullptr, write bf16 hi/lo split output; else fp32 C.
// ---------------------------------------------------------------------------
#define KC        32
#define TSTRIDE   40
#define TILE_B    (128 * TSTRIDE * 2)   // 10240 B
#define BUF_B     (4 * TILE_B)
#define GSMEM     (2 * BUF_B)           // 81920 B

__global__ __launch_bounds__(128, 2) void gemm_bf16_kernel(
    const __nv_bfloat16* __restrict__ Ah, const __nv_bfloat16* __restrict__ Al,
    const __nv_bfloat16* __restrict__ Bh, const __nv_bfloat16* __restrict__ Bl,
    float* __restrict__ C,
    __nv_bfloat16* __restrict__ Chi, __nv_bfloat16* __restrict__ Clo,
    int M, int N, int K, int ntiles)
{
    extern __shared__ char smem[];
    const uint32_t sbase = smem_u32(smem);

    const int tid  = threadIdx.x;
    const int wid  = tid >> 5;
    const int lane = tid & 31;
    const int m0 = (wid & 1) * 64;      // warp m offset (2x2 warp grid)
    const int n0 = (wid >> 1) * 64;     // warp n offset
    const int nb = N >> 7;

    const int quad = lane >> 3, lrow = lane & 7;
    // A fragment (16x16): g0 rows+0 k0, g1 rows+8 k0, g2 rows+0 k8, g3 rows+8 k8
    const int a_off = ((quad & 1) * 8 + lrow) * TSTRIDE + (quad >> 1) * 8;
    // B pair fragment (two 8x16 n-tiles in one x4):
    // g0 (ni,k0)  g1 (ni,k8)  g2 (ni+1,k0)  g3 (ni+1,k8)
    const int b_off = ((quad >> 1) * 8 + lrow) * TSTRIDE + (quad & 1) * 8;
    const int g = lane >> 2, tg = lane & 3;
    const int NCH = K / KC;

    for (int tile = blockIdx.x; tile < ntiles; tile += gridDim.x) {
        const int bm = (tile / nb) * 128;
        const int bn = (tile % nb) * 128;
        const __nv_bfloat16* srcs[4] = { Ah, Al, Bh, Bl };
        const int r0s[4] = { bm, bm, bn, bn };

        auto stage_async = [&](int buf, int ch) {
            #pragma unroll
            for (int t = 0; t < 4; t++) {
                const __nv_bfloat16* s = srcs[t] + (size_t)r0s[t] * K + ch * KC;
                uint32_t db = sbase + buf * BUF_B + t * TILE_B;
                #pragma unroll
                for (int i = 0; i < 4; i++) {
                    int u = tid + 128 * i;          // 0..511
                    int row = u >> 2, c16 = u & 3;
                    CP_ASYNC16(db + row * (TSTRIDE * 2) + c16 * 16,
                               s + (size_t)row * K + c16 * 8);
                }
            }
        };

        float acc[4][8][4] = {};

        stage_async(0, 0);
        CP_COMMIT();

        for (int c = 0; c < NCH; c++) {
            const int buf = c & 1;
            CP_WAIT0();
            __syncthreads();
            if (c + 1 < NCH) { stage_async((c + 1) & 1, c + 1); CP_COMMIT(); }

            const uint32_t base = sbase + buf * BUF_B;
            #pragma unroll
            for (int kk = 0; kk < 2; kk++) {
                uint32_t ah[4][4], al[4][4], bh[8][2], bl[8][2];
                #pragma unroll
                for (int mi = 0; mi < 4; mi++) {
                    uint32_t ea = ((m0 + mi * 16) * TSTRIDE + kk * 16 + a_off) * 2;
                    LDMX4(ah[mi][0], ah[mi][1], ah[mi][2], ah[mi][3], base + ea);
                    LDMX4(al[mi][0], al[mi][1], al[mi][2], al[mi][3], base + TILE_B + ea);
                }
                #pragma unroll
                for (int np = 0; np < 4; np++) {
                    uint32_t eb = ((n0 + np * 16) * TSTRIDE + kk * 16 + b_off) * 2;
                    LDMX4(bh[2*np][0], bh[2*np][1], bh[2*np+1][0], bh[2*np+1][1],
                          base + 2 * TILE_B + eb);
                    LDMX4(bl[2*np][0], bl[2*np][1], bl[2*np+1][0], bl[2*np+1][1],
                          base + 3 * TILE_B + eb);
                }
                #pragma unroll
                for (int mi = 0; mi < 4; mi++)
                    #pragma unroll
                    for (int ni = 0; ni < 8; ni++)
                        MMA16816(acc[mi][ni], ah[mi], bh[ni]);
                #pragma unroll
                for (int mi = 0; mi < 4; mi++)
                    #pragma unroll
                    for (int ni = 0; ni < 8; ni++)
                        MMA16816(acc[mi][ni], ah[mi], bl[ni]);
                #pragma unroll
                for (int mi = 0; mi < 4; mi++)
                    #pragma unroll
                    for (int ni = 0; ni < 8; ni++)
                        MMA16816(acc[mi][ni], al[mi], bh[ni]);
            }
            __syncthreads();
        }

        if (Chi) {
            #pragma unroll
            for (int mi = 0; mi < 4; mi++) {
                #pragma unroll
                for (int ni = 0; ni < 8; ni++) {
                    const int col = bn + n0 + ni * 8 + tg * 2;
                    size_t i0 = (size_t)(bm + m0 + mi * 16 + g) * N + col;
                    size_t i1 = i0 + 8 * (size_t)N;
                    *(uint32_t*)&Chi[i0] = pack_hi2(acc[mi][ni][0], acc[mi][ni][1]);
                    *(uint32_t*)&Clo[i0] = pack_lo2(acc[mi][ni][0], acc[mi][ni][1]);
                    *(uint32_t*)&Chi[i1] = pack_hi2(acc[mi][ni][2], acc[mi][ni][3]);
                    *(uint32_t*)&Clo[i1] = pack_lo2(acc[mi][ni][2], acc[mi][ni][3]);
                }
            }
        } else {
            #pragma unroll
            for (int mi = 0; mi < 4; mi++) {
                const int row = bm + m0 + mi * 16 + g;
                #pragma unroll
                for (int ni = 0; ni < 8; ni++) {
                    const int col = bn + n0 + ni * 8 + tg * 2;
                    *(float2*)&C[(size_t)row * N + col] =
                        make_float2(acc[mi][ni][0], acc[mi][ni][1]);
                    *(float2*)&C[(size_t)(row + 8) * N + col] =
                        make_float2(acc[mi][ni][2], acc[mi][ni][3]);
                }
            }
        }
        __syncthreads();
    }
}

// ---------------------------------------------------------------------------
// Sliding-window attention via HMMA (hi/lo bf16, 3-term). Unchanged from R10.
// ---------------------------------------------------------------------------
#define ASTR   72
#define O_QH   0
#define O_QL   (128 * ASTR)
#define O_KH   (2 * 128 * ASTR)
#define O_KL   (O_KH + 272 * ASTR)
#define O_VH   (O_KL + 272 * ASTR)
#define O_VL   (O_VH + 272 * ASTR)
#define ATT_SMEM_BYTES ((O_VL + 272 * ASTR) * 2)   // 193536

__global__ __launch_bounds__(256, 1) void attn_mma_kernel(
    const __nv_bfloat16* __restrict__ qh, const __nv_bfloat16* __restrict__ ql,
    const float2* __restrict__ rope,
    __nv_bfloat16* __restrict__ out_h, __nv_bfloat16* __restrict__ out_l)
{
    extern __shared__ __nv_bfloat16 smb[];
    const uint32_t sb = smem_u32(smb);

    const int bx = blockIdx.x;          // qt + 8*(h + 16*b)
    const int qt = bx & 7;
    const int h  = (bx >> 3) & 15;
    const int b  = bx >> 7;
    const int q0 = qt * 128;
    const int kbase = q0 - 64;
    const size_t tok_base = (size_t)b * S_LEN;
    const int koff = h * HDIM;

    const int tid = threadIdx.x;

    auto store4 = [&](int oh, int ol, int e, float x0, float x1, float x2, float x3) {
        __nv_bfloat16 h0 = __float2bfloat16(x0), h1 = __float2bfloat16(x1);
        __nv_bfloat16 h2 = __float2bfloat16(x2), h3 = __float2bfloat16(x3);
        *(__nv_bfloat162*)&smb[oh + e]     = __nv_bfloat162(h0, h1);
        *(__nv_bfloat162*)&smb[oh + e + 2] = __nv_bfloat162(h2, h3);
        *(__nv_bfloat162*)&smb[ol + e] = __nv_bfloat162(
            __float2bfloat16(x0 - __bfloat162float(h0)),
            __float2bfloat16(x1 - __bfloat162float(h1)));
        *(__nv_bfloat162*)&smb[ol + e + 2] = __nv_bfloat162(
            __float2bfloat16(x2 - __bfloat162float(h2)),
            __float2bfloat16(x3 - __bfloat162float(h3)));
    };

    auto load4 = [&](const __nv_bfloat16* ph, const __nv_bfloat16* pl, float* v) {
        __nv_bfloat162 h01 = *(const __nv_bfloat162*)(ph);
        __nv_bfloat162 h23 = *(const __nv_bfloat162*)(ph + 2);
        __nv_bfloat162 l01 = *(const __nv_bfloat162*)(pl);
        __nv_bfloat162 l23 = *(const __nv_bfloat162*)(pl + 2);
        v[0] = __bfloat162float(h01.x) + __bfloat162float(l01.x);
        v[1] = __bfloat162float(h01.y) + __bfloat162float(l01.y);
        v[2] = __bfloat162float(h23.x) + __bfloat162float(l23.x);
        v[3] = __bfloat162float(h23.y) + __bfloat162float(l23.y);
    };

    // ---- stage Q with table RoPE (scaled by 1/8) ----
    for (int idx = tid; idx < 128 * 8; idx += 256) {
        int row = idx >> 3, c4 = (idx & 7) << 2;
        size_t off = (tok_base + q0 + row) * QKV_N + koff;
        float a1[4], a2[4];
        load4(qh + off + c4,      ql + off + c4,      a1);
        load4(qh + off + 32 + c4, ql + off + 32 + c4, a2);
        const float2* rp = rope + (q0 + row) * 32 + c4;
        float r1[4], r2[4];
        #pragma unroll
        for (int j = 0; j < 4; j++) {
            float2 cs = rp[j];
            r1[j] = (a1[j] * cs.x - a2[j] * cs.y) * 0.125f;
            r2[j] = (a2[j] * cs.x + a1[j] * cs.y) * 0.125f;
        }
        int e = row * ASTR + c4;
        store4(O_QH, O_QL, e,      r1[0], r1[1], r1[2], r1[3]);
        store4(O_QH, O_QL, e + 32, r2[0], r2[1], r2[2], r2[3]);
    }
    // ---- stage K with table RoPE (272 rows, zero-fill OOB) ----
    for (int idx = tid; idx < 272 * 8; idx += 256) {
        int row = idx >> 3, c4 = (idx & 7) << 2;
        int kg = kbase + row;
        float r1[4] = {0.f, 0.f, 0.f, 0.f}, r2[4] = {0.f, 0.f, 0.f, 0.f};
        if (kg >= 0 && kg < S_LEN) {
            size_t off = (tok_base + kg) * QKV_N + HIDDEN + koff;
            float a1[4], a2[4];
            load4(qh + off + c4,      ql + off + c4,      a1);
            load4(qh + off + 32 + c4, ql + off + 32 + c4, a2);
            const float2* rp = rope + kg * 32 + c4;
            #pragma unroll
            for (int j = 0; j < 4; j++) {
                float2 cs = rp[j];
                r1[j] = a1[j] * cs.x - a2[j] * cs.y;
                r2[j] = a2[j] * cs.x + a1[j] * cs.y;
            }
        }
        int e = row * ASTR + c4;
        store4(O_KH, O_KL, e,      r1[0], r1[1], r1[2], r1[3]);
        store4(O_KH, O_KL, e + 32, r2[0], r2[1], r2[2], r2[3]);
    }
    // ---- stage V: pure bf16 copy ----
    for (int idx = tid; idx < 272 * 8; idx += 256) {
        int row = idx >> 3, c8 = (idx & 7) << 3;
        int kg = kbase + row;
        uint4 vh = make_uint4(0, 0, 0, 0), vl = vh;
        if (kg >= 0 && kg < S_LEN) {
            size_t off = (tok_base + kg) * QKV_N + 2 * HIDDEN + koff + c8;
            vh = *(const uint4*)(qh + off);
            vl = *(const uint4*)(ql + off);
        }
        int e = row * ASTR + c8;
        *(uint4*)&smb[O_VH + e] = vh;
        *(uint4*)&smb[O_VL + e] = vl;
    }
    __syncthreads();

    // ---- per-warp compute ----
    const int w = tid >> 5, lane = tid & 31;
    const int quad = lane >> 3, lrow = lane & 7;
    const int a_off = ((quad & 1) * 8 + lrow) * ASTR + (quad >> 1) * 8;
    const int b_off = lrow * ASTR + (quad & 1) * 8;
    const int qrow0 = 16 * w;

    float S[20][4];
    #pragma unroll
    for (int jj = 0; jj < 20; jj++)
        S[jj][0] = S[jj][1] = S[jj][2] = S[jj][3] = 0.f;

    #pragma unroll
    for (int kk = 0; kk < 4; kk++) {
        uint32_t qhf[4], qlf[4];
        uint32_t ea = sb + 2u * (O_QH + qrow0 * ASTR + kk * 16 + a_off);
        uint32_t el = sb + 2u * (O_QL + qrow0 * ASTR + kk * 16 + a_off);
        LDMX4(qhf[0], qhf[1], qhf[2], qhf[3], ea);
        LDMX4(qlf[0], qlf[1], qlf[2], qlf[3], el);
        #pragma unroll
        for (int jc = 0; jc < 4; jc++) {
            uint32_t kh[5][2], kl[5][2];
            #pragma unroll
            for (int j5 = 0; j5 < 5; j5++) {
                int kr = qrow0 + (jc * 5 + j5) * 8;
                LDMX2(kh[j5][0], kh[j5][1], sb + 2u * (O_KH + kr * ASTR + kk * 16 + b_off));
                LDMX2(kl[j5][0], kl[j5][1], sb + 2u * (O_KL + kr * ASTR + kk * 16 + b_off));
            }
            #pragma unroll
            for (int j5 = 0; j5 < 5; j5++)
                MMA16816(S[jc * 5 + j5], qhf, kh[j5]);
            #pragma unroll
            for (int j5 = 0; j5 < 5; j5++)
                MMA16816(S[jc * 5 + j5], qhf, kl[j5]);
            #pragma unroll
            for (int j5 = 0; j5 < 5; j5++)
                MMA16816(S[jc * 5 + j5], qlf, kh[j5]);
        }
    }

    // ---- mask + softmax ----
    const int g = lane >> 2, tg = lane & 3;
    const int qg = q0 + qrow0 + g;
    #pragma unroll
    for (int jj = 0; jj < 20; jj++) {
        int col = kbase + qrow0 + jj * 8 + 2 * tg;
        #pragma unroll
        for (int e = 0; e < 2; e++) {
            int c = col + e;
            bool okc = (c >= 0) && (c < S_LEN);
            int d0 = c - qg;
            if (!(okc && d0 >= -WIN && d0 <= WIN)) S[jj][e] = -1e30f;
            int d1 = d0 - 8;
            if (!(okc && d1 >= -WIN && d1 <= WIN)) S[jj][2 + e] = -1e30f;
        }
    }
    float m0 = -1e30f, m1 = -1e30f;
    #pragma unroll
    for (int jj = 0; jj < 20; jj++) {
        m0 = fmaxf(m0, fmaxf(S[jj][0], S[jj][1]));
        m1 = fmaxf(m1, fmaxf(S[jj][2], S[jj][3]));
    }
    m0 = fmaxf(m0, __shfl_xor_sync(0xffffffffu, m0, 1));
    m0 = fmaxf(m0, __shfl_xor_sync(0xffffffffu, m0, 2));
    m1 = fmaxf(m1, __shfl_xor_sync(0xffffffffu, m1, 1));
    m1 = fmaxf(m1, __shfl_xor_sync(0xffffffffu, m1, 2));
    float s0 = 0.f, s1 = 0.f;
    #pragma unroll
    for (int jj = 0; jj < 20; jj++) {
        S[jj][0] = __expf(S[jj][0] - m0); s0 += S[jj][0];
        S[jj][1] = __expf(S[jj][1] - m0); s0 += S[jj][1];
        S[jj][2] = __expf(S[jj][2] - m1); s1 += S[jj][2];
        S[jj][3] = __expf(S[jj][3] - m1); s1 += S[jj][3];
    }
    s0 += __shfl_xor_sync(0xffffffffu, s0, 1);
    s0 += __shfl_xor_sync(0xffffffffu, s0, 2);
    s1 += __shfl_xor_sync(0xffffffffu, s1, 1);
    s1 += __shfl_xor_sync(0xffffffffu, s1, 2);
    const float r0 = 1.0f / s0, r1 = 1.0f / s1;
    #pragma unroll
    for (int jj = 0; jj < 20; jj++) {
        S[jj][0] *= r0; S[jj][1] *= r0; S[jj][2] *= r1; S[jj][3] *= r1;
    }

    // ---- O = P V (3-term) ----
    float O[8][4];
    #pragma unroll
    for (int ni = 0; ni < 8; ni++)
        O[ni][0] = O[ni][1] = O[ni][2] = O[ni][3] = 0.f;

    const int vrow = lane & 15;
    #pragma unroll
    for (int kt = 0; kt < 10; kt++) {
        const float* sA = S[2 * kt];
        const float* sB = S[2 * kt + 1];
        uint32_t ph[4], pl[4];
        ph[0] = pack_hi2(sA[0], sA[1]); pl[0] = pack_lo2(sA[0], sA[1]);
        ph[1] = pack_hi2(sA[2], sA[3]); pl[1] = pack_lo2(sA[2], sA[3]);
        ph[2] = pack_hi2(sB[0], sB[1]); pl[2] = pack_lo2(sB[0], sB[1]);
        ph[3] = pack_hi2(sB[2], sB[3]); pl[3] = pack_lo2(sB[2], sB[3]);
        const int vr = qrow0 + kt * 16 + vrow;
        #pragma unroll
        for (int nc = 0; nc < 2; nc++) {
            uint32_t vh[4][2], vl[4][2];
            #pragma unroll
            for (int n4 = 0; n4 < 4; n4++) {
                int ni = nc * 4 + n4;
                LDMX2T(vh[n4][0], vh[n4][1], sb + 2u * (O_VH + vr * ASTR + ni * 8));
                LDMX2T(vl[n4][0], vl[n4][1], sb + 2u * (O_VL + vr * ASTR + ni * 8));
            }
            #pragma unroll
            for (int n4 = 0; n4 < 4; n4++)
                MMA16816(O[nc * 4 + n4], ph, vh[n4]);
            #pragma unroll
            for (int n4 = 0; n4 < 4; n4++)
                MMA16816(O[nc * 4 + n4], ph, vl[n4]);
            #pragma unroll
            for (int n4 = 0; n4 < 4; n4++)
                MMA16816(O[nc * 4 + n4], pl, vh[n4]);
        }
    }

    // ---- store O as bf16 hi/lo (feeds out-projection directly) ----
    #pragma unroll
    for (int ni = 0; ni < 8; ni++) {
        const int col = koff + ni * 8 + 2 * tg;
        size_t i0 = (tok_base + qg) * HIDDEN + col;
        size_t i1 = (tok_base + qg + 8) * HIDDEN + col;
        *(uint32_t*)&out_h[i0] = pack_hi2(O[ni][0], O[ni][1]);
        *(uint32_t*)&out_l[i0] = pack_lo2(O[ni][0], O[ni][1]);
        *(uint32_t*)&out_h[i1] = pack_hi2(O[ni][2], O[ni][3]);
        *(uint32_t*)&out_l[i1] = pack_lo2(O[ni][2], O[ni][3]);
    }
}

// ---------------------------------------------------------------------------
// Launch
// ---------------------------------------------------------------------------
extern "C" void kernel_launch(void* const* d_in, const int* in_sizes, int n_in,
                              void* d_out, int out_size)
{
    const float* hidden = nullptr;
    const float* wqkv = nullptr;
    const float* wo = nullptr;
    for (int i = 0; i < n_in; i++) {
        if (in_sizes[i] == NTOK * HIDDEN)            hidden = (const float*)d_in[i];
        else if (in_sizes[i] == QKV_N * HIDDEN)      wqkv   = (const float*)d_in[i];
        else if (in_sizes[i] == HIDDEN * HIDDEN)     wo     = (const float*)d_in[i];
    }

    __nv_bfloat16 *qh, *ql, *hh, *hl, *wqh, *wql, *woh, *wol, *ah, *al;
    float2* rope;
    cudaGetSymbolAddress((void**)&qh,  g_qh);
    cudaGetSymbolAddress((void**)&ql,  g_ql);
    cudaGetSymbolAddress((void**)&hh,  g_hh);
    cudaGetSymbolAddress((void**)&hl,  g_hl);
    cudaGetSymbolAddress((void**)&wqh, g_wqh);
    cudaGetSymbolAddress((void**)&wql, g_wql);
    cudaGetSymbolAddress((void**)&woh, g_woh);
    cudaGetSymbolAddress((void**)&wol, g_wol);
    cudaGetSymbolAddress((void**)&ah,  g_ah);
    cudaGetSymbolAddress((void**)&al,  g_al);
    cudaGetSymbolAddress((void**)&rope, g_rope);

    cudaFuncSetAttribute(gemm_bf16_kernel,
                         cudaFuncAttributeMaxDynamicSharedMemorySize, GSMEM);
    cudaFuncSetAttribute(attn_mma_kernel,
                         cudaFuncAttributeMaxDynamicSharedMemorySize, ATT_SMEM_BYTES);

    // 0) rope table + splits
    rope_table_kernel<<<(S_LEN * 32 + 255) / 256, 256>>>();
    {
        int n;
        n = NTOK * HIDDEN;
        split_bf16_kernel<<<(n / 4 + 255) / 256, 256>>>(hidden, hh, hl, n);
        n = QKV_N * HIDDEN;
        split_bf16_kernel<<<(n / 4 + 255) / 256, 256>>>(wqkv, wqh, wql, n);
        n = HIDDEN * HIDDEN;
        split_bf16_kernel<<<(n / 4 + 255) / 256, 256>>>(wo, woh, wol, n);
    }

    // 1) QKV projection (persistent HMMA) -> bf16 hi/lo qkv
    gemm_bf16_kernel<<<296, 128, GSMEM>>>(
        hh, hl, wqh, wql, nullptr, qh, ql,
        NTOK, QKV_N, HIDDEN, (NTOK / 128) * (QKV_N / 128));

    // 2) sliding-window attention (HMMA hi/lo, table RoPE) -> bf16 hi/lo
    attn_mma_kernel<<<B_SZ * NHEADS * (S_LEN / 128), 256, ATT_SMEM_BYTES>>>(
        qh, ql, rope, ah, al);

    // 3) output projection (persistent HMMA) -> fp32 d_out
    gemm_bf16_kernel<<<296, 128, GSMEM>>>(
        ah, al, woh, wol, (float*)d_out, nullptr, nullptr,
        NTOK, HIDDEN, HIDDEN, (NTOK / 128) * (HIDDEN / 128));
}

// round 12
// speedup vs baseline: 4.6860x; 1.3324x over previous
#include <cuda_runtime.h>
#include <cuda_fp16.h>
#include <math.h>
#include <stdint.h>

// Problem constants (fixed by setup_inputs)
#define B_SZ    8
#define S_LEN   1024
#define NHEADS  16
#define HDIM    64
#define HIDDEN  1024
#define WIN     64
#define NTOK    (B_SZ * S_LEN)          // 8192
#define QKV_N   (3 * HIDDEN)            // 3072

// ---------------------------------------------------------------------------
// Scratch (device globals — no allocation allowed in kernel_launch)
// ---------------------------------------------------------------------------
__device__ __half g_qh[(size_t)NTOK * QKV_N];   // 48 MB: qkv hi
__device__ __half g_ql[(size_t)NTOK * QKV_N];   // 48 MB: qkv lo

__device__ __half g_hh[(size_t)NTOK * HIDDEN];
__device__ __half g_hl[(size_t)NTOK * HIDDEN];
__device__ __half g_wqh[(size_t)QKV_N * HIDDEN];
__device__ __half g_woh[(size_t)HIDDEN * HIDDEN];
__device__ __half g_ah[(size_t)NTOK * HIDDEN];
__device__ __half g_al[(size_t)NTOK * HIDDEN];

__device__ float2 g_rope[S_LEN * 32];   // (cos, sin) per (t, d)

// ---------------------------------------------------------------------------
// rope table
// ---------------------------------------------------------------------------
__global__ void rope_table_kernel()
{
    int idx = blockIdx.x * blockDim.x + threadIdx.x;
    if (idx >= S_LEN * 32) return;
    int t = idx >> 5, d = idx & 31;
    float inv = powf(10000.0f, -(float)d * (1.0f / 32.0f));
    float sn, cs;
    sincosf((float)t * inv, &sn, &cs);
    g_rope[idx] = make_float2(cs, sn);
}

// ---------------------------------------------------------------------------
// fp32 -> fp16 hi/lo split (lo may be null -> hi-only convert)
// ---------------------------------------------------------------------------
__global__ void split_f16_kernel(const float* __restrict__ x,
                                 __half* __restrict__ hi,
                                 __half* __restrict__ lo, int n)
{
    int i = (blockIdx.x * blockDim.x + threadIdx.x) * 4;
    if (i >= n) return;
    float4 v = *(const float4*)(x + i);
    __half h0 = __float2half(v.x);
    __half h1 = __float2half(v.y);
    __half h2 = __float2half(v.z);
    __half h3 = __float2half(v.w);
    *(__half2*)(hi + i)     = __halves2half2(h0, h1);
    *(__half2*)(hi + i + 2) = __halves2half2(h2, h3);
    if (lo) {
        *(__half2*)(lo + i) = __halves2half2(
            __float2half(v.x - __half2float(h0)),
            __float2half(v.y - __half2float(h1)));
        *(__half2*)(lo + i + 2) = __halves2half2(
            __float2half(v.z - __half2float(h2)),
            __float2half(v.w - __half2float(h3)));
    }
}

// ---------------------------------------------------------------------------
// PTX helpers
// ---------------------------------------------------------------------------
__device__ __forceinline__ uint32_t smem_u32(const void* p) {
    uint32_t a;
    asm("{ .reg .u64 t; cvta.to.shared.u64 t, %1; cvt.u32.u64 %0, t; }"
        : "=r"(a) : "l"(p));
    return a;
}

#define CP_ASYNC16(dst, src) \
    asm volatile("cp.async.cg.shared.global [%0], [%1], 16;" \
                 :: "r"(dst), "l"(src) : "memory")
#define CP_COMMIT()  asm volatile("cp.async.commit_group;" ::: "memory")
#define CP_WAIT0()   asm volatile("cp.async.wait_group 0;" ::: "memory")

#define LDMX4(r0, r1, r2, r3, a) \
    asm volatile("ldmatrix.sync.aligned.m8n8.x4.shared.b16 {%0,%1,%2,%3}, [%4];" \
                 : "=r"(r0), "=r"(r1), "=r"(r2), "=r"(r3) : "r"(a))

#define LDMX2(r0, r1, a) \
    asm volatile("ldmatrix.sync.aligned.m8n8.x2.shared.b16 {%0,%1}, [%2];" \
                 : "=r"(r0), "=r"(r1) : "r"(a))

#define LDMX2T(r0, r1, a) \
    asm volatile("ldmatrix.sync.aligned.m8n8.x2.trans.shared.b16 {%0,%1}, [%2];" \
                 : "=r"(r0), "=r"(r1) : "r"(a))

// fp16 inputs, fp32 accumulate
#define MMA16816H(d, a, b) \
    asm volatile("mma.sync.aligned.m16n8k16.row.col.f32.f16.f16.f32 " \
                 "{%0,%1,%2,%3}, {%4,%5,%6,%7}, {%8,%9}, {%0,%1,%2,%3};" \
                 : "+f"((d)[0]), "+f"((d)[1]), "+f"((d)[2]), "+f"((d)[3]) \
                 : "r"((a)[0]), "r"((a)[1]), "r"((a)[2]), "r"((a)[3]), \
                   "r"((b)[0]), "r"((b)[1]))

__device__ __forceinline__ uint32_t pack_hi2(float x, float y) {
    __half2 p = __halves2half2(__float2half(x), __float2half(y));
    return *(uint32_t*)&p;
}
__device__ __forceinline__ uint32_t pack_lo2(float x, float y) {
    float hx = __half2float(__float2half(x));
    float hy = __half2float(__float2half(y));
    __half2 p = __halves2half2(__float2half(x - hx), __float2half(y - hy));
    return *(uint32_t*)&p;
}

// ---------------------------------------------------------------------------
// fp16 2-term GEMM via mma.sync: C = (Ah+Al) @ Bh^T   (B rounded to fp16)
// Persistent CTAs, 4 warps of 64x64, 3 staged tiles (Ah, Al, Bh).
// If Chi != nullptr, write fp16 hi/lo split output; else fp32 C.
// ---------------------------------------------------------------------------
#define KC        32
#define TSTRIDE   40
#define TILE_B    (128 * TSTRIDE * 2)   // 10240 B
#define BUF_B     (3 * TILE_B)          // Ah, Al, Bh
#define GSMEM     (2 * BUF_B)           // 61440 B

__global__ __launch_bounds__(128, 2) void gemm_f16_kernel(
    const __half* __restrict__ Ah, const __half* __restrict__ Al,
    const __half* __restrict__ Bh,
    float* __restrict__ C,
    __half* __restrict__ Chi, __half* __restrict__ Clo,
    int M, int N, int K, int ntiles)
{
    extern __shared__ char smem[];
    const uint32_t sbase = smem_u32(smem);

    const int tid  = threadIdx.x;
    const int wid  = tid >> 5;
    const int lane = tid & 31;
    const int m0 = (wid & 1) * 64;
    const int n0 = (wid >> 1) * 64;
    const int nb = N >> 7;

    const int quad = lane >> 3, lrow = lane & 7;
    const int a_off = ((quad & 1) * 8 + lrow) * TSTRIDE + (quad >> 1) * 8;
    const int b_off = ((quad >> 1) * 8 + lrow) * TSTRIDE + (quad & 1) * 8;
    const int g = lane >> 2, tg = lane & 3;
    const int NCH = K / KC;

    for (int tile = blockIdx.x; tile < ntiles; tile += gridDim.x) {
        const int bm = (tile / nb) * 128;
        const int bn = (tile % nb) * 128;
        const __half* srcs[3] = { Ah, Al, Bh };
        const int r0s[3] = { bm, bm, bn };

        auto stage_async = [&](int buf, int ch) {
            #pragma unroll
            for (int t = 0; t < 3; t++) {
                const __half* s = srcs[t] + (size_t)r0s[t] * K + ch * KC;
                uint32_t db = sbase + buf * BUF_B + t * TILE_B;
                #pragma unroll
                for (int i = 0; i < 4; i++) {
                    int u = tid + 128 * i;          // 0..511
                    int row = u >> 2, c16 = u & 3;
                    CP_ASYNC16(db + row * (TSTRIDE * 2) + c16 * 16,
                               s + (size_t)row * K + c16 * 8);
                }
            }
        };

        float acc[4][8][4] = {};

        stage_async(0, 0);
        CP_COMMIT();

        for (int c = 0; c < NCH; c++) {
            const int buf = c & 1;
            CP_WAIT0();
            __syncthreads();
            if (c + 1 < NCH) { stage_async((c + 1) & 1, c + 1); CP_COMMIT(); }

            const uint32_t base = sbase + buf * BUF_B;
            #pragma unroll
            for (int kk = 0; kk < 2; kk++) {
                uint32_t ah[4][4], al[4][4], bh[8][2];
                #pragma unroll
                for (int mi = 0; mi < 4; mi++) {
                    uint32_t ea = ((m0 + mi * 16) * TSTRIDE + kk * 16 + a_off) * 2;
                    LDMX4(ah[mi][0], ah[mi][1], ah[mi][2], ah[mi][3], base + ea);
                    LDMX4(al[mi][0], al[mi][1], al[mi][2], al[mi][3], base + TILE_B + ea);
                }
                #pragma unroll
                for (int np = 0; np < 4; np++) {
                    uint32_t eb = ((n0 + np * 16) * TSTRIDE + kk * 16 + b_off) * 2;
                    LDMX4(bh[2*np][0], bh[2*np][1], bh[2*np+1][0], bh[2*np+1][1],
                          base + 2 * TILE_B + eb);
                }
                #pragma unroll
                for (int mi = 0; mi < 4; mi++)
                    #pragma unroll
                    for (int ni = 0; ni < 8; ni++)
                        MMA16816H(acc[mi][ni], ah[mi], bh[ni]);
                #pragma unroll
                for (int mi = 0; mi < 4; mi++)
                    #pragma unroll
                    for (int ni = 0; ni < 8; ni++)
                        MMA16816H(acc[mi][ni], al[mi], bh[ni]);
            }
            __syncthreads();
        }

        if (Chi) {
            #pragma unroll
            for (int mi = 0; mi < 4; mi++) {
                #pragma unroll
                for (int ni = 0; ni < 8; ni++) {
                    const int col = bn + n0 + ni * 8 + tg * 2;
                    size_t i0 = (size_t)(bm + m0 + mi * 16 + g) * N + col;
                    size_t i1 = i0 + 8 * (size_t)N;
                    *(uint32_t*)&Chi[i0] = pack_hi2(acc[mi][ni][0], acc[mi][ni][1]);
                    *(uint32_t*)&Clo[i0] = pack_lo2(acc[mi][ni][0], acc[mi][ni][1]);
                    *(uint32_t*)&Chi[i1] = pack_hi2(acc[mi][ni][2], acc[mi][ni][3]);
                    *(uint32_t*)&Clo[i1] = pack_lo2(acc[mi][ni][2], acc[mi][ni][3]);
                }
            }
        } else {
            #pragma unroll
            for (int mi = 0; mi < 4; mi++) {
                const int row = bm + m0 + mi * 16 + g;
                #pragma unroll
                for (int ni = 0; ni < 8; ni++) {
                    const int col = bn + n0 + ni * 8 + tg * 2;
                    *(float2*)&C[(size_t)row * N + col] =
                        make_float2(acc[mi][ni][0], acc[mi][ni][1]);
                    *(float2*)&C[(size_t)(row + 8) * N + col] =
                        make_float2(acc[mi][ni][2], acc[mi][ni][3]);
                }
            }
        }
        __syncthreads();
    }
}

// ---------------------------------------------------------------------------
// Sliding-window attention via fp16 HMMA, 2-term:
//   S = (Qh+Ql)·Kh^T    (K rounded to fp16)
//   O = (Ph+Pl)·Vh      (V rounded to fp16)
// smem: Qh, Ql (128 rows) + Kh, Vh (272 rows), stride 72.
// ---------------------------------------------------------------------------
#define ASTR   72
#define O_QH   0
#define O_QL   (128 * ASTR)
#define O_KH   (2 * 128 * ASTR)
#define O_VH   (O_KH + 272 * ASTR)
#define ATT_SMEM_BYTES ((O_VH + 272 * ASTR) * 2)   // 115200

__global__ __launch_bounds__(256, 1) void attn_mma_kernel(
    const __half* __restrict__ qh, const __half* __restrict__ ql,
    const float2* __restrict__ rope,
    __half* __restrict__ out_h, __half* __restrict__ out_l)
{
    extern __shared__ __half smb[];
    const uint32_t sb = smem_u32(smb);

    const int bx = blockIdx.x;          // qt + 8*(h + 16*b)
    const int qt = bx & 7;
    const int h  = (bx >> 3) & 15;
    const int b  = bx >> 7;
    const int q0 = qt * 128;
    const int kbase = q0 - 64;
    const size_t tok_base = (size_t)b * S_LEN;
    const int koff = h * HDIM;

    const int tid = threadIdx.x;

    auto load4 = [&](const __half* ph, const __half* pl, float* v) {
        __half2 h01 = *(const __half2*)(ph);
        __half2 h23 = *(const __half2*)(ph + 2);
        __half2 l01 = *(const __half2*)(pl);
        __half2 l23 = *(const __half2*)(pl + 2);
        v[0] = __half2float(h01.x) + __half2float(l01.x);
        v[1] = __half2float(h01.y) + __half2float(l01.y);
        v[2] = __half2float(h23.x) + __half2float(l23.x);
        v[3] = __half2float(h23.y) + __half2float(l23.y);
    };

    // ---- stage Q with table RoPE (scaled by 1/8), split hi/lo ----
    for (int idx = tid; idx < 128 * 8; idx += 256) {
        int row = idx >> 3, c4 = (idx & 7) << 2;
        size_t off = (tok_base + q0 + row) * QKV_N + koff;
        float a1[4], a2[4];
        load4(qh + off + c4,      ql + off + c4,      a1);
        load4(qh + off + 32 + c4, ql + off + 32 + c4, a2);
        const float2* rp = rope + (q0 + row) * 32 + c4;
        float r1[4], r2[4];
        #pragma unroll
        for (int j = 0; j < 4; j++) {
            float2 cs = rp[j];
            r1[j] = (a1[j] * cs.x - a2[j] * cs.y) * 0.125f;
            r2[j] = (a2[j] * cs.x + a1[j] * cs.y) * 0.125f;
        }
        int e = row * ASTR + c4;
        *(uint32_t*)&smb[O_QH + e]      = pack_hi2(r1[0], r1[1]);
        *(uint32_t*)&smb[O_QH + e + 2]  = pack_hi2(r1[2], r1[3]);
        *(uint32_t*)&smb[O_QL + e]      = pack_lo2(r1[0], r1[1]);
        *(uint32_t*)&smb[O_QL + e + 2]  = pack_lo2(r1[2], r1[3]);
        *(uint32_t*)&smb[O_QH + e + 32] = pack_hi2(r2[0], r2[1]);
        *(uint32_t*)&smb[O_QH + e + 34] = pack_hi2(r2[2], r2[3]);
        *(uint32_t*)&smb[O_QL + e + 32] = pack_lo2(r2[0], r2[1]);
        *(uint32_t*)&smb[O_QL + e + 34] = pack_lo2(r2[2], r2[3]);
    }
    // ---- stage K with table RoPE (hi only; 272 rows, zero-fill OOB) ----
    for (int idx = tid; idx < 272 * 8; idx += 256) {
        int row = idx >> 3, c4 = (idx & 7) << 2;
        int kg = kbase + row;
        float r1[4] = {0.f, 0.f, 0.f, 0.f}, r2[4] = {0.f, 0.f, 0.f, 0.f};
        if (kg >= 0 && kg < S_LEN) {
            size_t off = (tok_base + kg) * QKV_N + HIDDEN + koff;
            float a1[4], a2[4];
            load4(qh + off + c4,      ql + off + c4,      a1);
            load4(qh + off + 32 + c4, ql + off + 32 + c4, a2);
            const float2* rp = rope + kg * 32 + c4;
            #pragma unroll
            for (int j = 0; j < 4; j++) {
                float2 cs = rp[j];
                r1[j] = a1[j] * cs.x - a2[j] * cs.y;
                r2[j] = a2[j] * cs.x + a1[j] * cs.y;
            }
        }
        int e = row * ASTR + c4;
        *(uint32_t*)&smb[O_KH + e]      = pack_hi2(r1[0], r1[1]);
        *(uint32_t*)&smb[O_KH + e + 2]  = pack_hi2(r1[2], r1[3]);
        *(uint32_t*)&smb[O_KH + e + 32] = pack_hi2(r2[0], r2[1]);
        *(uint32_t*)&smb[O_KH + e + 34] = pack_hi2(r2[2], r2[3]);
    }
    // ---- stage V: pure fp16 hi copy ----
    for (int idx = tid; idx < 272 * 8; idx += 256) {
        int row = idx >> 3, c8 = (idx & 7) << 3;
        int kg = kbase + row;
        uint4 vh = make_uint4(0, 0, 0, 0);
        if (kg >= 0 && kg < S_LEN)
            vh = *(const uint4*)(qh + (tok_base + kg) * QKV_N + 2 * HIDDEN + koff + c8);
        *(uint4*)&smb[O_VH + row * ASTR + c8] = vh;
    }
    __syncthreads();

    // ---- per-warp compute ----
    const int w = tid >> 5, lane = tid & 31;
    const int quad = lane >> 3, lrow = lane & 7;
    const int a_off = ((quad & 1) * 8 + lrow) * ASTR + (quad >> 1) * 8;
    const int b_off = lrow * ASTR + (quad & 1) * 8;
    const int qrow0 = 16 * w;

    float S[20][4];
    #pragma unroll
    for (int jj = 0; jj < 20; jj++)
        S[jj][0] = S[jj][1] = S[jj][2] = S[jj][3] = 0.f;

    #pragma unroll
    for (int kk = 0; kk < 4; kk++) {
        uint32_t qhf[4], qlf[4];
        uint32_t ea = sb + 2u * (O_QH + qrow0 * ASTR + kk * 16 + a_off);
        uint32_t el = sb + 2u * (O_QL + qrow0 * ASTR + kk * 16 + a_off);
        LDMX4(qhf[0], qhf[1], qhf[2], qhf[3], ea);
        LDMX4(qlf[0], qlf[1], qlf[2], qlf[3], el);
        #pragma unroll
        for (int jc = 0; jc < 4; jc++) {
            uint32_t kh[5][2];
            #pragma unroll
            for (int j5 = 0; j5 < 5; j5++) {
                int kr = qrow0 + (jc * 5 + j5) * 8;
                LDMX2(kh[j5][0], kh[j5][1], sb + 2u * (O_KH + kr * ASTR + kk * 16 + b_off));
            }
            #pragma unroll
            for (int j5 = 0; j5 < 5; j5++)
                MMA16816H(S[jc * 5 + j5], qhf, kh[j5]);
            #pragma unroll
            for (int j5 = 0; j5 < 5; j5++)
                MMA16816H(S[jc * 5 + j5], qlf, kh[j5]);
        }
    }

    // ---- mask + softmax ----
    const int g = lane >> 2, tg = lane & 3;
    const int qg = q0 + qrow0 + g;
    #pragma unroll
    for (int jj = 0; jj < 20; jj++) {
        int col = kbase + qrow0 + jj * 8 + 2 * tg;
        #pragma unroll
        for (int e = 0; e < 2; e++) {
            int c = col + e;
            bool okc = (c >= 0) && (c < S_LEN);
            int d0 = c - qg;
            if (!(okc && d0 >= -WIN && d0 <= WIN)) S[jj][e] = -1e30f;
            int d1 = d0 - 8;
            if (!(okc && d1 >= -WIN && d1 <= WIN)) S[jj][2 + e] = -1e30f;
        }
    }
    float m0 = -1e30f, m1 = -1e30f;
    #pragma unroll
    for (int jj = 0; jj < 20; jj++) {
        m0 = fmaxf(m0, fmaxf(S[jj][0], S[jj][1]));
        m1 = fmaxf(m1, fmaxf(S[jj][2], S[jj][3]));
    }
    m0 = fmaxf(m0, __shfl_xor_sync(0xffffffffu, m0, 1));
    m0 = fmaxf(m0, __shfl_xor_sync(0xffffffffu, m0, 2));
    m1 = fmaxf(m1, __shfl_xor_sync(0xffffffffu, m1, 1));
    m1 = fmaxf(m1, __shfl_xor_sync(0xffffffffu, m1, 2));
    float s0 = 0.f, s1 = 0.f;
    #pragma unroll
    for (int jj = 0; jj < 20; jj++) {
        S[jj][0] = __expf(S[jj][0] - m0); s0 += S[jj][0];
        S[jj][1] = __expf(S[jj][1] - m0); s0 += S[jj][1];
        S[jj][2] = __expf(S[jj][2] - m1); s1 += S[jj][2];
        S[jj][3] = __expf(S[jj][3] - m1); s1 += S[jj][3];
    }
    s0 += __shfl_xor_sync(0xffffffffu, s0, 1);
    s0 += __shfl_xor_sync(0xffffffffu, s0, 2);
    s1 += __shfl_xor_sync(0xffffffffu, s1, 1);
    s1 += __shfl_xor_sync(0xffffffffu, s1, 2);
    const float r0 = 1.0f / s0, r1 = 1.0f / s1;
    #pragma unroll
    for (int jj = 0; jj < 20; jj++) {
        S[jj][0] *= r0; S[jj][1] *= r0; S[jj][2] *= r1; S[jj][3] *= r1;
    }

    // ---- O = (Ph+Pl) Vh ----
    float O[8][4];
    #pragma unroll
    for (int ni = 0; ni < 8; ni++)
        O[ni][0] = O[ni][1] = O[ni][2] = O[ni][3] = 0.f;

    const int vrow = lane & 15;
    #pragma unroll
    for (int kt = 0; kt < 10; kt++) {
        const float* sA = S[2 * kt];
        const float* sB = S[2 * kt + 1];
        uint32_t ph[4], pl[4];
        ph[0] = pack_hi2(sA[0], sA[1]); pl[0] = pack_lo2(sA[0], sA[1]);
        ph[1] = pack_hi2(sA[2], sA[3]); pl[1] = pack_lo2(sA[2], sA[3]);
        ph[2] = pack_hi2(sB[0], sB[1]); pl[2] = pack_lo2(sB[0], sB[1]);
        ph[3] = pack_hi2(sB[2], sB[3]); pl[3] = pack_lo2(sB[2], sB[3]);
        const int vr = qrow0 + kt * 16 + vrow;
        #pragma unroll
        for (int nc = 0; nc < 2; nc++) {
            uint32_t vh[4][2];
            #pragma unroll
            for (int n4 = 0; n4 < 4; n4++) {
                int ni = nc * 4 + n4;
                LDMX2T(vh[n4][0], vh[n4][1], sb + 2u * (O_VH + vr * ASTR + ni * 8));
            }
            #pragma unroll
            for (int n4 = 0; n4 < 4; n4++)
                MMA16816H(O[nc * 4 + n4], ph, vh[n4]);
            #pragma unroll
            for (int n4 = 0; n4 < 4; n4++)
                MMA16816H(O[nc * 4 + n4], pl, vh[n4]);
        }
    }

    // ---- store O as fp16 hi/lo (feeds out-projection directly) ----
    #pragma unroll
    for (int ni = 0; ni < 8; ni++) {
        const int col = koff + ni * 8 + 2 * tg;
        size_t i0 = (tok_base + qg) * HIDDEN + col;
        size_t i1 = (tok_base + qg + 8) * HIDDEN + col;
        *(uint32_t*)&out_h[i0] = pack_hi2(O[ni][0], O[ni][1]);
        *(uint32_t*)&out_l[i0] = pack_lo2(O[ni][0], O[ni][1]);
        *(uint32_t*)&out_h[i1] = pack_hi2(O[ni][2], O[ni][3]);
        *(uint32_t*)&out_l[i1] = pack_lo2(O[ni][2], O[ni][3]);
    }
}

// ---------------------------------------------------------------------------
// Launch
// ---------------------------------------------------------------------------
extern "C" void kernel_launch(void* const* d_in, const int* in_sizes, int n_in,
                              void* d_out, int out_size)
{
    const float* hidden = nullptr;
    const float* wqkv = nullptr;
    const float* wo = nullptr;
    for (int i = 0; i < n_in; i++) {
        if (in_sizes[i] == NTOK * HIDDEN)            hidden = (const float*)d_in[i];
        else if (in_sizes[i] == QKV_N * HIDDEN)      wqkv   = (const float*)d_in[i];
        else if (in_sizes[i] == HIDDEN * HIDDEN)     wo     = (const float*)d_in[i];
    }

    __half *qh, *ql, *hh, *hl, *wqh, *woh, *ah, *al;
    float2* rope;
    cudaGetSymbolAddress((void**)&qh,  g_qh);
    cudaGetSymbolAddress((void**)&ql,  g_ql);
    cudaGetSymbolAddress((void**)&hh,  g_hh);
    cudaGetSymbolAddress((void**)&hl,  g_hl);
    cudaGetSymbolAddress((void**)&wqh, g_wqh);
    cudaGetSymbolAddress((void**)&woh, g_woh);
    cudaGetSymbolAddress((void**)&ah,  g_ah);
    cudaGetSymbolAddress((void**)&al,  g_al);
    cudaGetSymbolAddress((void**)&rope, g_rope);

    cudaFuncSetAttribute(gemm_f16_kernel,
                         cudaFuncAttributeMaxDynamicSharedMemorySize, GSMEM);
    cudaFuncSetAttribute(attn_mma_kernel,
                         cudaFuncAttributeMaxDynamicSharedMemorySize, ATT_SMEM_BYTES);

    // 0) rope table + splits (weights: hi only)
    rope_table_kernel<<<(S_LEN * 32 + 255) / 256, 256>>>();
    {
        int n;
        n = NTOK * HIDDEN;
        split_f16_kernel<<<(n / 4 + 255) / 256, 256>>>(hidden, hh, hl, n);
        n = QKV_N * HIDDEN;
        split_f16_kernel<<<(n / 4 + 255) / 256, 256>>>(wqkv, wqh, nullptr, n);
        n = HIDDEN * HIDDEN;
        split_f16_kernel<<<(n / 4 + 255) / 256, 256>>>(wo, woh, nullptr, n);
    }

    // 1) QKV projection (persistent fp16 HMMA, 2-term) -> fp16 hi/lo qkv
    gemm_f16_kernel<<<296, 128, GSMEM>>>(
        hh, hl, wqh, nullptr, qh, ql,
        NTOK, QKV_N, HIDDEN, (NTOK / 128) * (QKV_N / 128));

    // 2) sliding-window attention (fp16 HMMA 2-term, table RoPE)
    attn_mma_kernel<<<B_SZ * NHEADS * (S_LEN / 128), 256, ATT_SMEM_BYTES>>>(
        qh, ql, rope, ah, al);

    // 3) output projection (persistent fp16 HMMA, 2-term) -> fp32 d_out
    gemm_f16_kernel<<<296, 128, GSMEM>>>(
        ah, al, woh, (float*)d_out, nullptr, nullptr,
        NTOK, HIDDEN, HIDDEN, (NTOK / 128) * (HIDDEN / 128));
}

// round 15
// speedup vs baseline: 4.7172x; 1.0067x over previous
#include <cuda_runtime.h>
#include <cuda_fp16.h>
#include <math.h>
#include <stdint.h>

// Problem constants (fixed by setup_inputs)
#define B_SZ    8
#define S_LEN   1024
#define NHEADS  16
#define HDIM    64
#define HIDDEN  1024
#define WIN     64
#define NTOK    (B_SZ * S_LEN)          // 8192
#define QKV_N   (3 * HIDDEN)            // 3072

// ---------------------------------------------------------------------------
// Scratch (device globals — no allocation allowed in kernel_launch)
// ---------------------------------------------------------------------------
__device__ __half g_qh[(size_t)NTOK * QKV_N];   // 48 MB: qkv hi
__device__ __half g_ql[(size_t)NTOK * QKV_N];   // 48 MB: qkv lo

__device__ __half g_hh[(size_t)NTOK * HIDDEN];
__device__ __half g_hl[(size_t)NTOK * HIDDEN];
__device__ __half g_wqh[(size_t)QKV_N * HIDDEN];
__device__ __half g_woh[(size_t)HIDDEN * HIDDEN];
__device__ __half g_ah[(size_t)NTOK * HIDDEN];
__device__ __half g_al[(size_t)NTOK * HIDDEN];

__device__ float2 g_rope[S_LEN * 32];   // (cos, sin) per (t, d)

// ---------------------------------------------------------------------------
// rope table
// ---------------------------------------------------------------------------
__global__ void rope_table_kernel()
{
    int idx = blockIdx.x * blockDim.x + threadIdx.x;
    if (idx >= S_LEN * 32) return;
    int t = idx >> 5, d = idx & 31;
    float inv = powf(10000.0f, -(float)d * (1.0f / 32.0f));
    float sn, cs;
    sincosf((float)t * inv, &sn, &cs);
    g_rope[idx] = make_float2(cs, sn);
}

// ---------------------------------------------------------------------------
// fp32 -> fp16 hi/lo split (lo may be null -> hi-only convert)
// ---------------------------------------------------------------------------
__global__ void split_f16_kernel(const float* __restrict__ x,
                                 __half* __restrict__ hi,
                                 __half* __restrict__ lo, int n)
{
    int i = (blockIdx.x * blockDim.x + threadIdx.x) * 4;
    if (i >= n) return;
    float4 v = *(const float4*)(x + i);
    __half h0 = __float2half(v.x);
    __half h1 = __float2half(v.y);
    __half h2 = __float2half(v.z);
    __half h3 = __float2half(v.w);
    *(__half2*)(hi + i)     = __halves2half2(h0, h1);
    *(__half2*)(hi + i + 2) = __halves2half2(h2, h3);
    if (lo) {
        *(__half2*)(lo + i) = __halves2half2(
            __float2half(v.x - __half2float(h0)),
            __float2half(v.y - __half2float(h1)));
        *(__half2*)(lo + i + 2) = __halves2half2(
            __float2half(v.z - __half2float(h2)),
            __float2half(v.w - __half2float(h3)));
    }
}

// ---------------------------------------------------------------------------
// PTX helpers
// ---------------------------------------------------------------------------
__device__ __forceinline__ uint32_t smem_u32(const void* p) {
    uint32_t a;
    asm("{ .reg .u64 t; cvta.to.shared.u64 t, %1; cvt.u32.u64 %0, t; }"
        : "=r"(a) : "l"(p));
    return a;
}

#define CP_ASYNC16(dst, src) \
    asm volatile("cp.async.cg.shared.global [%0], [%1], 16;" \
                 :: "r"(dst), "l"(src) : "memory")
#define CP_COMMIT()  asm volatile("cp.async.commit_group;" ::: "memory")
#define CP_WAIT0()   asm volatile("cp.async.wait_group 0;" ::: "memory")

#define LDMX4(r0, r1, r2, r3, a) \
    asm volatile("ldmatrix.sync.aligned.m8n8.x4.shared.b16 {%0,%1,%2,%3}, [%4];" \
                 : "=r"(r0), "=r"(r1), "=r"(r2), "=r"(r3) : "r"(a))

#define LDMX2(r0, r1, a) \
    asm volatile("ldmatrix.sync.aligned.m8n8.x2.shared.b16 {%0,%1}, [%2];" \
                 : "=r"(r0), "=r"(r1) : "r"(a))

#define LDMX2T(r0, r1, a) \
    asm volatile("ldmatrix.sync.aligned.m8n8.x2.trans.shared.b16 {%0,%1}, [%2];" \
                 : "=r"(r0), "=r"(r1) : "r"(a))

// fp16 inputs, fp32 accumulate
#define MMA16816H(d, a, b) \
    asm volatile("mma.sync.aligned.m16n8k16.row.col.f32.f16.f16.f32 " \
                 "{%0,%1,%2,%3}, {%4,%5,%6,%7}, {%8,%9}, {%0,%1,%2,%3};" \
                 : "+f"((d)[0]), "+f"((d)[1]), "+f"((d)[2]), "+f"((d)[3]) \
                 : "r"((a)[0]), "r"((a)[1]), "r"((a)[2]), "r"((a)[3]), \
                   "r"((b)[0]), "r"((b)[1]))

// fp16 inputs, fp16 accumulate (correction terms only)
#define MMA16816HH(d, a, b) \
    asm volatile("mma.sync.aligned.m16n8k16.row.col.f16.f16.f16.f16 " \
                 "{%0,%1}, {%2,%3,%4,%5}, {%6,%7}, {%0,%1};" \
                 : "+r"((d)[0]), "+r"((d)[1]) \
                 : "r"((a)[0]), "r"((a)[1]), "r"((a)[2]), "r"((a)[3]), \
                   "r"((b)[0]), "r"((b)[1]))

__device__ __forceinline__ uint32_t pack_hi2(float x, float y) {
    __half2 p = __halves2half2(__float2half(x), __float2half(y));
    return *(uint32_t*)&p;
}
__device__ __forceinline__ uint32_t pack_lo2(float x, float y) {
    float hx = __half2float(__float2half(x));
    float hy = __half2float(__float2half(y));
    __half2 p = __halves2half2(__float2half(x - hx), __float2half(y - hy));
    return *(uint32_t*)&p;
}

// ---------------------------------------------------------------------------
// fp16 2-term GEMM via mma.sync: C = (Ah+Al) @ Bh^T
// Main term fp32-acc; correction term Al·Bh in fp16-acc (2x rate if HW
// supports; correction magnitude ~2^-11 of main so fp16 acc error ~1e-6).
// Persistent CTAs, 4 warps of 64x64, 3 staged tiles.
// ---------------------------------------------------------------------------
#define KC        32
#define TSTRIDE   40
#define TILE_B    (128 * TSTRIDE * 2)   // 10240 B
#define BUF_B     (3 * TILE_B)          // Ah, Al, Bh
#define GSMEM     (2 * BUF_B)           // 61440 B

__global__ __launch_bounds__(128, 2) void gemm_f16_kernel(
    const __half* __restrict__ Ah, const __half* __restrict__ Al,
    const __half* __restrict__ Bh,
    float* __restrict__ C,
    __half* __restrict__ Chi, __half* __restrict__ Clo,
    int M, int N, int K, int ntiles)
{
    extern __shared__ char smem[];
    const uint32_t sbase = smem_u32(smem);

    const int tid  = threadIdx.x;
    const int wid  = tid >> 5;
    const int lane = tid & 31;
    const int m0 = (wid & 1) * 64;
    const int n0 = (wid >> 1) * 64;
    const int nb = N >> 7;

    const int quad = lane >> 3, lrow = lane & 7;
    const int a_off = ((quad & 1) * 8 + lrow) * TSTRIDE + (quad >> 1) * 8;
    const int b_off = ((quad >> 1) * 8 + lrow) * TSTRIDE + (quad & 1) * 8;
    const int g = lane >> 2, tg = lane & 3;
    const int NCH = K / KC;

    for (int tile = blockIdx.x; tile < ntiles; tile += gridDim.x) {
        const int bm = (tile / nb) * 128;
        const int bn = (tile % nb) * 128;
        const __half* srcs[3] = { Ah, Al, Bh };
        const int r0s[3] = { bm, bm, bn };

        auto stage_async = [&](int buf, int ch) {
            #pragma unroll
            for (int t = 0; t < 3; t++) {
                const __half* s = srcs[t] + (size_t)r0s[t] * K + ch * KC;
                uint32_t db = sbase + buf * BUF_B + t * TILE_B;
                #pragma unroll
                for (int i = 0; i < 4; i++) {
                    int u = tid + 128 * i;          // 0..511
                    int row = u >> 2, c16 = u & 3;
                    CP_ASYNC16(db + row * (TSTRIDE * 2) + c16 * 16,
                               s + (size_t)row * K + c16 * 8);
                }
            }
        };

        float acc[4][8][4] = {};
        uint32_t acc16[4][8][2] = {};   // fp16 correction accumulators

        stage_async(0, 0);
        CP_COMMIT();

        for (int c = 0; c < NCH; c++) {
            const int buf = c & 1;
            CP_WAIT0();
            __syncthreads();
            if (c + 1 < NCH) { stage_async((c + 1) & 1, c + 1); CP_COMMIT(); }

            const uint32_t base = sbase + buf * BUF_B;
            #pragma unroll
            for (int kk = 0; kk < 2; kk++) {
                uint32_t ah[4][4], al[4][4], bh[8][2];
                #pragma unroll
                for (int mi = 0; mi < 4; mi++) {
                    uint32_t ea = ((m0 + mi * 16) * TSTRIDE + kk * 16 + a_off) * 2;
                    LDMX4(ah[mi][0], ah[mi][1], ah[mi][2], ah[mi][3], base + ea);
                    LDMX4(al[mi][0], al[mi][1], al[mi][2], al[mi][3], base + TILE_B + ea);
                }
                #pragma unroll
                for (int np = 0; np < 4; np++) {
                    uint32_t eb = ((n0 + np * 16) * TSTRIDE + kk * 16 + b_off) * 2;
                    LDMX4(bh[2*np][0], bh[2*np][1], bh[2*np+1][0], bh[2*np+1][1],
                          base + 2 * TILE_B + eb);
                }
                // main term: fp32 acc
                #pragma unroll
                for (int mi = 0; mi < 4; mi++)
                    #pragma unroll
                    for (int ni = 0; ni < 8; ni++)
                        MMA16816H(acc[mi][ni], ah[mi], bh[ni]);
                // correction term: fp16 acc
                #pragma unroll
                for (int mi = 0; mi < 4; mi++)
                    #pragma unroll
                    for (int ni = 0; ni < 8; ni++)
                        MMA16816HH(acc16[mi][ni], al[mi], bh[ni]);
            }
            __syncthreads();
        }

        // merge fp16 correction into fp32 acc
        #pragma unroll
        for (int mi = 0; mi < 4; mi++)
            #pragma unroll
            for (int ni = 0; ni < 8; ni++) {
                float2 c01 = __half22float2(*(__half2*)&acc16[mi][ni][0]);
                float2 c23 = __half22float2(*(__half2*)&acc16[mi][ni][1]);
                acc[mi][ni][0] += c01.x;
                acc[mi][ni][1] += c01.y;
                acc[mi][ni][2] += c23.x;
                acc[mi][ni][3] += c23.y;
            }

        if (Chi) {
            #pragma unroll
            for (int mi = 0; mi < 4; mi++) {
                #pragma unroll
                for (int ni = 0; ni < 8; ni++) {
                    const int col = bn + n0 + ni * 8 + tg * 2;
                    size_t i0 = (size_t)(bm + m0 + mi * 16 + g) * N + col;
                    size_t i1 = i0 + 8 * (size_t)N;
                    *(uint32_t*)&Chi[i0] = pack_hi2(acc[mi][ni][0], acc[mi][ni][1]);
                    *(uint32_t*)&Clo[i0] = pack_lo2(acc[mi][ni][0], acc[mi][ni][1]);
                    *(uint32_t*)&Chi[i1] = pack_hi2(acc[mi][ni][2], acc[mi][ni][3]);
                    *(uint32_t*)&Clo[i1] = pack_lo2(acc[mi][ni][2], acc[mi][ni][3]);
                }
            }
        } else {
            #pragma unroll
            for (int mi = 0; mi < 4; mi++) {
                const int row = bm + m0 + mi * 16 + g;
                #pragma unroll
                for (int ni = 0; ni < 8; ni++) {
                    const int col = bn + n0 + ni * 8 + tg * 2;
                    *(float2*)&C[(size_t)row * N + col] =
                        make_float2(acc[mi][ni][0], acc[mi][ni][1]);
                    *(float2*)&C[(size_t)(row + 8) * N + col] =
                        make_float2(acc[mi][ni][2], acc[mi][ni][3]);
                }
            }
        }
        __syncthreads();
    }
}

// ---------------------------------------------------------------------------
// Sliding-window attention via fp16 HMMA, 2-term.
// CHANGE vs R12: exact trim — j-tiles 20->18 (valid key span per warp is
// [16w, 16w+144)), PV kt 10->9, K/V staging rows 272->256.
// ---------------------------------------------------------------------------
#define ASTR   72
#define KROWS  256
#define O_QH   0
#define O_QL   (128 * ASTR)
#define O_KH   (2 * 128 * ASTR)
#define O_VH   (O_KH + KROWS * ASTR)
#define ATT_SMEM_BYTES ((O_VH + KROWS * ASTR) * 2)   // 110592

__global__ __launch_bounds__(256, 1) void attn_mma_kernel(
    const __half* __restrict__ qh, const __half* __restrict__ ql,
    const float2* __restrict__ rope,
    __half* __restrict__ out_h, __half* __restrict__ out_l)
{
    extern __shared__ __half smb[];
    const uint32_t sb = smem_u32(smb);

    const int bx = blockIdx.x;          // qt + 8*(h + 16*b)
    const int qt = bx & 7;
    const int h  = (bx >> 3) & 15;
    const int b  = bx >> 7;
    const int q0 = qt * 128;
    const int kbase = q0 - 64;
    const size_t tok_base = (size_t)b * S_LEN;
    const int koff = h * HDIM;

    const int tid = threadIdx.x;

    auto load4 = [&](const __half* ph, const __half* pl, float* v) {
        __half2 h01 = *(const __half2*)(ph);
        __half2 h23 = *(const __half2*)(ph + 2);
        __half2 l01 = *(const __half2*)(pl);
        __half2 l23 = *(const __half2*)(pl + 2);
        v[0] = __half2float(h01.x) + __half2float(l01.x);
        v[1] = __half2float(h01.y) + __half2float(l01.y);
        v[2] = __half2float(h23.x) + __half2float(l23.x);
        v[3] = __half2float(h23.y) + __half2float(l23.y);
    };

    // ---- stage Q with table RoPE (scaled by 1/8), split hi/lo ----
    for (int idx = tid; idx < 128 * 8; idx += 256) {
        int row = idx >> 3, c4 = (idx & 7) << 2;
        size_t off = (tok_base + q0 + row) * QKV_N + koff;
        float a1[4], a2[4];
        load4(qh + off + c4,      ql + off + c4,      a1);
        load4(qh + off + 32 + c4, ql + off + 32 + c4, a2);
        const float2* rp = rope + (q0 + row) * 32 + c4;
        float r1[4], r2[4];
        #pragma unroll
        for (int j = 0; j < 4; j++) {
            float2 cs = rp[j];
            r1[j] = (a1[j] * cs.x - a2[j] * cs.y) * 0.125f;
            r2[j] = (a2[j] * cs.x + a1[j] * cs.y) * 0.125f;
        }
        int e = row * ASTR + c4;
        *(uint32_t*)&smb[O_QH + e]      = pack_hi2(r1[0], r1[1]);
        *(uint32_t*)&smb[O_QH + e + 2]  = pack_hi2(r1[2], r1[3]);
        *(uint32_t*)&smb[O_QL + e]      = pack_lo2(r1[0], r1[1]);
        *(uint32_t*)&smb[O_QL + e + 2]  = pack_lo2(r1[2], r1[3]);
        *(uint32_t*)&smb[O_QH + e + 32] = pack_hi2(r2[0], r2[1]);
        *(uint32_t*)&smb[O_QH + e + 34] = pack_hi2(r2[2], r2[3]);
        *(uint32_t*)&smb[O_QL + e + 32] = pack_lo2(r2[0], r2[1]);
        *(uint32_t*)&smb[O_QL + e + 34] = pack_lo2(r2[2], r2[3]);
    }
    // ---- stage K with table RoPE (hi only; KROWS rows, zero-fill OOB) ----
    for (int idx = tid; idx < KROWS * 8; idx += 256) {
        int row = idx >> 3, c4 = (idx & 7) << 2;
        int kg = kbase + row;
        float r1[4] = {0.f, 0.f, 0.f, 0.f}, r2[4] = {0.f, 0.f, 0.f, 0.f};
        if (kg >= 0 && kg < S_LEN) {
            size_t off = (tok_base + kg) * QKV_N + HIDDEN + koff;
            float a1[4], a2[4];
            load4(qh + off + c4,      ql + off + c4,      a1);
            load4(qh + off + 32 + c4, ql + off + 32 + c4, a2);
            const float2* rp = rope + kg * 32 + c4;
            #pragma unroll
            for (int j = 0; j < 4; j++) {
                float2 cs = rp[j];
                r1[j] = a1[j] * cs.x - a2[j] * cs.y;
                r2[j] = a2[j] * cs.x + a1[j] * cs.y;
            }
        }
        int e = row * ASTR + c4;
        *(uint32_t*)&smb[O_KH + e]      = pack_hi2(r1[0], r1[1]);
        *(uint32_t*)&smb[O_KH + e + 2]  = pack_hi2(r1[2], r1[3]);
        *(uint32_t*)&smb[O_KH + e + 32] = pack_hi2(r2[0], r2[1]);
        *(uint32_t*)&smb[O_KH + e + 34] = pack_hi2(r2[2], r2[3]);
    }
    // ---- stage V: pure fp16 hi copy ----
    for (int idx = tid; idx < KROWS * 8; idx += 256) {
        int row = idx >> 3, c8 = (idx & 7) << 3;
        int kg = kbase + row;
        uint4 vh = make_uint4(0, 0, 0, 0);
        if (kg >= 0 && kg < S_LEN)
            vh = *(const uint4*)(qh + (tok_base + kg) * QKV_N + 2 * HIDDEN + koff + c8);
        *(uint4*)&smb[O_VH + row * ASTR + c8] = vh;
    }
    __syncthreads();

    // ---- per-warp compute ----
    const int w = tid >> 5, lane = tid & 31;
    const int quad = lane >> 3, lrow = lane & 7;
    const int a_off = ((quad & 1) * 8 + lrow) * ASTR + (quad >> 1) * 8;
    const int b_off = lrow * ASTR + (quad & 1) * 8;
    const int qrow0 = 16 * w;

    float S[18][4];
    #pragma unroll
    for (int jj = 0; jj < 18; jj++)
        S[jj][0] = S[jj][1] = S[jj][2] = S[jj][3] = 0.f;

    #pragma unroll
    for (int kk = 0; kk < 4; kk++) {
        uint32_t qhf[4], qlf[4];
        uint32_t ea = sb + 2u * (O_QH + qrow0 * ASTR + kk * 16 + a_off);
        uint32_t el = sb + 2u * (O_QL + qrow0 * ASTR + kk * 16 + a_off);
        LDMX4(qhf[0], qhf[1], qhf[2], qhf[3], ea);
        LDMX4(qlf[0], qlf[1], qlf[2], qlf[3], el);
        #pragma unroll
        for (int jc = 0; jc < 3; jc++) {        // 3 chunks of 6 j-tiles
            uint32_t kh[6][2];
            #pragma unroll
            for (int j6 = 0; j6 < 6; j6++) {
                int kr = qrow0 + (jc * 6 + j6) * 8;
                LDMX2(kh[j6][0], kh[j6][1], sb + 2u * (O_KH + kr * ASTR + kk * 16 + b_off));
            }
            #pragma unroll
            for (int j6 = 0; j6 < 6; j6++)
                MMA16816H(S[jc * 6 + j6], qhf, kh[j6]);
            #pragma unroll
            for (int j6 = 0; j6 < 6; j6++)
                MMA16816H(S[jc * 6 + j6], qlf, kh[j6]);
        }
    }

    // ---- mask + softmax ----
    const int g = lane >> 2, tg = lane & 3;
    const int qg = q0 + qrow0 + g;
    #pragma unroll
    for (int jj = 0; jj < 18; jj++) {
        int col = kbase + qrow0 + jj * 8 + 2 * tg;
        #pragma unroll
        for (int e = 0; e < 2; e++) {
            int c = col + e;
            bool okc = (c >= 0) && (c < S_LEN);
            int d0 = c - qg;
            if (!(okc && d0 >= -WIN && d0 <= WIN)) S[jj][e] = -1e30f;
            int d1 = d0 - 8;
            if (!(okc && d1 >= -WIN && d1 <= WIN)) S[jj][2 + e] = -1e30f;
        }
    }
    float m0 = -1e30f, m1 = -1e30f;
    #pragma unroll
    for (int jj = 0; jj < 18; jj++) {
        m0 = fmaxf(m0, fmaxf(S[jj][0], S[jj][1]));
        m1 = fmaxf(m1, fmaxf(S[jj][2], S[jj][3]));
    }
    m0 = fmaxf(m0, __shfl_xor_sync(0xffffffffu, m0, 1));
    m0 = fmaxf(m0, __shfl_xor_sync(0xffffffffu, m0, 2));
    m1 = fmaxf(m1, __shfl_xor_sync(0xffffffffu, m1, 1));
    m1 = fmaxf(m1, __shfl_xor_sync(0xffffffffu, m1, 2));
    float s0 = 0.f, s1 = 0.f;
    #pragma unroll
    for (int jj = 0; jj < 18; jj++) {
        S[jj][0] = __expf(S[jj][0] - m0); s0 += S[jj][0];
        S[jj][1] = __expf(S[jj][1] - m0); s0 += S[jj][1];
        S[jj][2] = __expf(S[jj][2] - m1); s1 += S[jj][2];
        S[jj][3] = __expf(S[jj][3] - m1); s1 += S[jj][3];
    }
    s0 += __shfl_xor_sync(0xffffffffu, s0, 1);
    s0 += __shfl_xor_sync(0xffffffffu, s0, 2);
    s1 += __shfl_xor_sync(0xffffffffu, s1, 1);
    s1 += __shfl_xor_sync(0xffffffffu, s1, 2);
    const float r0 = 1.0f / s0, r1 = 1.0f / s1;
    #pragma unroll
    for (int jj = 0; jj < 18; jj++) {
        S[jj][0] *= r0; S[jj][1] *= r0; S[jj][2] *= r1; S[jj][3] *= r1;
    }

    // ---- O = (Ph+Pl) Vh : 9 kt tiles (144 keys) ----
    float O[8][4];
    #pragma unroll
    for (int ni = 0; ni < 8; ni++)
        O[ni][0] = O[ni][1] = O[ni][2] = O[ni][3] = 0.f;

    const int vrow = lane & 15;
    #pragma unroll
    for (int kt = 0; kt < 9; kt++) {
        const float* sA = S[2 * kt];
        const float* sB = S[2 * kt + 1];
        uint32_t ph[4], pl[4];
        ph[0] = pack_hi2(sA[0], sA[1]); pl[0] = pack_lo2(sA[0], sA[1]);
        ph[1] = pack_hi2(sA[2], sA[3]); pl[1] = pack_lo2(sA[2], sA[3]);
        ph[2] = pack_hi2(sB[0], sB[1]); pl[2] = pack_lo2(sB[0], sB[1]);
        ph[3] = pack_hi2(sB[2], sB[3]); pl[3] = pack_lo2(sB[2], sB[3]);
        const int vr = qrow0 + kt * 16 + vrow;
        #pragma unroll
        for (int nc = 0; nc < 2; nc++) {
            uint32_t vh[4][2];
            #pragma unroll
            for (int n4 = 0; n4 < 4; n4++) {
                int ni = nc * 4 + n4;
                LDMX2T(vh[n4][0], vh[n4][1], sb + 2u * (O_VH + vr * ASTR + ni * 8));
            }
            #pragma unroll
            for (int n4 = 0; n4 < 4; n4++)
                MMA16816H(O[nc * 4 + n4], ph, vh[n4]);
            #pragma unroll
            for (int n4 = 0; n4 < 4; n4++)
                MMA16816H(O[nc * 4 + n4], pl, vh[n4]);
        }
    }

    // ---- store O as fp16 hi/lo (feeds out-projection directly) ----
    #pragma unroll
    for (int ni = 0; ni < 8; ni++) {
        const int col = koff + ni * 8 + 2 * tg;
        size_t i0 = (tok_base + qg) * HIDDEN + col;
        size_t i1 = (tok_base + qg + 8) * HIDDEN + col;
        *(uint32_t*)&out_h[i0] = pack_hi2(O[ni][0], O[ni][1]);
        *(uint32_t*)&out_l[i0] = pack_lo2(O[ni][0], O[ni][1]);
        *(uint32_t*)&out_h[i1] = pack_hi2(O[ni][2], O[ni][3]);
        *(uint32_t*)&out_l[i1] = pack_lo2(O[ni][2], O[ni][3]);
    }
}

// ---------------------------------------------------------------------------
// Launch
// ---------------------------------------------------------------------------
extern "C" void kernel_launch(void* const* d_in, const int* in_sizes, int n_in,
                              void* d_out, int out_size)
{
    const float* hidden = nullptr;
    const float* wqkv = nullptr;
    const float* wo = nullptr;
    for (int i = 0; i < n_in; i++) {
        if (in_sizes[i] == NTOK * HIDDEN)            hidden = (const float*)d_in[i];
        else if (in_sizes[i] == QKV_N * HIDDEN)      wqkv   = (const float*)d_in[i];
        else if (in_sizes[i] == HIDDEN * HIDDEN)     wo     = (const float*)d_in[i];
    }

    __half *qh, *ql, *hh, *hl, *wqh, *woh, *ah, *al;
    float2* rope;
    cudaGetSymbolAddress((void**)&qh,  g_qh);
    cudaGetSymbolAddress((void**)&ql,  g_ql);
    cudaGetSymbolAddress((void**)&hh,  g_hh);
    cudaGetSymbolAddress((void**)&hl,  g_hl);
    cudaGetSymbolAddress((void**)&wqh, g_wqh);
    cudaGetSymbolAddress((void**)&woh, g_woh);
    cudaGetSymbolAddress((void**)&ah,  g_ah);
    cudaGetSymbolAddress((void**)&al,  g_al);
    cudaGetSymbolAddress((void**)&rope, g_rope);

    cudaFuncSetAttribute(gemm_f16_kernel,
                         cudaFuncAttributeMaxDynamicSharedMemorySize, GSMEM);
    cudaFuncSetAttribute(attn_mma_kernel,
                         cudaFuncAttributeMaxDynamicSharedMemorySize, ATT_SMEM_BYTES);

    // 0) rope table + splits (weights: hi only)
    rope_table_kernel<<<(S_LEN * 32 + 255) / 256, 256>>>();
    {
        int n;
        n = NTOK * HIDDEN;
        split_f16_kernel<<<(n / 4 + 255) / 256, 256>>>(hidden, hh, hl, n);
        n = QKV_N * HIDDEN;
        split_f16_kernel<<<(n / 4 + 255) / 256, 256>>>(wqkv, wqh, nullptr, n);
        n = HIDDEN * HIDDEN;
        split_f16_kernel<<<(n / 4 + 255) / 256, 256>>>(wo, woh, nullptr, n);
    }

    // 1) QKV projection (persistent fp16 HMMA, 2-term) -> fp16 hi/lo qkv
    gemm_f16_kernel<<<296, 128, GSMEM>>>(
        hh, hl, wqh, nullptr, qh, ql,
        NTOK, QKV_N, HIDDEN, (NTOK / 128) * (QKV_N / 128));

    // 2) sliding-window attention (fp16 HMMA 2-term, table RoPE, trimmed)
    attn_mma_kernel<<<B_SZ * NHEADS * (S_LEN / 128), 256, ATT_SMEM_BYTES>>>(
        qh, ql, rope, ah, al);

    // 3) output projection (persistent fp16 HMMA, 2-term) -> fp32 d_out
    gemm_f16_kernel<<<296, 128, GSMEM>>>(
        ah, al, woh, (float*)d_out, nullptr, nullptr,
        NTOK, HIDDEN, HIDDEN, (NTOK / 128) * (HIDDEN / 128));
}